// round 1
// baseline (speedup 1.0000x reference)
#include <cuda_runtime.h>

#define Bn 4
#define Tn 2048
#define En 1024
#define Hn 16
#define Dn 64

// Static device scratch (allocation-free per harness rules): 128 MB total.
__device__ float g_q[Bn * Hn * Tn * Dn];
__device__ float g_k[Bn * Hn * Tn * Dn];
__device__ float g_v[Bn * Hn * Tn * Dn];
__device__ float g_y[Bn * Tn * En];
__device__ int g_shift;  // 1 if input_ids is int64 (stride 2 in int32 words), else 0

// ---------------------------------------------------------------------------
// Detect whether input_ids buffer is int64 or int32.
// Tokens are in [0, 50257). If stored as little-endian int64, every odd int32
// word is 0. If int32, odd words are random tokens (P(all 32 are 0) ~ 0).
// Deterministic: same input -> same result on every call.
// ---------------------------------------------------------------------------
__global__ void detect_ids_kernel(const int* __restrict__ w) {
    bool all0 = true;
    for (int i = 1; i < 64; i += 2) all0 = all0 && (w[i] == 0);
    g_shift = all0 ? 1 : 0;
}

// ---------------------------------------------------------------------------
// Tiled fp32 GEMM: C[M,N] = A[M,K=1024] * W[K,N] (+bias)
// BM=128, BN=64, BK=16; 256 threads; 8x4 microtile per thread.
// QKV=true: A = x, epilogue scatters into g_q/g_k/g_v with [B,H,T,D] layout.
// QKV=false: A = g_y, epilogue adds bias, writes Cout.
// ---------------------------------------------------------------------------
template <int N, bool QKV>
__global__ void __launch_bounds__(256)
gemm_kernel(const float* __restrict__ A_in, const float* __restrict__ W,
            const float* __restrict__ bias, float* __restrict__ Cout) {
    constexpr int K = En;
    __shared__ float As[16][128];  // [k][m]
    __shared__ float Bs[16][68];   // [k][n], padded

    const float* A = QKV ? A_in : (const float*)g_y;

    const int m0 = blockIdx.y * 128;
    const int n0 = blockIdx.x * 64;
    const int tid = threadIdx.x;
    const int tx = tid & 15;   // 16 col groups of 4
    const int ty = tid >> 4;   // 16 row groups of 8

    const int ar = tid >> 1;         // 0..127 (A row within tile)
    const int ac = (tid & 1) << 3;   // 0 or 8 (A col within BK)
    const int br = tid >> 4;         // 0..15  (B row = k)
    const int bc = (tid & 15) << 2;  // B col within BN

    float acc[8][4];
#pragma unroll
    for (int i = 0; i < 8; i++)
#pragma unroll
        for (int j = 0; j < 4; j++) acc[i][j] = 0.f;

    const float* aptr = A + (size_t)(m0 + ar) * K + ac;
    const float* bptr = W + (size_t)br * N + n0 + bc;

    for (int k0 = 0; k0 < K; k0 += 16) {
        float4 a0 = *(const float4*)(aptr + k0);
        float4 a1 = *(const float4*)(aptr + k0 + 4);
        float4 b0 = *(const float4*)(bptr + (size_t)k0 * N);
        __syncthreads();  // previous tile's compute done before overwrite
        As[ac + 0][ar] = a0.x; As[ac + 1][ar] = a0.y;
        As[ac + 2][ar] = a0.z; As[ac + 3][ar] = a0.w;
        As[ac + 4][ar] = a1.x; As[ac + 5][ar] = a1.y;
        As[ac + 6][ar] = a1.z; As[ac + 7][ar] = a1.w;
        *(float4*)&Bs[br][bc] = b0;
        __syncthreads();
#pragma unroll
        for (int k = 0; k < 16; k++) {
            float4 av0 = *(const float4*)&As[k][ty * 8];
            float4 av1 = *(const float4*)&As[k][ty * 8 + 4];
            float4 bv = *(const float4*)&Bs[k][tx * 4];
            float am[8] = {av0.x, av0.y, av0.z, av0.w, av1.x, av1.y, av1.z, av1.w};
            float bm[4] = {bv.x, bv.y, bv.z, bv.w};
#pragma unroll
            for (int i = 0; i < 8; i++)
#pragma unroll
                for (int j = 0; j < 4; j++)
                    acc[i][j] = fmaf(am[i], bm[j], acc[i][j]);
        }
    }

    if (QKV) {
        // n0 is a multiple of 64 -> fixed (which, head) per block.
        const int which = n0 >> 10;            // 0=q 1=k 2=v
        const int h = (n0 & 1023) >> 6;        // head index
        float* dst = which == 0 ? g_q : (which == 1 ? g_k : g_v);
#pragma unroll
        for (int i = 0; i < 8; i++) {
            int m = m0 + ty * 8 + i;
            int b = m >> 11;
            int t = m & (Tn - 1);
            float4 v4 = make_float4(acc[i][0], acc[i][1], acc[i][2], acc[i][3]);
            *(float4*)&dst[(((size_t)(b * Hn + h)) * Tn + t) * Dn + tx * 4] = v4;
        }
    } else {
        float4 bb = *(const float4*)&bias[n0 + tx * 4];
#pragma unroll
        for (int i = 0; i < 8; i++) {
            int m = m0 + ty * 8 + i;
            float4 v4 = make_float4(acc[i][0] + bb.x, acc[i][1] + bb.y,
                                    acc[i][2] + bb.z, acc[i][3] + bb.w);
            *(float4*)&Cout[(size_t)m * N + n0 + tx * 4] = v4;
        }
    }
}

// ---------------------------------------------------------------------------
// Flash attention: one block per (q-tile of 64 rows, b*H+h).
// S = Q*K^T in registers via smem tiles (d-major for conflict-free LDS.128),
// online softmax state (m, l, alpha) in smem, O accumulators in registers.
// Masks: causal (k <= q) and key_keep (input_ids != 0).
// ---------------------------------------------------------------------------
__global__ void __launch_bounds__(256)
flash_kernel(const int* __restrict__ idsw) {
    extern __shared__ float smbuf[];
    float* sQT = smbuf;              // [64 d][68] -> Q^T
    float* sKT = sQT + 64 * 68;      // [64 d][68] -> K^T
    float* sV = sKT + 64 * 68;       // [64 key][68] -> V
    float* sS = sV + 64 * 68;        // [64 row][65] -> scores/probs
    float* sM = sS + 64 * 65;        // running max
    float* sL = sM + 64;             // running sum
    float* sA = sL + 64;             // alpha (rescale)
    int* sKeep = (int*)(sA + 64);    // key mask

    // Long blocks (large qt) launch first for load balance.
    const int qt = (int)gridDim.x - 1 - (int)blockIdx.x;
    const int bh = blockIdx.y;
    const int b = bh >> 4;
    const int h = bh & 15;
    const int tid = threadIdx.x;
    const int tx = tid & 15, ty = tid >> 4;
    const int shift = g_shift;

    const float* qb = g_q + (size_t)bh * Tn * Dn + (size_t)qt * 64 * Dn;
    const float* kb = g_k + (size_t)bh * Tn * Dn;
    const float* vb = g_v + (size_t)bh * Tn * Dn;

    // Load Q tile transposed (d-major).
#pragma unroll
    for (int it = 0; it < 4; it++) {
        int g = tid + it * 256;
        int r = g >> 4;
        int dc = (g & 15) << 2;
        float4 qv = *(const float4*)&qb[r * Dn + dc];
        sQT[(dc + 0) * 68 + r] = qv.x;
        sQT[(dc + 1) * 68 + r] = qv.y;
        sQT[(dc + 2) * 68 + r] = qv.z;
        sQT[(dc + 3) * 68 + r] = qv.w;
    }
    if (tid < 64) { sM[tid] = -1e30f; sL[tid] = 0.f; }

    float o[4][4];
#pragma unroll
    for (int i = 0; i < 4; i++)
#pragma unroll
        for (int j = 0; j < 4; j++) o[i][j] = 0.f;

    for (int kt = 0; kt <= qt; kt++) {
        __syncthreads();  // previous phase-2 reads done before overwriting tiles
#pragma unroll
        for (int it = 0; it < 4; it++) {
            int g = tid + it * 256;
            int c = g >> 4;
            int dc = (g & 15) << 2;
            float4 kv = *(const float4*)&kb[(kt * 64 + c) * Dn + dc];
            sKT[(dc + 0) * 68 + c] = kv.x;
            sKT[(dc + 1) * 68 + c] = kv.y;
            sKT[(dc + 2) * 68 + c] = kv.z;
            sKT[(dc + 3) * 68 + c] = kv.w;
            float4 vv = *(const float4*)&vb[(kt * 64 + c) * Dn + dc];
            *(float4*)&sV[c * 68 + dc] = vv;
        }
        if (tid < 64) {
            size_t widx = ((size_t)b * Tn + kt * 64 + tid) << shift;
            sKeep[tid] = (idsw[widx] != 0) ? 1 : 0;
        }
        __syncthreads();

        // Phase 1: S = Q * K^T
        float s[4][4];
#pragma unroll
        for (int i = 0; i < 4; i++)
#pragma unroll
            for (int j = 0; j < 4; j++) s[i][j] = 0.f;

#pragma unroll 8
        for (int kk = 0; kk < 64; kk++) {
            float4 qv = *(const float4*)&sQT[kk * 68 + ty * 4];
            float4 kv = *(const float4*)&sKT[kk * 68 + tx * 4];
            float qa[4] = {qv.x, qv.y, qv.z, qv.w};
            float ka[4] = {kv.x, kv.y, kv.z, kv.w};
#pragma unroll
            for (int i = 0; i < 4; i++)
#pragma unroll
                for (int j = 0; j < 4; j++)
                    s[i][j] = fmaf(qa[i], ka[j], s[i][j]);
        }

        // Scale, mask, stage to smem.
        const int q0 = qt * 64;
        const int k0g = kt * 64;
#pragma unroll
        for (int i = 0; i < 4; i++) {
            int r = ty * 4 + i;
            int qg = q0 + r;
#pragma unroll
            for (int j = 0; j < 4; j++) {
                int c = tx * 4 + j;
                float sv = s[i][j] * 0.125f;  // 1/sqrt(64)
                if ((k0g + c > qg) || (sKeep[c] == 0)) sv = -1e30f;
                sS[r * 65 + c] = sv;
            }
        }
        __syncthreads();

        // Online softmax row pass (64 threads, conflict-free stride 65).
        if (tid < 64) {
            const int r = tid;
            float m_old = sM[r];
            float mx = m_old;
#pragma unroll 8
            for (int c = 0; c < 64; c++) mx = fmaxf(mx, sS[r * 65 + c]);
            float alpha = __expf(m_old - mx);
            float lsum = 0.f;
#pragma unroll 8
            for (int c = 0; c < 64; c++) {
                float p = __expf(sS[r * 65 + c] - mx);
                sS[r * 65 + c] = p;
                lsum += p;
            }
            sM[r] = mx;
            sL[r] = sL[r] * alpha + lsum;
            sA[r] = alpha;
        }
        __syncthreads();

        // Rescale O accumulators, then Phase 2: O += P * V.
#pragma unroll
        for (int i = 0; i < 4; i++) {
            float al = sA[ty * 4 + i];
#pragma unroll
            for (int j = 0; j < 4; j++) o[i][j] *= al;
        }
#pragma unroll 8
        for (int c = 0; c < 64; c++) {
            float4 vv = *(const float4*)&sV[c * 68 + tx * 4];
            float va[4] = {vv.x, vv.y, vv.z, vv.w};
#pragma unroll
            for (int i = 0; i < 4; i++) {
                float p = sS[(ty * 4 + i) * 65 + c];
#pragma unroll
                for (int j = 0; j < 4; j++)
                    o[i][j] = fmaf(p, va[j], o[i][j]);
            }
        }
    }

    // Finalize: divide by l, write y in [B,T,E] layout.
#pragma unroll
    for (int i = 0; i < 4; i++) {
        int r = ty * 4 + i;
        float inv = 1.0f / sL[r];
        float4 v4 = make_float4(o[i][0] * inv, o[i][1] * inv,
                                o[i][2] * inv, o[i][3] * inv);
        int t = qt * 64 + r;
        *(float4*)&g_y[((size_t)b * Tn + t) * En + h * Dn + tx * 4] = v4;
    }
}

// ---------------------------------------------------------------------------
extern "C" void kernel_launch(void* const* d_in, const int* in_sizes, int n_in,
                              void* d_out, int out_size) {
    (void)in_sizes; (void)n_in; (void)out_size;
    const float* x = (const float*)d_in[0];
    const int* idsw = (const int*)d_in[1];  // int32 view; stride handled by g_shift
    const float* w_qkv = (const float*)d_in[2];
    const float* w_out = (const float*)d_in[3];
    const float* b_out = (const float*)d_in[4];
    float* out = (float*)d_out;

    // Resolve input_ids element width (int64 vs int32), deterministically.
    detect_ids_kernel<<<1, 1>>>(idsw);

    // 1) QKV projection, scattered into [B,H,T,D] q/k/v.
    dim3 g1((3 * En) / 64, (Bn * Tn) / 128);  // (48, 64)
    gemm_kernel<3 * En, true><<<g1, 256>>>(x, w_qkv, nullptr, nullptr);

    // 2) Flash attention.
    int smem = (3 * 64 * 68 + 64 * 65 + 3 * 64) * (int)sizeof(float) +
               64 * (int)sizeof(int);  // ~70 KB
    cudaFuncSetAttribute(flash_kernel,
                         cudaFuncAttributeMaxDynamicSharedMemorySize, smem);
    dim3 g2(Tn / 64, Bn * Hn);  // (32, 64)
    flash_kernel<<<g2, 256, smem>>>(idsw);

    // 3) Output projection + bias.
    dim3 g3(En / 64, (Bn * Tn) / 128);  // (16, 64)
    gemm_kernel<En, false><<<g3, 256>>>(nullptr, w_out, b_out, out);
}

// round 3
// speedup vs baseline: 1.4066x; 1.4066x over previous
#include <cuda_runtime.h>
#include <cuda_bf16.h>
#include <cstdint>

#define Bn 4
#define Tn 2048
#define En 1024
#define Hn 16
#define Dn 64
#define Kdim 1024

// ---------------- static device scratch (allocation-free) -------------------
__device__ float g_q[Bn * Hn * Tn * Dn];
__device__ float g_k[Bn * Hn * Tn * Dn];
__device__ float g_v[Bn * Hn * Tn * Dn];
__device__ float g_y[Bn * Tn * En];
__device__ __nv_bfloat16 g_ah[Bn * Tn * En];       // activation hi (x, then y)
__device__ __nv_bfloat16 g_al[Bn * Tn * En];       // activation lo
__device__ __nv_bfloat16 g_wqh[3 * En * Kdim];     // w_qkv^T hi  [N=3072][K=1024]
__device__ __nv_bfloat16 g_wql[3 * En * Kdim];
__device__ __nv_bfloat16 g_woh[En * Kdim];         // w_out^T hi  [N=1024][K=1024]
__device__ __nv_bfloat16 g_wol[En * Kdim];
__device__ int g_shift;

// ---------------- helpers (baseline PTX only: sm_80+ features) --------------
__device__ __forceinline__ void cp16(uint32_t s, const void* g) {
    asm volatile("cp.async.cg.shared.global [%0], [%1], 16;" :: "r"(s), "l"(g));
}
#define CP_COMMIT() asm volatile("cp.async.commit_group;" ::: "memory")
#define CP_WAIT(n) asm volatile("cp.async.wait_group %0;" :: "n"(n) : "memory")

__device__ __forceinline__ uint32_t smem_u32(const void* p) {
    uint32_t a;
    asm("{ .reg .u64 t; cvta.to.shared.u64 t, %1; cvt.u32.u64 %0, t; }"
        : "=r"(a) : "l"(p));
    return a;
}
__device__ __forceinline__ void mma16816(float* c, const uint32_t* a,
                                         const uint32_t* b) {
    asm volatile(
        "mma.sync.aligned.m16n8k16.row.col.f32.bf16.bf16.f32 "
        "{%0,%1,%2,%3}, {%4,%5,%6,%7}, {%8,%9}, {%0,%1,%2,%3};"
        : "+f"(c[0]), "+f"(c[1]), "+f"(c[2]), "+f"(c[3])
        : "r"(a[0]), "r"(a[1]), "r"(a[2]), "r"(a[3]), "r"(b[0]), "r"(b[1]));
}

// ---------------- int64-vs-int32 input_ids detection ------------------------
__global__ void detect_ids_kernel(const int* __restrict__ w) {
    bool all0 = true;
    for (int i = 1; i < 64; i += 2) all0 = all0 && (w[i] == 0);
    g_shift = all0 ? 1 : 0;
}

// ---------------- fp32 -> bf16 hi/lo split (x or g_y) -----------------------
template <bool FROMY>
__global__ void split_kernel(const float* __restrict__ src_in) {
    const float* src = FROMY ? (const float*)g_y : src_in;
    int i = blockIdx.x * blockDim.x + threadIdx.x;  // float4 index
    float4 v = ((const float4*)src)[i];
    float a[4] = {v.x, v.y, v.z, v.w};
    __nv_bfloat16 h[4], l[4];
#pragma unroll
    for (int j = 0; j < 4; j++) {
        h[j] = __float2bfloat16_rn(a[j]);
        l[j] = __float2bfloat16_rn(a[j] - __bfloat162float(h[j]));
    }
    __nv_bfloat162* ph = (__nv_bfloat162*)g_ah;
    __nv_bfloat162* pl = (__nv_bfloat162*)g_al;
    ph[2 * i] = __nv_bfloat162(h[0], h[1]);
    ph[2 * i + 1] = __nv_bfloat162(h[2], h[3]);
    pl[2 * i] = __nv_bfloat162(l[0], l[1]);
    pl[2 * i + 1] = __nv_bfloat162(l[2], l[3]);
}

// ---------------- weight transpose + split: W[K,N] -> Wt[N,K] hi/lo ---------
template <bool QKVW>
__global__ void wsplit_kernel(const float* __restrict__ W) {
    constexpr int Nw = QKVW ? 3 * En : En;
    __nv_bfloat16* oh = QKVW ? g_wqh : g_woh;
    __nv_bfloat16* ol = QKVW ? g_wql : g_wol;
    __shared__ float tile[32][33];
    int n0 = blockIdx.x * 32, k0 = blockIdx.y * 32;
    int tx = threadIdx.x, ty = threadIdx.y;  // (32, 8)
#pragma unroll
    for (int i = 0; i < 32; i += 8)
        tile[ty + i][tx] = W[(size_t)(k0 + ty + i) * Nw + n0 + tx];
    __syncthreads();
#pragma unroll
    for (int i = 0; i < 32; i += 8) {
        float a = tile[tx][ty + i];
        __nv_bfloat16 h = __float2bfloat16_rn(a);
        __nv_bfloat16 l = __float2bfloat16_rn(a - __bfloat162float(h));
        size_t o = (size_t)(n0 + ty + i) * Kdim + k0 + tx;
        oh[o] = h;
        ol[o] = l;
    }
}

// ---------------- HMMA bf16x3 GEMM: C[8192, Ntot] = A * W^T -----------------
// BM=128, BN=64, BK=32. 256 threads = 8 warps as 4(m) x 2(n); warp tile 32x32
// = 2x4 m16n8k16 tiles, 3 products each (AhBh + AhBl + AlBh), fp32 acc.
// Smem row stride 40 bf16 (80B = 20 banks) -> conflict-free fragment loads.
template <int Ntot, bool QKV>
__global__ void __launch_bounds__(256)
hmma_gemm(const float* __restrict__ bias, float* __restrict__ Cout) {
    constexpr int LDS_ = 40;                     // bf16 elems per smem row
    constexpr int ASZ = 128 * LDS_;              // elems per A tile
    constexpr int BSZ = 64 * LDS_;               // elems per B tile
    constexpr int STG = 2 * ASZ + 2 * BSZ;       // elems per stage
    extern __shared__ __nv_bfloat16 sm[];
    const uint32_t smb = smem_u32(sm);

    const __nv_bfloat16* Ahg = g_ah;
    const __nv_bfloat16* Alg = g_al;
    const __nv_bfloat16* Bhg = QKV ? g_wqh : g_woh;
    const __nv_bfloat16* Blg = QKV ? g_wql : g_wol;

    const int m0 = blockIdx.y * 128;
    const int n0 = blockIdx.x * 64;
    const int tid = threadIdx.x;
    const int wid = tid >> 5;
    const int lane = tid & 31;
    const int wm = wid >> 1;   // 0..3
    const int wn = wid & 1;    // 0..1
    const int lg = lane >> 2;  // group id 0..7
    const int lc = lane & 3;   // thread in group

    float acc[2][4][4];
#pragma unroll
    for (int mi = 0; mi < 2; mi++)
#pragma unroll
        for (int ni = 0; ni < 4; ni++)
#pragma unroll
            for (int r = 0; r < 4; r++) acc[mi][ni][r] = 0.f;

    auto load_stage = [&](int kc, int s) {
        const int k0 = kc * 32;
        const uint32_t sb = smb + (uint32_t)s * STG * 2;
        // A tiles: 128 rows x 32 cols = 512 chunks of 8 bf16 (16B)
#pragma unroll
        for (int c = tid; c < 512; c += 256) {
            int row = c >> 2, col8 = (c & 3) * 8;
            uint32_t sa = sb + (uint32_t)(row * LDS_ + col8) * 2;
            size_t go = (size_t)(m0 + row) * Kdim + k0 + col8;
            cp16(sa, Ahg + go);
            cp16(sa + ASZ * 2, Alg + go);
        }
        // B tiles: 64 rows x 32 cols = 256 chunks (one per thread)
        {
            int row = tid >> 2, col8 = (tid & 3) * 8;
            uint32_t sbb = sb + (uint32_t)(2 * ASZ + row * LDS_ + col8) * 2;
            size_t go = (size_t)(n0 + row) * Kdim + k0 + col8;
            cp16(sbb, Bhg + go);
            cp16(sbb + BSZ * 2, Blg + go);
        }
        CP_COMMIT();
    };

    load_stage(0, 0);

    for (int kc = 0; kc < Kdim / 32; kc++) {
        const int s = kc & 1;
        if (kc + 1 < Kdim / 32) {
            load_stage(kc + 1, s ^ 1);
            CP_WAIT(1);
        } else {
            CP_WAIT(0);
        }
        __syncthreads();

        const __nv_bfloat16* As = sm + (size_t)s * STG;
        const __nv_bfloat16* Bs = As + 2 * ASZ;
#pragma unroll
        for (int ks = 0; ks < 2; ks++) {
            const int kb = ks * 16 + lc * 2;
            uint32_t ah[2][4], al[2][4];
#pragma unroll
            for (int mi = 0; mi < 2; mi++) {
                int r = wm * 32 + mi * 16 + lg;
                const __nv_bfloat16* p = As + r * LDS_ + kb;
                ah[mi][0] = *(const uint32_t*)(p);
                ah[mi][1] = *(const uint32_t*)(p + 8 * LDS_);
                ah[mi][2] = *(const uint32_t*)(p + 8);
                ah[mi][3] = *(const uint32_t*)(p + 8 * LDS_ + 8);
                const __nv_bfloat16* q = p + ASZ;
                al[mi][0] = *(const uint32_t*)(q);
                al[mi][1] = *(const uint32_t*)(q + 8 * LDS_);
                al[mi][2] = *(const uint32_t*)(q + 8);
                al[mi][3] = *(const uint32_t*)(q + 8 * LDS_ + 8);
            }
            uint32_t bh[4][2], bl[4][2];
#pragma unroll
            for (int ni = 0; ni < 4; ni++) {
                int n = wn * 32 + ni * 8 + lg;
                const __nv_bfloat16* p = Bs + n * LDS_ + kb;
                bh[ni][0] = *(const uint32_t*)(p);
                bh[ni][1] = *(const uint32_t*)(p + 8);
                const __nv_bfloat16* q = p + BSZ;
                bl[ni][0] = *(const uint32_t*)(q);
                bl[ni][1] = *(const uint32_t*)(q + 8);
            }
#pragma unroll
            for (int mi = 0; mi < 2; mi++)
#pragma unroll
                for (int ni = 0; ni < 4; ni++) {
                    mma16816(acc[mi][ni], ah[mi], bh[ni]);
                    mma16816(acc[mi][ni], ah[mi], bl[ni]);
                    mma16816(acc[mi][ni], al[mi], bh[ni]);
                }
        }
        __syncthreads();
    }

    // ---- epilogue: fragment-mapped float2 stores ----
#pragma unroll
    for (int mi = 0; mi < 2; mi++) {
#pragma unroll
        for (int ni = 0; ni < 4; ni++) {
            int r0 = m0 + wm * 32 + mi * 16 + lg;
            int n = n0 + wn * 32 + ni * 8 + lc * 2;
#pragma unroll
            for (int half = 0; half < 2; half++) {
                int m = r0 + half * 8;
                float2 v = make_float2(acc[mi][ni][half * 2],
                                       acc[mi][ni][half * 2 + 1]);
                if (QKV) {
                    int which = n >> 10;
                    float* dst = which == 0 ? g_q : (which == 1 ? g_k : g_v);
                    int h = (n & 1023) >> 6;
                    int d = n & 63;
                    int b = m >> 11, t = m & (Tn - 1);
                    *(float2*)&dst[(((size_t)(b * Hn + h)) * Tn + t) * Dn + d] = v;
                } else {
                    v.x += bias[n];
                    v.y += bias[n + 1];
                    *(float2*)&Cout[(size_t)m * Ntot + n] = v;
                }
            }
        }
    }
}

// ---------------- flash attention (unchanged SIMT, fp32) --------------------
__global__ void __launch_bounds__(256)
flash_kernel(const int* __restrict__ idsw) {
    extern __shared__ float smbuf[];
    float* sQT = smbuf;
    float* sKT = sQT + 64 * 68;
    float* sV = sKT + 64 * 68;
    float* sS = sV + 64 * 68;
    float* sM = sS + 64 * 65;
    float* sL = sM + 64;
    float* sA = sL + 64;
    int* sKeep = (int*)(sA + 64);

    const int qt = (int)gridDim.x - 1 - (int)blockIdx.x;
    const int bh = blockIdx.y;
    const int b = bh >> 4;
    const int h = bh & 15;
    const int tid = threadIdx.x;
    const int tx = tid & 15, ty = tid >> 4;
    const int shift = g_shift;

    const float* qb = g_q + (size_t)bh * Tn * Dn + (size_t)qt * 64 * Dn;
    const float* kb = g_k + (size_t)bh * Tn * Dn;
    const float* vb = g_v + (size_t)bh * Tn * Dn;

#pragma unroll
    for (int it = 0; it < 4; it++) {
        int g = tid + it * 256;
        int r = g >> 4;
        int dc = (g & 15) << 2;
        float4 qv = *(const float4*)&qb[r * Dn + dc];
        sQT[(dc + 0) * 68 + r] = qv.x;
        sQT[(dc + 1) * 68 + r] = qv.y;
        sQT[(dc + 2) * 68 + r] = qv.z;
        sQT[(dc + 3) * 68 + r] = qv.w;
    }
    if (tid < 64) { sM[tid] = -1e30f; sL[tid] = 0.f; }

    float o[4][4];
#pragma unroll
    for (int i = 0; i < 4; i++)
#pragma unroll
        for (int j = 0; j < 4; j++) o[i][j] = 0.f;

    for (int kt = 0; kt <= qt; kt++) {
        __syncthreads();
#pragma unroll
        for (int it = 0; it < 4; it++) {
            int g = tid + it * 256;
            int c = g >> 4;
            int dc = (g & 15) << 2;
            float4 kv = *(const float4*)&kb[(kt * 64 + c) * Dn + dc];
            sKT[(dc + 0) * 68 + c] = kv.x;
            sKT[(dc + 1) * 68 + c] = kv.y;
            sKT[(dc + 2) * 68 + c] = kv.z;
            sKT[(dc + 3) * 68 + c] = kv.w;
            float4 vv = *(const float4*)&vb[(kt * 64 + c) * Dn + dc];
            *(float4*)&sV[c * 68 + dc] = vv;
        }
        if (tid < 64) {
            size_t widx = ((size_t)b * Tn + kt * 64 + tid) << shift;
            sKeep[tid] = (idsw[widx] != 0) ? 1 : 0;
        }
        __syncthreads();

        float s[4][4];
#pragma unroll
        for (int i = 0; i < 4; i++)
#pragma unroll
            for (int j = 0; j < 4; j++) s[i][j] = 0.f;

#pragma unroll 8
        for (int kk = 0; kk < 64; kk++) {
            float4 qv = *(const float4*)&sQT[kk * 68 + ty * 4];
            float4 kv = *(const float4*)&sKT[kk * 68 + tx * 4];
            float qa[4] = {qv.x, qv.y, qv.z, qv.w};
            float ka[4] = {kv.x, kv.y, kv.z, kv.w};
#pragma unroll
            for (int i = 0; i < 4; i++)
#pragma unroll
                for (int j = 0; j < 4; j++)
                    s[i][j] = fmaf(qa[i], ka[j], s[i][j]);
        }

        const int q0 = qt * 64;
        const int k0g = kt * 64;
#pragma unroll
        for (int i = 0; i < 4; i++) {
            int rr = ty * 4 + i;
            int qg = q0 + rr;
#pragma unroll
            for (int j = 0; j < 4; j++) {
                int c = tx * 4 + j;
                float sv = s[i][j] * 0.125f;
                if ((k0g + c > qg) || (sKeep[c] == 0)) sv = -1e30f;
                sS[rr * 65 + c] = sv;
            }
        }
        __syncthreads();

        if (tid < 64) {
            const int rr = tid;
            float m_old = sM[rr];
            float mx = m_old;
#pragma unroll 8
            for (int c = 0; c < 64; c++) mx = fmaxf(mx, sS[rr * 65 + c]);
            float alpha = __expf(m_old - mx);
            float lsum = 0.f;
#pragma unroll 8
            for (int c = 0; c < 64; c++) {
                float p = __expf(sS[rr * 65 + c] - mx);
                sS[rr * 65 + c] = p;
                lsum += p;
            }
            sM[rr] = mx;
            sL[rr] = sL[rr] * alpha + lsum;
            sA[rr] = alpha;
        }
        __syncthreads();

#pragma unroll
        for (int i = 0; i < 4; i++) {
            float al = sA[ty * 4 + i];
#pragma unroll
            for (int j = 0; j < 4; j++) o[i][j] *= al;
        }
#pragma unroll 8
        for (int c = 0; c < 64; c++) {
            float4 vv = *(const float4*)&sV[c * 68 + tx * 4];
            float va[4] = {vv.x, vv.y, vv.z, vv.w};
#pragma unroll
            for (int i = 0; i < 4; i++) {
                float p = sS[(ty * 4 + i) * 65 + c];
#pragma unroll
                for (int j = 0; j < 4; j++)
                    o[i][j] = fmaf(p, va[j], o[i][j]);
            }
        }
    }

#pragma unroll
    for (int i = 0; i < 4; i++) {
        int rr = ty * 4 + i;
        float inv = 1.0f / sL[rr];
        float4 v4 = make_float4(o[i][0] * inv, o[i][1] * inv,
                                o[i][2] * inv, o[i][3] * inv);
        int t = qt * 64 + rr;
        *(float4*)&g_y[((size_t)b * Tn + t) * En + h * Dn + tx * 4] = v4;
    }
}

// ---------------------------------------------------------------------------
extern "C" void kernel_launch(void* const* d_in, const int* in_sizes, int n_in,
                              void* d_out, int out_size) {
    (void)in_sizes; (void)n_in; (void)out_size;
    const float* x = (const float*)d_in[0];
    const int* idsw = (const int*)d_in[1];
    const float* w_qkv = (const float*)d_in[2];
    const float* w_out = (const float*)d_in[3];
    const float* b_out = (const float*)d_in[4];
    float* out = (float*)d_out;

    detect_ids_kernel<<<1, 1>>>(idsw);

    split_kernel<false><<<(Bn * Tn * En / 4) / 256, 256>>>(x);
    wsplit_kernel<true><<<dim3(3 * En / 32, Kdim / 32), dim3(32, 8)>>>(w_qkv);
    wsplit_kernel<false><<<dim3(En / 32, Kdim / 32), dim3(32, 8)>>>(w_out);

    const int gsmem = 2 * (2 * 128 * 40 + 2 * 64 * 40) * 2;  // 61440 B
    cudaFuncSetAttribute(hmma_gemm<3 * En, true>,
                         cudaFuncAttributeMaxDynamicSharedMemorySize, gsmem);
    cudaFuncSetAttribute(hmma_gemm<En, false>,
                         cudaFuncAttributeMaxDynamicSharedMemorySize, gsmem);

    // 1) QKV projection (HMMA), scatter into [B,H,T,D]
    dim3 g1(3 * En / 64, Bn * Tn / 128);  // (48, 64)
    hmma_gemm<3 * En, true><<<g1, 256, gsmem>>>(nullptr, nullptr);

    // 2) flash attention (SIMT fp32)
    int fsmem = (3 * 64 * 68 + 64 * 65 + 3 * 64) * (int)sizeof(float) +
                64 * (int)sizeof(int);
    cudaFuncSetAttribute(flash_kernel,
                         cudaFuncAttributeMaxDynamicSharedMemorySize, fsmem);
    dim3 g2(Tn / 64, Bn * Hn);
    flash_kernel<<<g2, 256, fsmem>>>(idsw);

    // 3) split y -> bf16 hi/lo, then output projection + bias
    split_kernel<true><<<(Bn * Tn * En / 4) / 256, 256>>>(nullptr);
    dim3 g3(En / 64, Bn * Tn / 128);  // (16, 64)
    hmma_gemm<En, false><<<g3, 256, gsmem>>>(b_out, out);
}

// round 4
// speedup vs baseline: 2.5629x; 1.8221x over previous
#include <cuda_runtime.h>
#include <cuda_bf16.h>
#include <cstdint>

#define Bn 4
#define Tn 2048
#define En 1024
#define Hn 16
#define Dn 64
#define Kdim 1024

// ---------------- static device scratch (allocation-free) -------------------
__device__ __nv_bfloat16 g_ah[Bn * Tn * En];       // activation hi (x, then y)
__device__ __nv_bfloat16 g_al[Bn * Tn * En];       // activation lo
__device__ __nv_bfloat16 g_wqh[3 * En * Kdim];     // w_qkv^T hi  [N=3072][K=1024]
__device__ __nv_bfloat16 g_wql[3 * En * Kdim];
__device__ __nv_bfloat16 g_woh[En * Kdim];         // w_out^T hi
__device__ __nv_bfloat16 g_wol[En * Kdim];
__device__ __nv_bfloat16 g_qh[Bn * Hn * Tn * Dn];  // q hi  [bh][t][d]
__device__ __nv_bfloat16 g_ql[Bn * Hn * Tn * Dn];
__device__ __nv_bfloat16 g_kh[Bn * Hn * Tn * Dn];  // k hi  [bh][t][d]
__device__ __nv_bfloat16 g_kl[Bn * Hn * Tn * Dn];
__device__ __nv_bfloat16 g_vth[Bn * Hn * Dn * Tn]; // v hi TRANSPOSED [bh][d][t]
__device__ __nv_bfloat16 g_vtl[Bn * Hn * Dn * Tn];
__device__ int g_shift;

// ---------------- helpers (baseline PTX only: sm_80+ features) --------------
__device__ __forceinline__ void cp16(uint32_t s, const void* g) {
    asm volatile("cp.async.cg.shared.global [%0], [%1], 16;" :: "r"(s), "l"(g));
}
#define CP_COMMIT() asm volatile("cp.async.commit_group;" ::: "memory")
#define CP_WAIT(n) asm volatile("cp.async.wait_group %0;" :: "n"(n) : "memory")

__device__ __forceinline__ uint32_t smem_u32(const void* p) {
    uint32_t a;
    asm("{ .reg .u64 t; cvta.to.shared.u64 t, %1; cvt.u32.u64 %0, t; }"
        : "=r"(a) : "l"(p));
    return a;
}
__device__ __forceinline__ void mma16816(float* c, const uint32_t* a,
                                         const uint32_t* b) {
    asm volatile(
        "mma.sync.aligned.m16n8k16.row.col.f32.bf16.bf16.f32 "
        "{%0,%1,%2,%3}, {%4,%5,%6,%7}, {%8,%9}, {%0,%1,%2,%3};"
        : "+f"(c[0]), "+f"(c[1]), "+f"(c[2]), "+f"(c[3])
        : "r"(a[0]), "r"(a[1]), "r"(a[2]), "r"(a[3]), "r"(b[0]), "r"(b[1]));
}
#define LM4(r, addr)                                                       \
    asm volatile("ldmatrix.sync.aligned.m8n8.x4.shared.b16 "               \
                 "{%0,%1,%2,%3}, [%4];"                                    \
                 : "=r"((r)[0]), "=r"((r)[1]), "=r"((r)[2]), "=r"((r)[3])  \
                 : "r"(addr))
__device__ __forceinline__ float ex2f(float x) {
    float r;
    asm("ex2.approx.f32 %0, %1;" : "=f"(r) : "f"(x));
    return r;
}
__device__ __forceinline__ uint32_t bfpack(float lo, float hi) {
    __nv_bfloat162 t = __floats2bfloat162_rn(lo, hi);
    return *(uint32_t*)&t;
}
__device__ __forceinline__ float bfred(float x) {
    return __bfloat162float(__float2bfloat16_rn(x));
}

// ---------------- int64-vs-int32 input_ids detection ------------------------
__global__ void detect_ids_kernel(const int* __restrict__ w) {
    bool all0 = true;
    for (int i = 1; i < 64; i += 2) all0 = all0 && (w[i] == 0);
    g_shift = all0 ? 1 : 0;
}

// ---------------- fp32 -> bf16 hi/lo split (x) ------------------------------
__global__ void split_kernel(const float* __restrict__ src) {
    int i = blockIdx.x * blockDim.x + threadIdx.x;
    float4 v = ((const float4*)src)[i];
    float a[4] = {v.x, v.y, v.z, v.w};
    uint32_t h0 = bfpack(a[0], a[1]), h1 = bfpack(a[2], a[3]);
    uint32_t l0 = bfpack(a[0] - bfred(a[0]), a[1] - bfred(a[1]));
    uint32_t l1 = bfpack(a[2] - bfred(a[2]), a[3] - bfred(a[3]));
    uint32_t* ph = (uint32_t*)g_ah;
    uint32_t* pl = (uint32_t*)g_al;
    ph[2 * i] = h0; ph[2 * i + 1] = h1;
    pl[2 * i] = l0; pl[2 * i + 1] = l1;
}

// ---------------- weight transpose + split: W[K,N] -> Wt[N,K] hi/lo ---------
template <bool QKVW>
__global__ void wsplit_kernel(const float* __restrict__ W) {
    constexpr int Nw = QKVW ? 3 * En : En;
    __nv_bfloat16* oh = QKVW ? g_wqh : g_woh;
    __nv_bfloat16* ol = QKVW ? g_wql : g_wol;
    __shared__ float tile[32][33];
    int n0 = blockIdx.x * 32, k0 = blockIdx.y * 32;
    int tx = threadIdx.x, ty = threadIdx.y;  // (32, 8)
#pragma unroll
    for (int i = 0; i < 32; i += 8)
        tile[ty + i][tx] = W[(size_t)(k0 + ty + i) * Nw + n0 + tx];
    __syncthreads();
#pragma unroll
    for (int i = 0; i < 32; i += 8) {
        float a = tile[tx][ty + i];
        size_t o = (size_t)(n0 + ty + i) * Kdim + k0 + tx;
        oh[o] = __float2bfloat16_rn(a);
        ol[o] = __float2bfloat16_rn(a - bfred(a));
    }
}

// ---------------- HMMA bf16x3 GEMM: C[8192, Ntot] = A * W^T -----------------
// BM=128, BN=64, BK=32. QKV=true: epilogue emits bf16 hi/lo q/k ([bh][t][d])
// and transposed v ([bh][d][t]); QKV=false: bias + fp32 out.
template <int Ntot, bool QKV>
__global__ void __launch_bounds__(256)
hmma_gemm(const float* __restrict__ bias, float* __restrict__ Cout) {
    constexpr int LDS_ = 40;
    constexpr int ASZ = 128 * LDS_;
    constexpr int BSZ = 64 * LDS_;
    constexpr int STG = 2 * ASZ + 2 * BSZ;
    extern __shared__ __nv_bfloat16 sm[];
    const uint32_t smb = smem_u32(sm);

    const __nv_bfloat16* Ahg = g_ah;
    const __nv_bfloat16* Alg = g_al;
    const __nv_bfloat16* Bhg = QKV ? g_wqh : g_woh;
    const __nv_bfloat16* Blg = QKV ? g_wql : g_wol;

    const int m0 = blockIdx.y * 128;
    const int n0 = blockIdx.x * 64;
    const int tid = threadIdx.x;
    const int wid = tid >> 5;
    const int lane = tid & 31;
    const int wm = wid >> 1;
    const int wn = wid & 1;
    const int lg = lane >> 2;
    const int lc = lane & 3;

    float acc[2][4][4];
#pragma unroll
    for (int mi = 0; mi < 2; mi++)
#pragma unroll
        for (int ni = 0; ni < 4; ni++)
#pragma unroll
            for (int r = 0; r < 4; r++) acc[mi][ni][r] = 0.f;

    auto load_stage = [&](int kc, int s) {
        const int k0 = kc * 32;
        const uint32_t sb = smb + (uint32_t)s * STG * 2;
#pragma unroll
        for (int c = tid; c < 512; c += 256) {
            int row = c >> 2, col8 = (c & 3) * 8;
            uint32_t sa = sb + (uint32_t)(row * LDS_ + col8) * 2;
            size_t go = (size_t)(m0 + row) * Kdim + k0 + col8;
            cp16(sa, Ahg + go);
            cp16(sa + ASZ * 2, Alg + go);
        }
        {
            int row = tid >> 2, col8 = (tid & 3) * 8;
            uint32_t sbb = sb + (uint32_t)(2 * ASZ + row * LDS_ + col8) * 2;
            size_t go = (size_t)(n0 + row) * Kdim + k0 + col8;
            cp16(sbb, Bhg + go);
            cp16(sbb + BSZ * 2, Blg + go);
        }
        CP_COMMIT();
    };

    load_stage(0, 0);

    for (int kc = 0; kc < Kdim / 32; kc++) {
        const int s = kc & 1;
        if (kc + 1 < Kdim / 32) {
            load_stage(kc + 1, s ^ 1);
            CP_WAIT(1);
        } else {
            CP_WAIT(0);
        }
        __syncthreads();

        const __nv_bfloat16* As = sm + (size_t)s * STG;
        const __nv_bfloat16* Bs = As + 2 * ASZ;
#pragma unroll
        for (int ks = 0; ks < 2; ks++) {
            const int kb = ks * 16 + lc * 2;
            uint32_t ah[2][4], al[2][4];
#pragma unroll
            for (int mi = 0; mi < 2; mi++) {
                int r = wm * 32 + mi * 16 + lg;
                const __nv_bfloat16* p = As + r * LDS_ + kb;
                ah[mi][0] = *(const uint32_t*)(p);
                ah[mi][1] = *(const uint32_t*)(p + 8 * LDS_);
                ah[mi][2] = *(const uint32_t*)(p + 8);
                ah[mi][3] = *(const uint32_t*)(p + 8 * LDS_ + 8);
                const __nv_bfloat16* q = p + ASZ;
                al[mi][0] = *(const uint32_t*)(q);
                al[mi][1] = *(const uint32_t*)(q + 8 * LDS_);
                al[mi][2] = *(const uint32_t*)(q + 8);
                al[mi][3] = *(const uint32_t*)(q + 8 * LDS_ + 8);
            }
            uint32_t bh[4][2], bl[4][2];
#pragma unroll
            for (int ni = 0; ni < 4; ni++) {
                int n = wn * 32 + ni * 8 + lg;
                const __nv_bfloat16* p = Bs + n * LDS_ + kb;
                bh[ni][0] = *(const uint32_t*)(p);
                bh[ni][1] = *(const uint32_t*)(p + 8);
                const __nv_bfloat16* q = p + BSZ;
                bl[ni][0] = *(const uint32_t*)(q);
                bl[ni][1] = *(const uint32_t*)(q + 8);
            }
#pragma unroll
            for (int mi = 0; mi < 2; mi++)
#pragma unroll
                for (int ni = 0; ni < 4; ni++) {
                    mma16816(acc[mi][ni], ah[mi], bh[ni]);
                    mma16816(acc[mi][ni], ah[mi], bl[ni]);
                    mma16816(acc[mi][ni], al[mi], bh[ni]);
                }
        }
        __syncthreads();
    }

    if (QKV) {
        const int which = n0 >> 10;
        const int h = (n0 & 1023) >> 6;
        const int b = m0 >> 11;
        const int bh_ = b * Hn + h;
        if (which < 2) {
            __nv_bfloat16* dh = which == 0 ? g_qh : g_kh;
            __nv_bfloat16* dl = which == 0 ? g_ql : g_kl;
#pragma unroll
            for (int mi = 0; mi < 2; mi++)
#pragma unroll
                for (int ni = 0; ni < 4; ni++)
#pragma unroll
                    for (int half = 0; half < 2; half++) {
                        int m = m0 + wm * 32 + mi * 16 + lg + half * 8;
                        int t = m & (Tn - 1);
                        int d = wn * 32 + ni * 8 + lc * 2;
                        float vx = acc[mi][ni][half * 2];
                        float vy = acc[mi][ni][half * 2 + 1];
                        size_t off = ((size_t)bh_ * Tn + t) * Dn + d;
                        *(uint32_t*)&dh[off] = bfpack(vx, vy);
                        *(uint32_t*)&dl[off] =
                            bfpack(vx - bfred(vx), vy - bfred(vy));
                    }
        } else {
            // V: transpose through smem -> [bh][d][t], coalesced stores
            __nv_bfloat16* sVh = sm;            // [64][136]
            __nv_bfloat16* sVl = sm + 64 * 136;
#pragma unroll
            for (int mi = 0; mi < 2; mi++)
#pragma unroll
                for (int ni = 0; ni < 4; ni++)
#pragma unroll
                    for (int half = 0; half < 2; half++) {
                        int tl = wm * 32 + mi * 16 + lg + half * 8;
                        int d = wn * 32 + ni * 8 + lc * 2;
                        float vx = acc[mi][ni][half * 2];
                        float vy = acc[mi][ni][half * 2 + 1];
                        sVh[d * 136 + tl] = __float2bfloat16_rn(vx);
                        sVh[(d + 1) * 136 + tl] = __float2bfloat16_rn(vy);
                        sVl[d * 136 + tl] = __float2bfloat16_rn(vx - bfred(vx));
                        sVl[(d + 1) * 136 + tl] =
                            __float2bfloat16_rn(vy - bfred(vy));
                    }
            __syncthreads();
#pragma unroll
            for (int c = tid; c < 1024; c += 256) {
                int d = c >> 4, t8 = (c & 15) * 8;
                uint4 vh = *(uint4*)&sVh[d * 136 + t8];
                uint4 vl = *(uint4*)&sVl[d * 136 + t8];
                size_t off = ((size_t)bh_ * Dn + d) * Tn + (m0 & (Tn - 1)) + t8;
                *(uint4*)&g_vth[off] = vh;
                *(uint4*)&g_vtl[off] = vl;
            }
        }
    } else {
#pragma unroll
        for (int mi = 0; mi < 2; mi++)
#pragma unroll
            for (int ni = 0; ni < 4; ni++) {
                int r0 = m0 + wm * 32 + mi * 16 + lg;
                int n = n0 + wn * 32 + ni * 8 + lc * 2;
#pragma unroll
                for (int half = 0; half < 2; half++) {
                    int m = r0 + half * 8;
                    float2 v = make_float2(acc[mi][ni][half * 2],
                                           acc[mi][ni][half * 2 + 1]);
                    v.x += bias[n];
                    v.y += bias[n + 1];
                    *(float2*)&Cout[(size_t)m * Ntot + n] = v;
                }
            }
    }
}

// ---------------- flash attention: HMMA bf16x3, FA-2 style ------------------
// Block: 128 q-rows x one head. 8 warps x 16 rows. kv tiles of 64,
// cp.async double-buffered. S and P stay in register fragments.
#define SQH 0
#define SQL 18432
#define SSTG 36864       // stage base; per stage: KH+0 KL+9216 VH+18432 VL+27648
#define SSTGSZ 36864
#define SKEEP 110592     // float[2][64]
#define FLASH_SMEM 111104
#define SC_LOG2 0.18033688f  // 0.125 * log2(e)

__global__ void __launch_bounds__(256, 2)
flash_kernel(const int* __restrict__ idsw) {
    extern __shared__ char smc[];
    const uint32_t smb = smem_u32(smc);

    const int qt = (int)gridDim.x - 1 - (int)blockIdx.x;
    const int bh = blockIdx.y;
    const int b = bh >> 4;
    const int h = bh & 15;
    const int qbase = qt * 128;
    const int tid = threadIdx.x;
    const int wm = tid >> 5;
    const int lane = tid & 31;
    const int lg = lane >> 2;
    const int lc = lane & 3;
    const int shift = g_shift;
    const int nt = 2 * qt + 2;

    // ldmatrix lane address components
    const int qrow = (lane & 7) + ((lane >> 3) & 1) * 8;
    const int qcol = ((lane >> 4) & 1) * 8;
    const int krow = (lane & 7) + ((lane >> 4) & 1) * 8;
    const int kcol = ((lane >> 3) & 1) * 8;

    const uint32_t aq_h = smb + SQH + (uint32_t)((wm * 16 + qrow) * 72 + qcol) * 2;
    const uint32_t aq_l = aq_h + (SQL - SQH);

    auto load_kv = [&](int kt, int s) {
        const int kv0 = kt * 64;
        const uint32_t sb = smb + SSTG + (uint32_t)s * SSTGSZ;
#pragma unroll
        for (int ch = tid; ch < 512; ch += 256) {
            int r = ch >> 3, c8 = (ch & 7) << 3;
            uint32_t so = sb + (uint32_t)(r * 72 + c8) * 2;
            size_t gk = ((size_t)bh * Tn + kv0 + r) * Dn + c8;
            cp16(so, g_kh + gk);
            cp16(so + 9216, g_kl + gk);
            size_t gv = ((size_t)bh * Dn + r) * Tn + kv0 + c8;
            cp16(so + 18432, g_vth + gv);
            cp16(so + 27648, g_vtl + gv);
        }
        if (tid < 64) {
            size_t w = ((size_t)(b * Tn + kv0 + tid)) << shift;
            float ka = (idsw[w] != 0) ? 0.f : -1e30f;
            *(float*)(smc + SKEEP + s * 256 + tid * 4) = ka;
        }
        CP_COMMIT();
    };

    // prologue: Q tile (once) + first kv stage in one cp.async group
#pragma unroll
    for (int ch = tid; ch < 1024; ch += 256) {
        int r = ch >> 3, c8 = (ch & 7) << 3;
        uint32_t so = smb + SQH + (uint32_t)(r * 72 + c8) * 2;
        size_t gq = ((size_t)bh * Tn + qbase + r) * Dn + c8;
        cp16(so, g_qh + gq);
        cp16(so + (SQL - SQH), g_ql + gq);
    }
    load_kv(0, 0);

    float o[8][4];
#pragma unroll
    for (int i = 0; i < 8; i++)
#pragma unroll
        for (int j = 0; j < 4; j++) o[i][j] = 0.f;
    float m0r = -1e30f, m1r = -1e30f, l0r = 0.f, l1r = 0.f;

    const int r0gl = qbase + wm * 16 + lg;
    const int r1gl = r0gl + 8;

    for (int kt = 0; kt < nt; kt++) {
        const int s = kt & 1;
        if (kt + 1 < nt) {
            load_kv(kt + 1, s ^ 1);
            CP_WAIT(1);
        } else {
            CP_WAIT(0);
        }
        __syncthreads();

        const uint32_t stg = smb + SSTG + (uint32_t)s * SSTGSZ;
        const int kv0 = kt * 64;

        // ---- S = Q K^T (3-product split), fragments in registers ----
        float c[8][4];
#pragma unroll
        for (int i = 0; i < 8; i++)
#pragma unroll
            for (int j = 0; j < 4; j++) c[i][j] = 0.f;

#pragma unroll
        for (int ks = 0; ks < 4; ks++) {
            uint32_t ah[4], al[4];
            LM4(ah, aq_h + ks * 32);
            LM4(al, aq_l + ks * 32);
#pragma unroll
            for (int pi = 0; pi < 4; pi++) {
                uint32_t kbh[4], kbl[4];
                uint32_t ka = stg + (uint32_t)((pi * 16 + krow) * 72 + kcol) * 2 +
                              ks * 32;
                LM4(kbh, ka);
                LM4(kbl, ka + 9216);
                mma16816(c[2 * pi], ah, kbh);
                mma16816(c[2 * pi], ah, kbl);
                mma16816(c[2 * pi], al, kbh);
                mma16816(c[2 * pi + 1], ah, kbh + 2);
                mma16816(c[2 * pi + 1], ah, kbl + 2);
                mma16816(c[2 * pi + 1], al, kbh + 2);
            }
        }

        // ---- mask + online softmax (log2 domain) ----
        const float* keepf = (const float*)(smc + SKEEP + s * 256);
        float mx0 = -1e30f, mx1 = -1e30f;
#pragma unroll
        for (int ni = 0; ni < 8; ni++) {
            int cg = kv0 + ni * 8 + 2 * lc;
            float k0 = keepf[ni * 8 + 2 * lc];
            float k1 = keepf[ni * 8 + 2 * lc + 1];
            float t0 = c[ni][0] * SC_LOG2 + k0;
            float t1 = c[ni][1] * SC_LOG2 + k1;
            float t2 = c[ni][2] * SC_LOG2 + k0;
            float t3 = c[ni][3] * SC_LOG2 + k1;
            if (cg > r0gl) t0 = -1e30f;
            if (cg + 1 > r0gl) t1 = -1e30f;
            if (cg > r1gl) t2 = -1e30f;
            if (cg + 1 > r1gl) t3 = -1e30f;
            c[ni][0] = t0; c[ni][1] = t1; c[ni][2] = t2; c[ni][3] = t3;
            mx0 = fmaxf(mx0, fmaxf(t0, t1));
            mx1 = fmaxf(mx1, fmaxf(t2, t3));
        }
        mx0 = fmaxf(mx0, __shfl_xor_sync(0xffffffffu, mx0, 1));
        mx0 = fmaxf(mx0, __shfl_xor_sync(0xffffffffu, mx0, 2));
        mx1 = fmaxf(mx1, __shfl_xor_sync(0xffffffffu, mx1, 1));
        mx1 = fmaxf(mx1, __shfl_xor_sync(0xffffffffu, mx1, 2));
        float mn0 = fmaxf(m0r, mx0), mn1 = fmaxf(m1r, mx1);
        float al0 = ex2f(m0r - mn0), al1 = ex2f(m1r - mn1);
        float ls0 = 0.f, ls1 = 0.f;
#pragma unroll
        for (int ni = 0; ni < 8; ni++) {
            float p0 = ex2f(c[ni][0] - mn0);
            float p1 = ex2f(c[ni][1] - mn0);
            float p2 = ex2f(c[ni][2] - mn1);
            float p3 = ex2f(c[ni][3] - mn1);
            c[ni][0] = p0; c[ni][1] = p1; c[ni][2] = p2; c[ni][3] = p3;
            ls0 += p0 + p1;
            ls1 += p2 + p3;
        }
        ls0 += __shfl_xor_sync(0xffffffffu, ls0, 1);
        ls0 += __shfl_xor_sync(0xffffffffu, ls0, 2);
        ls1 += __shfl_xor_sync(0xffffffffu, ls1, 1);
        ls1 += __shfl_xor_sync(0xffffffffu, ls1, 2);
        l0r = l0r * al0 + ls0;
        l1r = l1r * al1 + ls1;
        m0r = mn0;
        m1r = mn1;
#pragma unroll
        for (int nd = 0; nd < 8; nd++) {
            o[nd][0] *= al0; o[nd][1] *= al0;
            o[nd][2] *= al1; o[nd][3] *= al1;
        }

        // ---- O += P V (P hi/lo packed from registers; V from smem) ----
#pragma unroll
        for (int ks = 0; ks < 4; ks++) {
            uint32_t pah[4], pal[4];
#pragma unroll
            for (int u = 0; u < 2; u++) {  // ntile 2ks, 2ks+1 -> a0/a1, a2/a3
                float x0 = c[2 * ks + u][0], x1 = c[2 * ks + u][1];
                float x2 = c[2 * ks + u][2], x3 = c[2 * ks + u][3];
                pah[2 * u] = bfpack(x0, x1);
                pah[2 * u + 1] = bfpack(x2, x3);
                pal[2 * u] = bfpack(x0 - bfred(x0), x1 - bfred(x1));
                pal[2 * u + 1] = bfpack(x2 - bfred(x2), x3 - bfred(x3));
            }
#pragma unroll
            for (int pd = 0; pd < 4; pd++) {
                uint32_t vbh[4], vbl[4];
                uint32_t va = stg + 18432 +
                              (uint32_t)((pd * 16 + krow) * 72 + kcol) * 2 +
                              ks * 32;
                LM4(vbh, va);
                LM4(vbl, va + 9216);
                mma16816(o[2 * pd], pah, vbh);
                mma16816(o[2 * pd], pah, vbl);
                mma16816(o[2 * pd], pal, vbh);
                mma16816(o[2 * pd + 1], pah, vbh + 2);
                mma16816(o[2 * pd + 1], pah, vbl + 2);
                mma16816(o[2 * pd + 1], pal, vbh + 2);
            }
        }
        __syncthreads();
    }

    // ---- finalize: divide by l, write y as bf16 hi/lo into g_ah/g_al ----
    const float i0 = 1.f / l0r, i1 = 1.f / l1r;
    const size_t row0 = (size_t)b * Tn + qbase + wm * 16 + lg;
    const size_t row1 = row0 + 8;
#pragma unroll
    for (int nd = 0; nd < 8; nd++) {
        int col = h * Dn + nd * 8 + 2 * lc;
        float y0 = o[nd][0] * i0, y1 = o[nd][1] * i0;
        float y2 = o[nd][2] * i1, y3 = o[nd][3] * i1;
        *(uint32_t*)&g_ah[row0 * En + col] = bfpack(y0, y1);
        *(uint32_t*)&g_al[row0 * En + col] =
            bfpack(y0 - bfred(y0), y1 - bfred(y1));
        *(uint32_t*)&g_ah[row1 * En + col] = bfpack(y2, y3);
        *(uint32_t*)&g_al[row1 * En + col] =
            bfpack(y2 - bfred(y2), y3 - bfred(y3));
    }
}

// ---------------------------------------------------------------------------
extern "C" void kernel_launch(void* const* d_in, const int* in_sizes, int n_in,
                              void* d_out, int out_size) {
    (void)in_sizes; (void)n_in; (void)out_size;
    const float* x = (const float*)d_in[0];
    const int* idsw = (const int*)d_in[1];
    const float* w_qkv = (const float*)d_in[2];
    const float* w_out = (const float*)d_in[3];
    const float* b_out = (const float*)d_in[4];
    float* out = (float*)d_out;

    detect_ids_kernel<<<1, 1>>>(idsw);

    split_kernel<<<(Bn * Tn * En / 4) / 256, 256>>>(x);
    wsplit_kernel<true><<<dim3(3 * En / 32, Kdim / 32), dim3(32, 8)>>>(w_qkv);
    wsplit_kernel<false><<<dim3(En / 32, Kdim / 32), dim3(32, 8)>>>(w_out);

    const int gsmem = 2 * (2 * 128 * 40 + 2 * 64 * 40) * 2;  // 61440 B
    cudaFuncSetAttribute(hmma_gemm<3 * En, true>,
                         cudaFuncAttributeMaxDynamicSharedMemorySize, gsmem);
    cudaFuncSetAttribute(hmma_gemm<En, false>,
                         cudaFuncAttributeMaxDynamicSharedMemorySize, gsmem);

    // 1) QKV projection (HMMA) -> bf16 hi/lo q/k ([bh][t][d]) + v^T ([bh][d][t])
    dim3 g1(3 * En / 64, Bn * Tn / 128);  // (48, 64)
    hmma_gemm<3 * En, true><<<g1, 256, gsmem>>>(nullptr, nullptr);

    // 2) flash attention (HMMA bf16x3) -> writes y hi/lo into g_ah/g_al
    cudaFuncSetAttribute(flash_kernel,
                         cudaFuncAttributeMaxDynamicSharedMemorySize, FLASH_SMEM);
    dim3 g2(Tn / 128, Bn * Hn);  // (16, 64)
    flash_kernel<<<g2, 256, FLASH_SMEM>>>(idsw);

    // 3) output projection + bias (HMMA)
    dim3 g3(En / 64, Bn * Tn / 128);  // (16, 64)
    hmma_gemm<En, false><<<g3, 256, gsmem>>>(b_out, out);
}

// round 5
// speedup vs baseline: 2.7446x; 1.0709x over previous
#include <cuda_runtime.h>
#include <cuda_bf16.h>
#include <cstdint>

#define Bn 4
#define Tn 2048
#define En 1024
#define Hn 16
#define Dn 64
#define Kdim 1024

// ---------------- static device scratch (allocation-free) -------------------
__device__ __nv_bfloat16 g_ah[Bn * Tn * En];       // activation hi (x, then y)
__device__ __nv_bfloat16 g_al[Bn * Tn * En];       // activation lo
__device__ __nv_bfloat16 g_wqh[3 * En * Kdim];     // w_qkv^T hi  [N=3072][K=1024]
__device__ __nv_bfloat16 g_wql[3 * En * Kdim];
__device__ __nv_bfloat16 g_woh[En * Kdim];         // w_out^T hi
__device__ __nv_bfloat16 g_wol[En * Kdim];
__device__ __nv_bfloat16 g_qh[Bn * Hn * Tn * Dn];  // q hi  [bh][t][d]
__device__ __nv_bfloat16 g_ql[Bn * Hn * Tn * Dn];
__device__ __nv_bfloat16 g_kh[Bn * Hn * Tn * Dn];  // k hi  [bh][t][d]
__device__ __nv_bfloat16 g_kl[Bn * Hn * Tn * Dn];
__device__ __nv_bfloat16 g_vth[Bn * Hn * Dn * Tn]; // v hi TRANSPOSED [bh][d][t]
__device__ __nv_bfloat16 g_vtl[Bn * Hn * Dn * Tn];
__device__ int g_shift;

// ---------------- helpers (baseline PTX only: sm_80+ features) --------------
__device__ __forceinline__ void cp16(uint32_t s, const void* g) {
    asm volatile("cp.async.cg.shared.global [%0], [%1], 16;" :: "r"(s), "l"(g));
}
#define CP_COMMIT() asm volatile("cp.async.commit_group;" ::: "memory")
#define CP_WAIT(n) asm volatile("cp.async.wait_group %0;" :: "n"(n) : "memory")

__device__ __forceinline__ uint32_t smem_u32(const void* p) {
    uint32_t a;
    asm("{ .reg .u64 t; cvta.to.shared.u64 t, %1; cvt.u32.u64 %0, t; }"
        : "=r"(a) : "l"(p));
    return a;
}
__device__ __forceinline__ void mma16816(float* c, const uint32_t* a,
                                         const uint32_t* b) {
    asm volatile(
        "mma.sync.aligned.m16n8k16.row.col.f32.bf16.bf16.f32 "
        "{%0,%1,%2,%3}, {%4,%5,%6,%7}, {%8,%9}, {%0,%1,%2,%3};"
        : "+f"(c[0]), "+f"(c[1]), "+f"(c[2]), "+f"(c[3])
        : "r"(a[0]), "r"(a[1]), "r"(a[2]), "r"(a[3]), "r"(b[0]), "r"(b[1]));
}
#define LM4(r, addr)                                                       \
    asm volatile("ldmatrix.sync.aligned.m8n8.x4.shared.b16 "               \
                 "{%0,%1,%2,%3}, [%4];"                                    \
                 : "=r"((r)[0]), "=r"((r)[1]), "=r"((r)[2]), "=r"((r)[3])  \
                 : "r"(addr))
__device__ __forceinline__ float ex2f(float x) {
    float r;
    asm("ex2.approx.f32 %0, %1;" : "=f"(r) : "f"(x));
    return r;
}
__device__ __forceinline__ uint32_t bfpack(float lo, float hi) {
    __nv_bfloat162 t = __floats2bfloat162_rn(lo, hi);
    return *(uint32_t*)&t;
}
__device__ __forceinline__ float bfred(float x) {
    return __bfloat162float(__float2bfloat16_rn(x));
}

// ---------------- int64-vs-int32 input_ids detection ------------------------
__global__ void detect_ids_kernel(const int* __restrict__ w) {
    bool all0 = true;
    for (int i = 1; i < 64; i += 2) all0 = all0 && (w[i] == 0);
    g_shift = all0 ? 1 : 0;
}

// ---------------- fp32 -> bf16 hi/lo split (x) ------------------------------
__global__ void split_kernel(const float* __restrict__ src) {
    int i = blockIdx.x * blockDim.x + threadIdx.x;
    float4 v = ((const float4*)src)[i];
    float a[4] = {v.x, v.y, v.z, v.w};
    uint32_t h0 = bfpack(a[0], a[1]), h1 = bfpack(a[2], a[3]);
    uint32_t l0 = bfpack(a[0] - bfred(a[0]), a[1] - bfred(a[1]));
    uint32_t l1 = bfpack(a[2] - bfred(a[2]), a[3] - bfred(a[3]));
    uint32_t* ph = (uint32_t*)g_ah;
    uint32_t* pl = (uint32_t*)g_al;
    ph[2 * i] = h0; ph[2 * i + 1] = h1;
    pl[2 * i] = l0; pl[2 * i + 1] = l1;
}

// ---------------- weight transpose + split: W[K,N] -> Wt[N,K] hi/lo ---------
template <bool QKVW>
__global__ void wsplit_kernel(const float* __restrict__ W) {
    constexpr int Nw = QKVW ? 3 * En : En;
    __nv_bfloat16* oh = QKVW ? g_wqh : g_woh;
    __nv_bfloat16* ol = QKVW ? g_wql : g_wol;
    __shared__ float tile[32][33];
    int n0 = blockIdx.x * 32, k0 = blockIdx.y * 32;
    int tx = threadIdx.x, ty = threadIdx.y;  // (32, 8)
#pragma unroll
    for (int i = 0; i < 32; i += 8)
        tile[ty + i][tx] = W[(size_t)(k0 + ty + i) * Nw + n0 + tx];
    __syncthreads();
#pragma unroll
    for (int i = 0; i < 32; i += 8) {
        float a = tile[tx][ty + i];
        size_t o = (size_t)(n0 + ty + i) * Kdim + k0 + tx;
        oh[o] = __float2bfloat16_rn(a);
        ol[o] = __float2bfloat16_rn(a - bfred(a));
    }
}

// ---------------- HMMA bf16x3 GEMM: C[8192, Ntot] = A * W^T -----------------
// BM=128, BN=64, BK=32. 3-stage cp.async pipeline, ldmatrix fragment loads.
// 8 warps as 4(m) x 2(n), warp tile 32x32. 3 products (AhBh+AhBl+AlBh).
template <int Ntot, bool QKV>
__global__ void __launch_bounds__(256, 2)
hmma_gemm(const float* __restrict__ bias, float* __restrict__ Cout) {
    constexpr int ROWB = 80;                    // bytes per smem row (40 bf16)
    constexpr int OFF_AL = 10240;               // 128*80
    constexpr int OFF_BH = 20480;
    constexpr int OFF_BL = 25600;               // +64*80
    constexpr int STG = 30720;                  // bytes per stage
    constexpr int NK = Kdim / 32;               // 32
    extern __shared__ char smc[];
    const uint32_t smb = smem_u32(smc);

    const __nv_bfloat16* Bhg = QKV ? g_wqh : g_woh;
    const __nv_bfloat16* Blg = QKV ? g_wql : g_wol;

    const int m0 = blockIdx.y * 128;
    const int n0 = blockIdx.x * 64;
    const int tid = threadIdx.x;
    const int wid = tid >> 5;
    const int lane = tid & 31;
    const int wm = wid >> 1;
    const int wn = wid & 1;
    const int lg = lane >> 2;
    const int lc = lane & 3;
    // ldmatrix lane address components
    const int arow = (lane & 7) + ((lane >> 3) & 1) * 8;  // A: row-major frag
    const int acol = ((lane >> 4) & 1) * 8;
    const int brow = (lane & 7) + ((lane >> 4) & 1) * 8;  // B: col-major frag
    const int bcol = ((lane >> 3) & 1) * 8;

    float acc[2][4][4];
#pragma unroll
    for (int mi = 0; mi < 2; mi++)
#pragma unroll
        for (int ni = 0; ni < 4; ni++)
#pragma unroll
            for (int r = 0; r < 4; r++) acc[mi][ni][r] = 0.f;

    auto load_stage = [&](int kc, int s) {
        const int k0 = kc * 32;
        const uint32_t sb = smb + (uint32_t)s * STG;
#pragma unroll
        for (int c = tid; c < 512; c += 256) {
            int row = c >> 2, col8 = (c & 3) * 8;
            uint32_t sa = sb + (uint32_t)(row * ROWB + col8 * 2);
            size_t go = (size_t)(m0 + row) * Kdim + k0 + col8;
            cp16(sa, g_ah + go);
            cp16(sa + OFF_AL, g_al + go);
        }
        {
            int row = tid >> 2, col8 = (tid & 3) * 8;
            uint32_t sbb = sb + OFF_BH + (uint32_t)(row * ROWB + col8 * 2);
            size_t go = (size_t)(n0 + row) * Kdim + k0 + col8;
            cp16(sbb, Bhg + go);
            cp16(sbb + (OFF_BL - OFF_BH), Blg + go);
        }
        CP_COMMIT();
    };

    load_stage(0, 0);
    load_stage(1, 1);

    int s = 0;
    for (int kc = 0; kc < NK; kc++) {
        if (kc < NK - 1) CP_WAIT(1); else CP_WAIT(0);
        __syncthreads();
        if (kc + 2 < NK) {
            int s2 = s + 2;
            if (s2 >= 3) s2 -= 3;
            load_stage(kc + 2, s2);
        }
        const uint32_t sb = smb + (uint32_t)s * STG;
        const uint32_t aB = sb + (uint32_t)((wm * 32 + arow) * ROWB + acol * 2);
        const uint32_t bB = sb + OFF_BH +
                            (uint32_t)((wn * 32 + brow) * ROWB + bcol * 2);
#pragma unroll
        for (int ks = 0; ks < 2; ks++) {
            uint32_t ah[2][4], al[2][4], bh[2][4], bl[2][4];
#pragma unroll
            for (int mi = 0; mi < 2; mi++) {
                uint32_t a = aB + mi * 16 * ROWB + ks * 32;
                LM4(ah[mi], a);
                LM4(al[mi], a + OFF_AL);
            }
#pragma unroll
            for (int nj = 0; nj < 2; nj++) {
                uint32_t a = bB + nj * 16 * ROWB + ks * 32;
                LM4(bh[nj], a);
                LM4(bl[nj], a + (OFF_BL - OFF_BH));
            }
#pragma unroll
            for (int mi = 0; mi < 2; mi++)
#pragma unroll
                for (int nj = 0; nj < 2; nj++) {
                    mma16816(acc[mi][2 * nj], ah[mi], bh[nj]);
                    mma16816(acc[mi][2 * nj], ah[mi], bl[nj]);
                    mma16816(acc[mi][2 * nj], al[mi], bh[nj]);
                    mma16816(acc[mi][2 * nj + 1], ah[mi], bh[nj] + 2);
                    mma16816(acc[mi][2 * nj + 1], ah[mi], bl[nj] + 2);
                    mma16816(acc[mi][2 * nj + 1], al[mi], bh[nj] + 2);
                }
        }
        if (++s == 3) s = 0;
    }

    if (QKV) {
        const int which = n0 >> 10;
        const int h = (n0 & 1023) >> 6;
        const int b = m0 >> 11;
        const int bh_ = b * Hn + h;
        if (which < 2) {
            __nv_bfloat16* dh = which == 0 ? g_qh : g_kh;
            __nv_bfloat16* dl = which == 0 ? g_ql : g_kl;
#pragma unroll
            for (int mi = 0; mi < 2; mi++)
#pragma unroll
                for (int ni = 0; ni < 4; ni++)
#pragma unroll
                    for (int half = 0; half < 2; half++) {
                        int m = m0 + wm * 32 + mi * 16 + lg + half * 8;
                        int t = m & (Tn - 1);
                        int d = wn * 32 + ni * 8 + lc * 2;
                        float vx = acc[mi][ni][half * 2];
                        float vy = acc[mi][ni][half * 2 + 1];
                        size_t off = ((size_t)bh_ * Tn + t) * Dn + d;
                        *(uint32_t*)&dh[off] = bfpack(vx, vy);
                        *(uint32_t*)&dl[off] =
                            bfpack(vx - bfred(vx), vy - bfred(vy));
                    }
        } else {
            // V: transpose through smem -> [bh][d][t], coalesced stores
            __syncthreads();  // all warps done reading stage smem
            __nv_bfloat16* sVh = (__nv_bfloat16*)smc;  // [64][136]
            __nv_bfloat16* sVl = (__nv_bfloat16*)smc + 64 * 136;
#pragma unroll
            for (int mi = 0; mi < 2; mi++)
#pragma unroll
                for (int ni = 0; ni < 4; ni++)
#pragma unroll
                    for (int half = 0; half < 2; half++) {
                        int tl = wm * 32 + mi * 16 + lg + half * 8;
                        int d = wn * 32 + ni * 8 + lc * 2;
                        float vx = acc[mi][ni][half * 2];
                        float vy = acc[mi][ni][half * 2 + 1];
                        sVh[d * 136 + tl] = __float2bfloat16_rn(vx);
                        sVh[(d + 1) * 136 + tl] = __float2bfloat16_rn(vy);
                        sVl[d * 136 + tl] = __float2bfloat16_rn(vx - bfred(vx));
                        sVl[(d + 1) * 136 + tl] =
                            __float2bfloat16_rn(vy - bfred(vy));
                    }
            __syncthreads();
#pragma unroll
            for (int c = tid; c < 1024; c += 256) {
                int d = c >> 4, t8 = (c & 15) * 8;
                uint4 vh = *(uint4*)&sVh[d * 136 + t8];
                uint4 vl = *(uint4*)&sVl[d * 136 + t8];
                size_t off = ((size_t)bh_ * Dn + d) * Tn + (m0 & (Tn - 1)) + t8;
                *(uint4*)&g_vth[off] = vh;
                *(uint4*)&g_vtl[off] = vl;
            }
        }
    } else {
#pragma unroll
        for (int mi = 0; mi < 2; mi++)
#pragma unroll
            for (int ni = 0; ni < 4; ni++) {
                int r0 = m0 + wm * 32 + mi * 16 + lg;
                int n = n0 + wn * 32 + ni * 8 + lc * 2;
#pragma unroll
                for (int half = 0; half < 2; half++) {
                    int m = r0 + half * 8;
                    float2 v = make_float2(acc[mi][ni][half * 2],
                                           acc[mi][ni][half * 2 + 1]);
                    v.x += bias[n];
                    v.y += bias[n + 1];
                    *(float2*)&Cout[(size_t)m * Ntot + n] = v;
                }
            }
    }
}

// ---------------- flash attention: HMMA bf16x3, FA-2 style ------------------
#define SQH 0
#define SQL 18432
#define SSTG 36864       // stage base; per stage: KH+0 KL+9216 VH+18432 VL+27648
#define SSTGSZ 36864
#define SKEEP 110592     // float[2][64]
#define FLASH_SMEM 111104
#define SC_LOG2 0.18033688f  // 0.125 * log2(e)

__global__ void __launch_bounds__(256, 2)
flash_kernel(const int* __restrict__ idsw) {
    extern __shared__ char smc[];
    const uint32_t smb = smem_u32(smc);

    const int qt = (int)gridDim.x - 1 - (int)blockIdx.x;
    const int bh = blockIdx.y;
    const int b = bh >> 4;
    const int h = bh & 15;
    const int qbase = qt * 128;
    const int tid = threadIdx.x;
    const int wm = tid >> 5;
    const int lane = tid & 31;
    const int lg = lane >> 2;
    const int lc = lane & 3;
    const int shift = g_shift;
    const int nt = 2 * qt + 2;

    const int qrow = (lane & 7) + ((lane >> 3) & 1) * 8;
    const int qcol = ((lane >> 4) & 1) * 8;
    const int krow = (lane & 7) + ((lane >> 4) & 1) * 8;
    const int kcol = ((lane >> 3) & 1) * 8;

    const uint32_t aq_h = smb + SQH + (uint32_t)((wm * 16 + qrow) * 72 + qcol) * 2;
    const uint32_t aq_l = aq_h + (SQL - SQH);

    auto load_kv = [&](int kt, int s) {
        const int kv0 = kt * 64;
        const uint32_t sb = smb + SSTG + (uint32_t)s * SSTGSZ;
#pragma unroll
        for (int ch = tid; ch < 512; ch += 256) {
            int r = ch >> 3, c8 = (ch & 7) << 3;
            uint32_t so = sb + (uint32_t)(r * 72 + c8) * 2;
            size_t gk = ((size_t)bh * Tn + kv0 + r) * Dn + c8;
            cp16(so, g_kh + gk);
            cp16(so + 9216, g_kl + gk);
            size_t gv = ((size_t)bh * Dn + r) * Tn + kv0 + c8;
            cp16(so + 18432, g_vth + gv);
            cp16(so + 27648, g_vtl + gv);
        }
        if (tid < 64) {
            size_t w = ((size_t)(b * Tn + kv0 + tid)) << shift;
            float ka = (idsw[w] != 0) ? 0.f : -1e30f;
            *(float*)(smc + SKEEP + s * 256 + tid * 4) = ka;
        }
        CP_COMMIT();
    };

#pragma unroll
    for (int ch = tid; ch < 1024; ch += 256) {
        int r = ch >> 3, c8 = (ch & 7) << 3;
        uint32_t so = smb + SQH + (uint32_t)(r * 72 + c8) * 2;
        size_t gq = ((size_t)bh * Tn + qbase + r) * Dn + c8;
        cp16(so, g_qh + gq);
        cp16(so + (SQL - SQH), g_ql + gq);
    }
    load_kv(0, 0);

    float o[8][4];
#pragma unroll
    for (int i = 0; i < 8; i++)
#pragma unroll
        for (int j = 0; j < 4; j++) o[i][j] = 0.f;
    float m0r = -1e30f, m1r = -1e30f, l0r = 0.f, l1r = 0.f;

    const int r0gl = qbase + wm * 16 + lg;
    const int r1gl = r0gl + 8;

    for (int kt = 0; kt < nt; kt++) {
        const int s = kt & 1;
        if (kt + 1 < nt) {
            load_kv(kt + 1, s ^ 1);
            CP_WAIT(1);
        } else {
            CP_WAIT(0);
        }
        __syncthreads();

        const uint32_t stg = smb + SSTG + (uint32_t)s * SSTGSZ;
        const int kv0 = kt * 64;

        float c[8][4];
#pragma unroll
        for (int i = 0; i < 8; i++)
#pragma unroll
            for (int j = 0; j < 4; j++) c[i][j] = 0.f;

#pragma unroll
        for (int ks = 0; ks < 4; ks++) {
            uint32_t ah[4], al[4];
            LM4(ah, aq_h + ks * 32);
            LM4(al, aq_l + ks * 32);
#pragma unroll
            for (int pi = 0; pi < 4; pi++) {
                uint32_t kbh[4], kbl[4];
                uint32_t ka = stg + (uint32_t)((pi * 16 + krow) * 72 + kcol) * 2 +
                              ks * 32;
                LM4(kbh, ka);
                LM4(kbl, ka + 9216);
                mma16816(c[2 * pi], ah, kbh);
                mma16816(c[2 * pi], ah, kbl);
                mma16816(c[2 * pi], al, kbh);
                mma16816(c[2 * pi + 1], ah, kbh + 2);
                mma16816(c[2 * pi + 1], ah, kbl + 2);
                mma16816(c[2 * pi + 1], al, kbh + 2);
            }
        }

        const float* keepf = (const float*)(smc + SKEEP + s * 256);
        float mx0 = -1e30f, mx1 = -1e30f;
#pragma unroll
        for (int ni = 0; ni < 8; ni++) {
            int cg = kv0 + ni * 8 + 2 * lc;
            float k0 = keepf[ni * 8 + 2 * lc];
            float k1 = keepf[ni * 8 + 2 * lc + 1];
            float t0 = c[ni][0] * SC_LOG2 + k0;
            float t1 = c[ni][1] * SC_LOG2 + k1;
            float t2 = c[ni][2] * SC_LOG2 + k0;
            float t3 = c[ni][3] * SC_LOG2 + k1;
            if (cg > r0gl) t0 = -1e30f;
            if (cg + 1 > r0gl) t1 = -1e30f;
            if (cg > r1gl) t2 = -1e30f;
            if (cg + 1 > r1gl) t3 = -1e30f;
            c[ni][0] = t0; c[ni][1] = t1; c[ni][2] = t2; c[ni][3] = t3;
            mx0 = fmaxf(mx0, fmaxf(t0, t1));
            mx1 = fmaxf(mx1, fmaxf(t2, t3));
        }
        mx0 = fmaxf(mx0, __shfl_xor_sync(0xffffffffu, mx0, 1));
        mx0 = fmaxf(mx0, __shfl_xor_sync(0xffffffffu, mx0, 2));
        mx1 = fmaxf(mx1, __shfl_xor_sync(0xffffffffu, mx1, 1));
        mx1 = fmaxf(mx1, __shfl_xor_sync(0xffffffffu, mx1, 2));
        float mn0 = fmaxf(m0r, mx0), mn1 = fmaxf(m1r, mx1);
        float al0 = ex2f(m0r - mn0), al1 = ex2f(m1r - mn1);
        float ls0 = 0.f, ls1 = 0.f;
#pragma unroll
        for (int ni = 0; ni < 8; ni++) {
            float p0 = ex2f(c[ni][0] - mn0);
            float p1 = ex2f(c[ni][1] - mn0);
            float p2 = ex2f(c[ni][2] - mn1);
            float p3 = ex2f(c[ni][3] - mn1);
            c[ni][0] = p0; c[ni][1] = p1; c[ni][2] = p2; c[ni][3] = p3;
            ls0 += p0 + p1;
            ls1 += p2 + p3;
        }
        ls0 += __shfl_xor_sync(0xffffffffu, ls0, 1);
        ls0 += __shfl_xor_sync(0xffffffffu, ls0, 2);
        ls1 += __shfl_xor_sync(0xffffffffu, ls1, 1);
        ls1 += __shfl_xor_sync(0xffffffffu, ls1, 2);
        l0r = l0r * al0 + ls0;
        l1r = l1r * al1 + ls1;
        m0r = mn0;
        m1r = mn1;
#pragma unroll
        for (int nd = 0; nd < 8; nd++) {
            o[nd][0] *= al0; o[nd][1] *= al0;
            o[nd][2] *= al1; o[nd][3] *= al1;
        }

#pragma unroll
        for (int ks = 0; ks < 4; ks++) {
            uint32_t pah[4], pal[4];
#pragma unroll
            for (int u = 0; u < 2; u++) {
                float x0 = c[2 * ks + u][0], x1 = c[2 * ks + u][1];
                float x2 = c[2 * ks + u][2], x3 = c[2 * ks + u][3];
                pah[2 * u] = bfpack(x0, x1);
                pah[2 * u + 1] = bfpack(x2, x3);
                pal[2 * u] = bfpack(x0 - bfred(x0), x1 - bfred(x1));
                pal[2 * u + 1] = bfpack(x2 - bfred(x2), x3 - bfred(x3));
            }
#pragma unroll
            for (int pd = 0; pd < 4; pd++) {
                uint32_t vbh[4], vbl[4];
                uint32_t va = stg + 18432 +
                              (uint32_t)((pd * 16 + krow) * 72 + kcol) * 2 +
                              ks * 32;
                LM4(vbh, va);
                LM4(vbl, va + 9216);
                mma16816(o[2 * pd], pah, vbh);
                mma16816(o[2 * pd], pah, vbl);
                mma16816(o[2 * pd], pal, vbh);
                mma16816(o[2 * pd + 1], pah, vbh + 2);
                mma16816(o[2 * pd + 1], pah, vbl + 2);
                mma16816(o[2 * pd + 1], pal, vbh + 2);
            }
        }
        __syncthreads();
    }

    const float i0 = 1.f / l0r, i1 = 1.f / l1r;
    const size_t row0 = (size_t)b * Tn + qbase + wm * 16 + lg;
    const size_t row1 = row0 + 8;
#pragma unroll
    for (int nd = 0; nd < 8; nd++) {
        int col = h * Dn + nd * 8 + 2 * lc;
        float y0 = o[nd][0] * i0, y1 = o[nd][1] * i0;
        float y2 = o[nd][2] * i1, y3 = o[nd][3] * i1;
        *(uint32_t*)&g_ah[row0 * En + col] = bfpack(y0, y1);
        *(uint32_t*)&g_al[row0 * En + col] =
            bfpack(y0 - bfred(y0), y1 - bfred(y1));
        *(uint32_t*)&g_ah[row1 * En + col] = bfpack(y2, y3);
        *(uint32_t*)&g_al[row1 * En + col] =
            bfpack(y2 - bfred(y2), y3 - bfred(y3));
    }
}

// ---------------------------------------------------------------------------
extern "C" void kernel_launch(void* const* d_in, const int* in_sizes, int n_in,
                              void* d_out, int out_size) {
    (void)in_sizes; (void)n_in; (void)out_size;
    const float* x = (const float*)d_in[0];
    const int* idsw = (const int*)d_in[1];
    const float* w_qkv = (const float*)d_in[2];
    const float* w_out = (const float*)d_in[3];
    const float* b_out = (const float*)d_in[4];
    float* out = (float*)d_out;

    detect_ids_kernel<<<1, 1>>>(idsw);

    split_kernel<<<(Bn * Tn * En / 4) / 256, 256>>>(x);
    wsplit_kernel<true><<<dim3(3 * En / 32, Kdim / 32), dim3(32, 8)>>>(w_qkv);
    wsplit_kernel<false><<<dim3(En / 32, Kdim / 32), dim3(32, 8)>>>(w_out);

    const int gsmem = 3 * 30720;  // 92160 B
    cudaFuncSetAttribute(hmma_gemm<3 * En, true>,
                         cudaFuncAttributeMaxDynamicSharedMemorySize, gsmem);
    cudaFuncSetAttribute(hmma_gemm<En, false>,
                         cudaFuncAttributeMaxDynamicSharedMemorySize, gsmem);

    // 1) QKV projection (HMMA) -> bf16 hi/lo q/k ([bh][t][d]) + v^T ([bh][d][t])
    dim3 g1(3 * En / 64, Bn * Tn / 128);  // (48, 64)
    hmma_gemm<3 * En, true><<<g1, 256, gsmem>>>(nullptr, nullptr);

    // 2) flash attention (HMMA bf16x3) -> writes y hi/lo into g_ah/g_al
    cudaFuncSetAttribute(flash_kernel,
                         cudaFuncAttributeMaxDynamicSharedMemorySize, FLASH_SMEM);
    dim3 g2(Tn / 128, Bn * Hn);  // (16, 64)
    flash_kernel<<<g2, 256, FLASH_SMEM>>>(idsw);

    // 3) output projection + bias (HMMA)
    dim3 g3(En / 64, Bn * Tn / 128);  // (16, 64)
    hmma_gemm<En, false><<<g3, 256, gsmem>>>(b_out, out);
}

// round 6
// speedup vs baseline: 2.8623x; 1.0429x over previous
#include <cuda_runtime.h>
#include <cuda_bf16.h>
#include <cstdint>

#define Bn 4
#define Tn 2048
#define En 1024
#define Hn 16
#define Dn 64
#define Kdim 1024

// ---------------- static device scratch (allocation-free) -------------------
__device__ __nv_bfloat16 g_ah[Bn * Tn * En];       // activation hi (x, then y)
__device__ __nv_bfloat16 g_al[Bn * Tn * En];       // activation lo
__device__ __nv_bfloat16 g_wqh[3 * En * Kdim];     // w_qkv^T hi  [N=3072][K=1024]
__device__ __nv_bfloat16 g_wql[3 * En * Kdim];
__device__ __nv_bfloat16 g_woh[En * Kdim];         // w_out^T hi
__device__ __nv_bfloat16 g_wol[En * Kdim];
__device__ __nv_bfloat16 g_qh[Bn * Hn * Tn * Dn];  // q hi  [bh][t][d]
__device__ __nv_bfloat16 g_ql[Bn * Hn * Tn * Dn];
__device__ __nv_bfloat16 g_kh[Bn * Hn * Tn * Dn];  // k hi  [bh][t][d]
__device__ __nv_bfloat16 g_kl[Bn * Hn * Tn * Dn];
__device__ __nv_bfloat16 g_vth[Bn * Hn * Dn * Tn]; // v hi TRANSPOSED [bh][d][t]
__device__ __nv_bfloat16 g_vtl[Bn * Hn * Dn * Tn];
__device__ int g_shift;

// ---------------- helpers (baseline PTX only: sm_80+ features) --------------
__device__ __forceinline__ void cp16(uint32_t s, const void* g) {
    asm volatile("cp.async.cg.shared.global [%0], [%1], 16;" :: "r"(s), "l"(g));
}
#define CP_COMMIT() asm volatile("cp.async.commit_group;" ::: "memory")
#define CP_WAIT(n) asm volatile("cp.async.wait_group %0;" :: "n"(n) : "memory")

__device__ __forceinline__ uint32_t smem_u32(const void* p) {
    uint32_t a;
    asm("{ .reg .u64 t; cvta.to.shared.u64 t, %1; cvt.u32.u64 %0, t; }"
        : "=r"(a) : "l"(p));
    return a;
}
__device__ __forceinline__ void mma16816(float* c, const uint32_t* a,
                                         const uint32_t* b) {
    asm volatile(
        "mma.sync.aligned.m16n8k16.row.col.f32.bf16.bf16.f32 "
        "{%0,%1,%2,%3}, {%4,%5,%6,%7}, {%8,%9}, {%0,%1,%2,%3};"
        : "+f"(c[0]), "+f"(c[1]), "+f"(c[2]), "+f"(c[3])
        : "r"(a[0]), "r"(a[1]), "r"(a[2]), "r"(a[3]), "r"(b[0]), "r"(b[1]));
}
#define LM4(r, addr)                                                       \
    asm volatile("ldmatrix.sync.aligned.m8n8.x4.shared.b16 "               \
                 "{%0,%1,%2,%3}, [%4];"                                    \
                 : "=r"((r)[0]), "=r"((r)[1]), "=r"((r)[2]), "=r"((r)[3])  \
                 : "r"(addr))
__device__ __forceinline__ float ex2f(float x) {
    float r;
    asm("ex2.approx.f32 %0, %1;" : "=f"(r) : "f"(x));
    return r;
}
__device__ __forceinline__ uint32_t bfpack(float lo, float hi) {
    __nv_bfloat162 t = __floats2bfloat162_rn(lo, hi);
    return *(uint32_t*)&t;
}
__device__ __forceinline__ float bfred(float x) {
    return __bfloat162float(__float2bfloat16_rn(x));
}

// ---------------- int64-vs-int32 input_ids detection ------------------------
__global__ void detect_ids_kernel(const int* __restrict__ w) {
    bool all0 = true;
    for (int i = 1; i < 64; i += 2) all0 = all0 && (w[i] == 0);
    g_shift = all0 ? 1 : 0;
}

// ---------------- fp32 -> bf16 hi/lo split (x) ------------------------------
__global__ void split_kernel(const float* __restrict__ src) {
    int i = blockIdx.x * blockDim.x + threadIdx.x;
    float4 v = ((const float4*)src)[i];
    float a[4] = {v.x, v.y, v.z, v.w};
    uint32_t h0 = bfpack(a[0], a[1]), h1 = bfpack(a[2], a[3]);
    uint32_t l0 = bfpack(a[0] - bfred(a[0]), a[1] - bfred(a[1]));
    uint32_t l1 = bfpack(a[2] - bfred(a[2]), a[3] - bfred(a[3]));
    uint32_t* ph = (uint32_t*)g_ah;
    uint32_t* pl = (uint32_t*)g_al;
    ph[2 * i] = h0; ph[2 * i + 1] = h1;
    pl[2 * i] = l0; pl[2 * i + 1] = l1;
}

// ---------------- weight transpose + split: W[K,N] -> Wt[N,K] hi/lo ---------
template <bool QKVW>
__global__ void wsplit_kernel(const float* __restrict__ W) {
    constexpr int Nw = QKVW ? 3 * En : En;
    __nv_bfloat16* oh = QKVW ? g_wqh : g_woh;
    __nv_bfloat16* ol = QKVW ? g_wql : g_wol;
    __shared__ float tile[32][33];
    int n0 = blockIdx.x * 32, k0 = blockIdx.y * 32;
    int tx = threadIdx.x, ty = threadIdx.y;  // (32, 8)
#pragma unroll
    for (int i = 0; i < 32; i += 8)
        tile[ty + i][tx] = W[(size_t)(k0 + ty + i) * Nw + n0 + tx];
    __syncthreads();
#pragma unroll
    for (int i = 0; i < 32; i += 8) {
        float a = tile[tx][ty + i];
        size_t o = (size_t)(n0 + ty + i) * Kdim + k0 + tx;
        oh[o] = __float2bfloat16_rn(a);
        ol[o] = __float2bfloat16_rn(a - bfred(a));
    }
}

// ---------------- HMMA bf16x3 GEMM: C[8192, Ntot] = A * W^T -----------------
// BM=128, BN=128, BK=32. 2-stage cp.async, ldmatrix fragment loads.
// 8 warps as 4(m) x 2(n), warp tile 32x64. 3 products (AhBh+AhBl+AlBh).
template <int Ntot, bool QKV>
__global__ void __launch_bounds__(256, 2)
hmma_gemm(const float* __restrict__ bias, float* __restrict__ Cout) {
    constexpr int ROWB = 80;                    // bytes per smem row (40 bf16)
    constexpr int OFF_AL = 10240;               // 128*80
    constexpr int OFF_BH = 20480;
    constexpr int OFF_BL = 30720;
    constexpr int STG = 40960;                  // bytes per stage
    constexpr int NK = Kdim / 32;               // 32
    extern __shared__ char smc[];
    const uint32_t smb = smem_u32(smc);

    const __nv_bfloat16* Bhg = QKV ? g_wqh : g_woh;
    const __nv_bfloat16* Blg = QKV ? g_wql : g_wol;

    const int m0 = blockIdx.y * 128;
    const int n0 = blockIdx.x * 128;
    const int tid = threadIdx.x;
    const int wid = tid >> 5;
    const int lane = tid & 31;
    const int wm = wid >> 1;   // 0..3
    const int wn = wid & 1;    // 0..1
    const int lg = lane >> 2;
    const int lc = lane & 3;
    // ldmatrix lane address components
    const int arow = (lane & 7) + ((lane >> 3) & 1) * 8;  // A: row-major frag
    const int acol = ((lane >> 4) & 1) * 8;
    const int brow = (lane & 7) + ((lane >> 4) & 1) * 8;  // B: col-major frag
    const int bcol = ((lane >> 3) & 1) * 8;

    float acc[2][8][4];
#pragma unroll
    for (int mi = 0; mi < 2; mi++)
#pragma unroll
        for (int ni = 0; ni < 8; ni++)
#pragma unroll
            for (int r = 0; r < 4; r++) acc[mi][ni][r] = 0.f;

    auto load_stage = [&](int kc, int s) {
        const int k0 = kc * 32;
        const uint32_t sb = smb + (uint32_t)s * STG;
#pragma unroll
        for (int c = tid; c < 512; c += 256) {
            int row = c >> 2, col8 = (c & 3) * 8;
            uint32_t sa = sb + (uint32_t)(row * ROWB + col8 * 2);
            size_t ga = (size_t)(m0 + row) * Kdim + k0 + col8;
            cp16(sa, g_ah + ga);
            cp16(sa + OFF_AL, g_al + ga);
            uint32_t sbw = sb + OFF_BH + (uint32_t)(row * ROWB + col8 * 2);
            size_t gb = (size_t)(n0 + row) * Kdim + k0 + col8;
            cp16(sbw, Bhg + gb);
            cp16(sbw + (OFF_BL - OFF_BH), Blg + gb);
        }
        CP_COMMIT();
    };

    load_stage(0, 0);

    int s = 0;
    for (int kc = 0; kc < NK; kc++) {
        CP_WAIT(0);
        __syncthreads();
        if (kc + 1 < NK) load_stage(kc + 1, s ^ 1);

        const uint32_t sb = smb + (uint32_t)s * STG;
        const uint32_t aB = sb + (uint32_t)((wm * 32 + arow) * ROWB + acol * 2);
        const uint32_t bB = sb + OFF_BH + (uint32_t)(brow * ROWB + bcol * 2);
#pragma unroll
        for (int ks = 0; ks < 2; ks++) {
            uint32_t ah[2][4], al[2][4];
#pragma unroll
            for (int mi = 0; mi < 2; mi++) {
                uint32_t a = aB + mi * 16 * ROWB + ks * 32;
                LM4(ah[mi], a);
                LM4(al[mi], a + OFF_AL);
            }
#pragma unroll
            for (int nj = 0; nj < 4; nj++) {
                uint32_t bh[4], bl[4];
                uint32_t a = bB + (wn * 64 + nj * 16) * ROWB + ks * 32;
                LM4(bh, a);
                LM4(bl, a + (OFF_BL - OFF_BH));
#pragma unroll
                for (int mi = 0; mi < 2; mi++) {
                    mma16816(acc[mi][2 * nj], ah[mi], bh);
                    mma16816(acc[mi][2 * nj], ah[mi], bl);
                    mma16816(acc[mi][2 * nj], al[mi], bh);
                    mma16816(acc[mi][2 * nj + 1], ah[mi], bh + 2);
                    mma16816(acc[mi][2 * nj + 1], ah[mi], bl + 2);
                    mma16816(acc[mi][2 * nj + 1], al[mi], bh + 2);
                }
            }
        }
        s ^= 1;
    }

    if (QKV) {
        const int which = n0 >> 10;  // tile fully inside one of q/k/v regions
        const int b = m0 >> 11;
        if (which < 2) {
            __nv_bfloat16* dh = which == 0 ? g_qh : g_kh;
            __nv_bfloat16* dl = which == 0 ? g_ql : g_kl;
#pragma unroll
            for (int mi = 0; mi < 2; mi++)
#pragma unroll
                for (int ni = 0; ni < 8; ni++)
#pragma unroll
                    for (int half = 0; half < 2; half++) {
                        int m = m0 + wm * 32 + mi * 16 + lg + half * 8;
                        int t = m & (Tn - 1);
                        int n = n0 + wn * 64 + ni * 8 + lc * 2;
                        int h = (n & 1023) >> 6;
                        int d = n & 63;
                        float vx = acc[mi][ni][half * 2];
                        float vy = acc[mi][ni][half * 2 + 1];
                        size_t off = (((size_t)(b * Hn + h)) * Tn + t) * Dn + d;
                        *(uint32_t*)&dh[off] = bfpack(vx, vy);
                        *(uint32_t*)&dl[off] =
                            bfpack(vx - bfred(vx), vy - bfred(vy));
                    }
        } else {
            // V: transpose through smem -> [bh][d][t] (tile spans 2 heads)
            __syncthreads();  // all warps done reading stage smem
            __nv_bfloat16* sVh = (__nv_bfloat16*)smc;   // [128 col][136]
            __nv_bfloat16* sVl = sVh + 128 * 136;
#pragma unroll
            for (int mi = 0; mi < 2; mi++)
#pragma unroll
                for (int ni = 0; ni < 8; ni++)
#pragma unroll
                    for (int half = 0; half < 2; half++) {
                        int tl = wm * 32 + mi * 16 + lg + half * 8;
                        int col = wn * 64 + ni * 8 + lc * 2;
                        float vx = acc[mi][ni][half * 2];
                        float vy = acc[mi][ni][half * 2 + 1];
                        sVh[col * 136 + tl] = __float2bfloat16_rn(vx);
                        sVh[(col + 1) * 136 + tl] = __float2bfloat16_rn(vy);
                        sVl[col * 136 + tl] = __float2bfloat16_rn(vx - bfred(vx));
                        sVl[(col + 1) * 136 + tl] =
                            __float2bfloat16_rn(vy - bfred(vy));
                    }
            __syncthreads();
            const int h0 = (n0 & 1023) >> 6;
            const int t0 = m0 & (Tn - 1);
#pragma unroll
            for (int c = tid; c < 2048; c += 256) {
                int col = c >> 4, t8 = (c & 15) * 8;
                int h = h0 + (col >> 6);
                int d = col & 63;
                uint4 vh = *(uint4*)&sVh[col * 136 + t8];
                uint4 vl = *(uint4*)&sVl[col * 136 + t8];
                size_t off = (((size_t)(b * Hn + h)) * Dn + d) * Tn + t0 + t8;
                *(uint4*)&g_vth[off] = vh;
                *(uint4*)&g_vtl[off] = vl;
            }
        }
    } else {
#pragma unroll
        for (int mi = 0; mi < 2; mi++)
#pragma unroll
            for (int ni = 0; ni < 8; ni++) {
                int r0 = m0 + wm * 32 + mi * 16 + lg;
                int n = n0 + wn * 64 + ni * 8 + lc * 2;
#pragma unroll
                for (int half = 0; half < 2; half++) {
                    int m = r0 + half * 8;
                    float2 v = make_float2(acc[mi][ni][half * 2],
                                           acc[mi][ni][half * 2 + 1]);
                    v.x += bias[n];
                    v.y += bias[n + 1];
                    *(float2*)&Cout[(size_t)m * Ntot + n] = v;
                }
            }
    }
}

// ---------------- flash attention: HMMA bf16x3, FA-2 style ------------------
#define SQH 0
#define SQL 18432
#define SSTG 36864       // stage base; per stage: KH+0 KL+9216 VH+18432 VL+27648
#define SSTGSZ 36864
#define SKEEP 110592     // float[2][64]
#define FLASH_SMEM 111104
#define SC_LOG2 0.18033688f  // 0.125 * log2(e)

__global__ void __launch_bounds__(256, 2)
flash_kernel(const int* __restrict__ idsw) {
    extern __shared__ char smc[];
    const uint32_t smb = smem_u32(smc);

    const int qt = (int)gridDim.x - 1 - (int)blockIdx.x;
    const int bh = blockIdx.y;
    const int b = bh >> 4;
    const int h = bh & 15;
    const int qbase = qt * 128;
    const int tid = threadIdx.x;
    const int wm = tid >> 5;
    const int lane = tid & 31;
    const int lg = lane >> 2;
    const int lc = lane & 3;
    const int shift = g_shift;
    const int nt = 2 * qt + 2;

    const int qrow = (lane & 7) + ((lane >> 3) & 1) * 8;
    const int qcol = ((lane >> 4) & 1) * 8;
    const int krow = (lane & 7) + ((lane >> 4) & 1) * 8;
    const int kcol = ((lane >> 3) & 1) * 8;

    const uint32_t aq_h = smb + SQH + (uint32_t)((wm * 16 + qrow) * 72 + qcol) * 2;
    const uint32_t aq_l = aq_h + (SQL - SQH);

    auto load_kv = [&](int kt, int s) {
        const int kv0 = kt * 64;
        const uint32_t sb = smb + SSTG + (uint32_t)s * SSTGSZ;
#pragma unroll
        for (int ch = tid; ch < 512; ch += 256) {
            int r = ch >> 3, c8 = (ch & 7) << 3;
            uint32_t so = sb + (uint32_t)(r * 72 + c8) * 2;
            size_t gk = ((size_t)bh * Tn + kv0 + r) * Dn + c8;
            cp16(so, g_kh + gk);
            cp16(so + 9216, g_kl + gk);
            size_t gv = ((size_t)bh * Dn + r) * Tn + kv0 + c8;
            cp16(so + 18432, g_vth + gv);
            cp16(so + 27648, g_vtl + gv);
        }
        if (tid < 64) {
            size_t w = ((size_t)(b * Tn + kv0 + tid)) << shift;
            float ka = (idsw[w] != 0) ? 0.f : -1e30f;
            *(float*)(smc + SKEEP + s * 256 + tid * 4) = ka;
        }
        CP_COMMIT();
    };

#pragma unroll
    for (int ch = tid; ch < 1024; ch += 256) {
        int r = ch >> 3, c8 = (ch & 7) << 3;
        uint32_t so = smb + SQH + (uint32_t)(r * 72 + c8) * 2;
        size_t gq = ((size_t)bh * Tn + qbase + r) * Dn + c8;
        cp16(so, g_qh + gq);
        cp16(so + (SQL - SQH), g_ql + gq);
    }
    load_kv(0, 0);

    float o[8][4];
#pragma unroll
    for (int i = 0; i < 8; i++)
#pragma unroll
        for (int j = 0; j < 4; j++) o[i][j] = 0.f;
    float m0r = -1e30f, m1r = -1e30f, l0r = 0.f, l1r = 0.f;

    const int r0gl = qbase + wm * 16 + lg;
    const int r1gl = r0gl + 8;

    for (int kt = 0; kt < nt; kt++) {
        const int s = kt & 1;
        if (kt + 1 < nt) {
            load_kv(kt + 1, s ^ 1);
            CP_WAIT(1);
        } else {
            CP_WAIT(0);
        }
        __syncthreads();

        const uint32_t stg = smb + SSTG + (uint32_t)s * SSTGSZ;
        const int kv0 = kt * 64;

        float c[8][4];
#pragma unroll
        for (int i = 0; i < 8; i++)
#pragma unroll
            for (int j = 0; j < 4; j++) c[i][j] = 0.f;

#pragma unroll
        for (int ks = 0; ks < 4; ks++) {
            uint32_t ah[4], al[4];
            LM4(ah, aq_h + ks * 32);
            LM4(al, aq_l + ks * 32);
#pragma unroll
            for (int pi = 0; pi < 4; pi++) {
                uint32_t kbh[4], kbl[4];
                uint32_t ka = stg + (uint32_t)((pi * 16 + krow) * 72 + kcol) * 2 +
                              ks * 32;
                LM4(kbh, ka);
                LM4(kbl, ka + 9216);
                mma16816(c[2 * pi], ah, kbh);
                mma16816(c[2 * pi], ah, kbl);
                mma16816(c[2 * pi], al, kbh);
                mma16816(c[2 * pi + 1], ah, kbh + 2);
                mma16816(c[2 * pi + 1], ah, kbl + 2);
                mma16816(c[2 * pi + 1], al, kbh + 2);
            }
        }

        const float* keepf = (const float*)(smc + SKEEP + s * 256);
        float mx0 = -1e30f, mx1 = -1e30f;
#pragma unroll
        for (int ni = 0; ni < 8; ni++) {
            int cg = kv0 + ni * 8 + 2 * lc;
            float k0 = keepf[ni * 8 + 2 * lc];
            float k1 = keepf[ni * 8 + 2 * lc + 1];
            float t0 = c[ni][0] * SC_LOG2 + k0;
            float t1 = c[ni][1] * SC_LOG2 + k1;
            float t2 = c[ni][2] * SC_LOG2 + k0;
            float t3 = c[ni][3] * SC_LOG2 + k1;
            if (cg > r0gl) t0 = -1e30f;
            if (cg + 1 > r0gl) t1 = -1e30f;
            if (cg > r1gl) t2 = -1e30f;
            if (cg + 1 > r1gl) t3 = -1e30f;
            c[ni][0] = t0; c[ni][1] = t1; c[ni][2] = t2; c[ni][3] = t3;
            mx0 = fmaxf(mx0, fmaxf(t0, t1));
            mx1 = fmaxf(mx1, fmaxf(t2, t3));
        }
        mx0 = fmaxf(mx0, __shfl_xor_sync(0xffffffffu, mx0, 1));
        mx0 = fmaxf(mx0, __shfl_xor_sync(0xffffffffu, mx0, 2));
        mx1 = fmaxf(mx1, __shfl_xor_sync(0xffffffffu, mx1, 1));
        mx1 = fmaxf(mx1, __shfl_xor_sync(0xffffffffu, mx1, 2));
        float mn0 = fmaxf(m0r, mx0), mn1 = fmaxf(m1r, mx1);
        float al0 = ex2f(m0r - mn0), al1 = ex2f(m1r - mn1);
        float ls0 = 0.f, ls1 = 0.f;
#pragma unroll
        for (int ni = 0; ni < 8; ni++) {
            float p0 = ex2f(c[ni][0] - mn0);
            float p1 = ex2f(c[ni][1] - mn0);
            float p2 = ex2f(c[ni][2] - mn1);
            float p3 = ex2f(c[ni][3] - mn1);
            c[ni][0] = p0; c[ni][1] = p1; c[ni][2] = p2; c[ni][3] = p3;
            ls0 += p0 + p1;
            ls1 += p2 + p3;
        }
        ls0 += __shfl_xor_sync(0xffffffffu, ls0, 1);
        ls0 += __shfl_xor_sync(0xffffffffu, ls0, 2);
        ls1 += __shfl_xor_sync(0xffffffffu, ls1, 1);
        ls1 += __shfl_xor_sync(0xffffffffu, ls1, 2);
        l0r = l0r * al0 + ls0;
        l1r = l1r * al1 + ls1;
        m0r = mn0;
        m1r = mn1;
#pragma unroll
        for (int nd = 0; nd < 8; nd++) {
            o[nd][0] *= al0; o[nd][1] *= al0;
            o[nd][2] *= al1; o[nd][3] *= al1;
        }

#pragma unroll
        for (int ks = 0; ks < 4; ks++) {
            uint32_t pah[4], pal[4];
#pragma unroll
            for (int u = 0; u < 2; u++) {
                float x0 = c[2 * ks + u][0], x1 = c[2 * ks + u][1];
                float x2 = c[2 * ks + u][2], x3 = c[2 * ks + u][3];
                pah[2 * u] = bfpack(x0, x1);
                pah[2 * u + 1] = bfpack(x2, x3);
                pal[2 * u] = bfpack(x0 - bfred(x0), x1 - bfred(x1));
                pal[2 * u + 1] = bfpack(x2 - bfred(x2), x3 - bfred(x3));
            }
#pragma unroll
            for (int pd = 0; pd < 4; pd++) {
                uint32_t vbh[4], vbl[4];
                uint32_t va = stg + 18432 +
                              (uint32_t)((pd * 16 + krow) * 72 + kcol) * 2 +
                              ks * 32;
                LM4(vbh, va);
                LM4(vbl, va + 9216);
                mma16816(o[2 * pd], pah, vbh);
                mma16816(o[2 * pd], pah, vbl);
                mma16816(o[2 * pd], pal, vbh);
                mma16816(o[2 * pd + 1], pah, vbh + 2);
                mma16816(o[2 * pd + 1], pah, vbl + 2);
                mma16816(o[2 * pd + 1], pal, vbh + 2);
            }
        }
        __syncthreads();
    }

    const float i0 = 1.f / l0r, i1 = 1.f / l1r;
    const size_t row0 = (size_t)b * Tn + qbase + wm * 16 + lg;
    const size_t row1 = row0 + 8;
#pragma unroll
    for (int nd = 0; nd < 8; nd++) {
        int col = h * Dn + nd * 8 + 2 * lc;
        float y0 = o[nd][0] * i0, y1 = o[nd][1] * i0;
        float y2 = o[nd][2] * i1, y3 = o[nd][3] * i1;
        *(uint32_t*)&g_ah[row0 * En + col] = bfpack(y0, y1);
        *(uint32_t*)&g_al[row0 * En + col] =
            bfpack(y0 - bfred(y0), y1 - bfred(y1));
        *(uint32_t*)&g_ah[row1 * En + col] = bfpack(y2, y3);
        *(uint32_t*)&g_al[row1 * En + col] =
            bfpack(y2 - bfred(y2), y3 - bfred(y3));
    }
}

// ---------------------------------------------------------------------------
extern "C" void kernel_launch(void* const* d_in, const int* in_sizes, int n_in,
                              void* d_out, int out_size) {
    (void)in_sizes; (void)n_in; (void)out_size;
    const float* x = (const float*)d_in[0];
    const int* idsw = (const int*)d_in[1];
    const float* w_qkv = (const float*)d_in[2];
    const float* w_out = (const float*)d_in[3];
    const float* b_out = (const float*)d_in[4];
    float* out = (float*)d_out;

    detect_ids_kernel<<<1, 1>>>(idsw);

    split_kernel<<<(Bn * Tn * En / 4) / 256, 256>>>(x);
    wsplit_kernel<true><<<dim3(3 * En / 32, Kdim / 32), dim3(32, 8)>>>(w_qkv);
    wsplit_kernel<false><<<dim3(En / 32, Kdim / 32), dim3(32, 8)>>>(w_out);

    const int gsmem = 2 * 40960;  // 81920 B
    cudaFuncSetAttribute(hmma_gemm<3 * En, true>,
                         cudaFuncAttributeMaxDynamicSharedMemorySize, gsmem);
    cudaFuncSetAttribute(hmma_gemm<En, false>,
                         cudaFuncAttributeMaxDynamicSharedMemorySize, gsmem);

    // 1) QKV projection (HMMA) -> bf16 hi/lo q/k ([bh][t][d]) + v^T ([bh][d][t])
    dim3 g1(3 * En / 128, Bn * Tn / 128);  // (24, 64)
    hmma_gemm<3 * En, true><<<g1, 256, gsmem>>>(nullptr, nullptr);

    // 2) flash attention (HMMA bf16x3) -> writes y hi/lo into g_ah/g_al
    cudaFuncSetAttribute(flash_kernel,
                         cudaFuncAttributeMaxDynamicSharedMemorySize, FLASH_SMEM);
    dim3 g2(Tn / 128, Bn * Hn);  // (16, 64)
    flash_kernel<<<g2, 256, FLASH_SMEM>>>(idsw);

    // 3) output projection + bias (HMMA)
    dim3 g3(En / 128, Bn * Tn / 128);  // (8, 64)
    hmma_gemm<En, false><<<g3, 256, gsmem>>>(b_out, out);
}

// round 8
// speedup vs baseline: 3.9343x; 1.3746x over previous
#include <cuda_runtime.h>
#include <cuda_fp16.h>
#include <cstdint>

#define Bn 4
#define Tn 2048
#define En 1024
#define Hn 16
#define Dn 64
#define Kdim 1024

// ---------------- static device scratch (allocation-free) -------------------
__device__ __half g_ah[Bn * Tn * En];        // activation hi (x, then y)
__device__ __half g_al[Bn * Tn * En];        // activation lo
__device__ __half g_wq[3 * En * Kdim];       // w_qkv^T fp16 single [N=3072][K]
__device__ __half g_wo[En * Kdim];           // w_out^T fp16 single
__device__ __half g_qh[Bn * Hn * Tn * Dn];   // q hi  [bh][t][d]
__device__ __half g_ql[Bn * Hn * Tn * Dn];   // q lo
__device__ __half g_k[Bn * Hn * Tn * Dn];    // k fp16 single [bh][t][d]
__device__ __half g_vt[Bn * Hn * Dn * Tn];   // v fp16 single TRANSPOSED [bh][d][t]
__device__ int g_shift;

// ---------------- helpers (baseline PTX only: sm_80+ features) --------------
__device__ __forceinline__ void cp16(uint32_t s, const void* g) {
    asm volatile("cp.async.cg.shared.global [%0], [%1], 16;" :: "r"(s), "l"(g));
}
#define CP_COMMIT() asm volatile("cp.async.commit_group;" ::: "memory")
#define CP_WAIT(n) asm volatile("cp.async.wait_group %0;" :: "n"(n) : "memory")

__device__ __forceinline__ uint32_t smem_u32(const void* p) {
    uint32_t a;
    asm("{ .reg .u64 t; cvta.to.shared.u64 t, %1; cvt.u32.u64 %0, t; }"
        : "=r"(a) : "l"(p));
    return a;
}
__device__ __forceinline__ void mma16816(float* c, const uint32_t* a,
                                         const uint32_t* b) {
    asm volatile(
        "mma.sync.aligned.m16n8k16.row.col.f32.f16.f16.f32 "
        "{%0,%1,%2,%3}, {%4,%5,%6,%7}, {%8,%9}, {%0,%1,%2,%3};"
        : "+f"(c[0]), "+f"(c[1]), "+f"(c[2]), "+f"(c[3])
        : "r"(a[0]), "r"(a[1]), "r"(a[2]), "r"(a[3]), "r"(b[0]), "r"(b[1]));
}
#define LM4(r, addr)                                                       \
    asm volatile("ldmatrix.sync.aligned.m8n8.x4.shared.b16 "               \
                 "{%0,%1,%2,%3}, [%4];"                                    \
                 : "=r"((r)[0]), "=r"((r)[1]), "=r"((r)[2]), "=r"((r)[3])  \
                 : "r"(addr))
__device__ __forceinline__ float ex2f(float x) {
    float r;
    asm("ex2.approx.f32 %0, %1;" : "=f"(r) : "f"(x));
    return r;
}
__device__ __forceinline__ uint32_t hpack(float lo, float hi) {
    __half2 t = __floats2half2_rn(lo, hi);
    return *(uint32_t*)&t;
}
__device__ __forceinline__ float hred(float x) {
    return __half2float(__float2half_rn(x));
}

// ---------------- int64-vs-int32 input_ids detection ------------------------
__global__ void detect_ids_kernel(const int* __restrict__ w) {
    bool all0 = true;
    for (int i = 1; i < 64; i += 2) all0 = all0 && (w[i] == 0);
    g_shift = all0 ? 1 : 0;
}

// ---------------- fp32 -> fp16 hi/lo split (x) ------------------------------
__global__ void split_kernel(const float* __restrict__ src) {
    int i = blockIdx.x * blockDim.x + threadIdx.x;
    float4 v = ((const float4*)src)[i];
    float a[4] = {v.x, v.y, v.z, v.w};
    uint32_t h0 = hpack(a[0], a[1]), h1 = hpack(a[2], a[3]);
    uint32_t l0 = hpack(a[0] - hred(a[0]), a[1] - hred(a[1]));
    uint32_t l1 = hpack(a[2] - hred(a[2]), a[3] - hred(a[3]));
    uint32_t* ph = (uint32_t*)g_ah;
    uint32_t* pl = (uint32_t*)g_al;
    ph[2 * i] = h0; ph[2 * i + 1] = h1;
    pl[2 * i] = l0; pl[2 * i + 1] = l1;
}

// ---------------- weight transpose: W[K,N] -> Wt[N,K] fp16 single -----------
template <bool QKVW>
__global__ void wsplit_kernel(const float* __restrict__ W) {
    constexpr int Nw = QKVW ? 3 * En : En;
    __half* oh = QKVW ? g_wq : g_wo;
    __shared__ float tile[32][33];
    int n0 = blockIdx.x * 32, k0 = blockIdx.y * 32;
    int tx = threadIdx.x, ty = threadIdx.y;  // (32, 8)
#pragma unroll
    for (int i = 0; i < 32; i += 8)
        tile[ty + i][tx] = W[(size_t)(k0 + ty + i) * Nw + n0 + tx];
    __syncthreads();
#pragma unroll
    for (int i = 0; i < 32; i += 8) {
        float a = tile[tx][ty + i];
        oh[(size_t)(n0 + ty + i) * Kdim + k0 + tx] = __float2half_rn(a);
    }
}

// ---------------- HMMA fp16 2-product GEMM: C = (Ah+Al) * W^T ---------------
// BM=128, BN=128, BK=32. 2-stage cp.async, ldmatrix. 8 warps 4(m)x2(n),
// warp tile 32x64. 2 products per unit: AhB + AlB (B single fp16).
template <int Ntot, bool QKV>
__global__ void __launch_bounds__(256, 2)
hmma_gemm(const float* __restrict__ bias, float* __restrict__ Cout) {
    constexpr int ROWB = 80;                    // bytes per smem row (40 half)
    constexpr int OFF_AL = 10240;               // 128*80
    constexpr int OFF_B = 20480;
    constexpr int STG = 30720;                  // bytes per stage
    constexpr int NK = Kdim / 32;               // 32
    extern __shared__ char smc[];
    const uint32_t smb = smem_u32(smc);

    const __half* Bg = QKV ? g_wq : g_wo;

    const int m0 = blockIdx.y * 128;
    const int n0 = blockIdx.x * 128;
    const int tid = threadIdx.x;
    const int wid = tid >> 5;
    const int lane = tid & 31;
    const int wm = wid >> 1;   // 0..3
    const int wn = wid & 1;    // 0..1
    const int lg = lane >> 2;
    const int lc = lane & 3;
    const int arow = (lane & 7) + ((lane >> 3) & 1) * 8;
    const int acol = ((lane >> 4) & 1) * 8;
    const int brow = (lane & 7) + ((lane >> 4) & 1) * 8;
    const int bcol = ((lane >> 3) & 1) * 8;

    float acc[2][8][4];
#pragma unroll
    for (int mi = 0; mi < 2; mi++)
#pragma unroll
        for (int ni = 0; ni < 8; ni++)
#pragma unroll
            for (int r = 0; r < 4; r++) acc[mi][ni][r] = 0.f;

    auto load_stage = [&](int kc, int s) {
        const int k0 = kc * 32;
        const uint32_t sb = smb + (uint32_t)s * STG;
#pragma unroll
        for (int c = tid; c < 512; c += 256) {
            int row = c >> 2, col8 = (c & 3) * 8;
            uint32_t sa = sb + (uint32_t)(row * ROWB + col8 * 2);
            size_t ga = (size_t)(m0 + row) * Kdim + k0 + col8;
            cp16(sa, g_ah + ga);
            cp16(sa + OFF_AL, g_al + ga);
            cp16(sb + OFF_B + (uint32_t)(row * ROWB + col8 * 2),
                 Bg + (size_t)(n0 + row) * Kdim + k0 + col8);
        }
        CP_COMMIT();
    };

    load_stage(0, 0);

    int s = 0;
    for (int kc = 0; kc < NK; kc++) {
        CP_WAIT(0);
        __syncthreads();
        if (kc + 1 < NK) load_stage(kc + 1, s ^ 1);

        const uint32_t sb = smb + (uint32_t)s * STG;
        const uint32_t aB = sb + (uint32_t)((wm * 32 + arow) * ROWB + acol * 2);
        const uint32_t bB = sb + OFF_B + (uint32_t)(brow * ROWB + bcol * 2);
#pragma unroll
        for (int ks = 0; ks < 2; ks++) {
            uint32_t ah[2][4], al[2][4];
#pragma unroll
            for (int mi = 0; mi < 2; mi++) {
                uint32_t a = aB + mi * 16 * ROWB + ks * 32;
                LM4(ah[mi], a);
                LM4(al[mi], a + OFF_AL);
            }
#pragma unroll
            for (int nj = 0; nj < 4; nj++) {
                uint32_t b[4];
                LM4(b, bB + (wn * 64 + nj * 16) * ROWB + ks * 32);
#pragma unroll
                for (int mi = 0; mi < 2; mi++) {
                    mma16816(acc[mi][2 * nj], ah[mi], b);
                    mma16816(acc[mi][2 * nj], al[mi], b);
                    mma16816(acc[mi][2 * nj + 1], ah[mi], b + 2);
                    mma16816(acc[mi][2 * nj + 1], al[mi], b + 2);
                }
            }
        }
        s ^= 1;
    }

    if (QKV) {
        const int which = n0 >> 10;
        const int b = m0 >> 11;
        if (which == 0) {
            // Q: split hi/lo (A-side of the S MMA)
#pragma unroll
            for (int mi = 0; mi < 2; mi++)
#pragma unroll
                for (int ni = 0; ni < 8; ni++)
#pragma unroll
                    for (int half = 0; half < 2; half++) {
                        int m = m0 + wm * 32 + mi * 16 + lg + half * 8;
                        int t = m & (Tn - 1);
                        int n = n0 + wn * 64 + ni * 8 + lc * 2;
                        int h = (n & 1023) >> 6;
                        int d = n & 63;
                        float vx = acc[mi][ni][half * 2];
                        float vy = acc[mi][ni][half * 2 + 1];
                        size_t off = (((size_t)(b * Hn + h)) * Tn + t) * Dn + d;
                        *(uint32_t*)&g_qh[off] = hpack(vx, vy);
                        *(uint32_t*)&g_ql[off] =
                            hpack(vx - hred(vx), vy - hred(vy));
                    }
        } else if (which == 1) {
            // K: single fp16
#pragma unroll
            for (int mi = 0; mi < 2; mi++)
#pragma unroll
                for (int ni = 0; ni < 8; ni++)
#pragma unroll
                    for (int half = 0; half < 2; half++) {
                        int m = m0 + wm * 32 + mi * 16 + lg + half * 8;
                        int t = m & (Tn - 1);
                        int n = n0 + wn * 64 + ni * 8 + lc * 2;
                        int h = (n & 1023) >> 6;
                        int d = n & 63;
                        size_t off = (((size_t)(b * Hn + h)) * Tn + t) * Dn + d;
                        *(uint32_t*)&g_k[off] =
                            hpack(acc[mi][ni][half * 2], acc[mi][ni][half * 2 + 1]);
                    }
        } else {
            // V: single fp16, transposed through smem -> [bh][d][t]
            __syncthreads();
            __half* sV = (__half*)smc;  // [128 col][136]
#pragma unroll
            for (int mi = 0; mi < 2; mi++)
#pragma unroll
                for (int ni = 0; ni < 8; ni++)
#pragma unroll
                    for (int half = 0; half < 2; half++) {
                        int tl = wm * 32 + mi * 16 + lg + half * 8;
                        int col = wn * 64 + ni * 8 + lc * 2;
                        sV[col * 136 + tl] =
                            __float2half_rn(acc[mi][ni][half * 2]);
                        sV[(col + 1) * 136 + tl] =
                            __float2half_rn(acc[mi][ni][half * 2 + 1]);
                    }
            __syncthreads();
            const int h0 = (n0 & 1023) >> 6;
            const int t0 = m0 & (Tn - 1);
#pragma unroll
            for (int c = tid; c < 2048; c += 256) {
                int col = c >> 4, t8 = (c & 15) * 8;
                int h = h0 + (col >> 6);
                int d = col & 63;
                uint4 vh = *(uint4*)&sV[col * 136 + t8];
                size_t off = (((size_t)(b * Hn + h)) * Dn + d) * Tn + t0 + t8;
                *(uint4*)&g_vt[off] = vh;
            }
        }
    } else {
#pragma unroll
        for (int mi = 0; mi < 2; mi++)
#pragma unroll
            for (int ni = 0; ni < 8; ni++) {
                int r0 = m0 + wm * 32 + mi * 16 + lg;
                int n = n0 + wn * 64 + ni * 8 + lc * 2;
#pragma unroll
                for (int half = 0; half < 2; half++) {
                    int m = r0 + half * 8;
                    float2 v = make_float2(acc[mi][ni][half * 2],
                                           acc[mi][ni][half * 2 + 1]);
                    v.x += bias[n];
                    v.y += bias[n + 1];
                    *(float2*)&Cout[(size_t)m * Ntot + n] = v;
                }
            }
    }
}

// ---------------- flash attention: HMMA fp16 2-product, FA-2 style ----------
// Q split hi/lo, K single; P split hi/lo (registers), V single.
#define SQL 18432
#define SSTG 36864       // stage base; per stage: K@0, V@9216
#define SSTGSZ 18432
#define SKEEP 73728      // float[2][64]
#define FLASH_SMEM 74240
#define SC_LOG2 0.18033688f  // 0.125 * log2(e)

__global__ void __launch_bounds__(256, 2)
flash_kernel(const int* __restrict__ idsw) {
    extern __shared__ char smc[];
    const uint32_t smb = smem_u32(smc);

    const int qt = (int)gridDim.x - 1 - (int)blockIdx.x;
    const int bh = blockIdx.y;
    const int b = bh >> 4;
    const int h = bh & 15;
    const int qbase = qt * 128;
    const int tid = threadIdx.x;
    const int wm = tid >> 5;
    const int lane = tid & 31;
    const int lg = lane >> 2;
    const int lc = lane & 3;
    const int shift = g_shift;
    const int nt = 2 * qt + 2;

    const int qrow = (lane & 7) + ((lane >> 3) & 1) * 8;
    const int qcol = ((lane >> 4) & 1) * 8;
    const int krow = (lane & 7) + ((lane >> 4) & 1) * 8;
    const int kcol = ((lane >> 3) & 1) * 8;

    const uint32_t aq_h = smb + (uint32_t)((wm * 16 + qrow) * 144 + qcol * 2);
    const uint32_t aq_l = aq_h + SQL;

    auto load_kv = [&](int kt, int s) {
        const int kv0 = kt * 64;
        const uint32_t sb = smb + SSTG + (uint32_t)s * SSTGSZ;
        // 64 rows x 64 halfs = 8 chunks of 16B per row -> 512 transfers each
#pragma unroll
        for (int ch = tid; ch < 512; ch += 256) {
            int r = ch >> 3, c8 = (ch & 7) << 3;
            uint32_t so = sb + (uint32_t)(r * 144 + c8 * 2);
            cp16(so, g_k + ((size_t)bh * Tn + kv0 + r) * Dn + c8);
            cp16(so + 9216, g_vt + ((size_t)bh * Dn + r) * Tn + kv0 + c8);
        }
        if (tid < 64) {
            size_t w = ((size_t)(b * Tn + kv0 + tid)) << shift;
            float ka = (idsw[w] != 0) ? 0.f : -1e30f;
            *(float*)(smc + SKEEP + s * 256 + tid * 4) = ka;
        }
        CP_COMMIT();
    };

#pragma unroll
    for (int ch = tid; ch < 1024; ch += 256) {
        int r = ch >> 3, c8 = (ch & 7) << 3;
        uint32_t so = smb + (uint32_t)(r * 144 + c8 * 2);
        size_t gq = ((size_t)bh * Tn + qbase + r) * Dn + c8;
        cp16(so, g_qh + gq);
        cp16(so + SQL, g_ql + gq);
    }
    load_kv(0, 0);

    float o[8][4];
#pragma unroll
    for (int i = 0; i < 8; i++)
#pragma unroll
        for (int j = 0; j < 4; j++) o[i][j] = 0.f;
    float m0r = -1e30f, m1r = -1e30f, l0r = 0.f, l1r = 0.f;

    const int r0gl = qbase + wm * 16 + lg;
    const int r1gl = r0gl + 8;

    for (int kt = 0; kt < nt; kt++) {
        const int s = kt & 1;
        if (kt + 1 < nt) {
            load_kv(kt + 1, s ^ 1);
            CP_WAIT(1);
        } else {
            CP_WAIT(0);
        }
        __syncthreads();

        const uint32_t stg = smb + SSTG + (uint32_t)s * SSTGSZ;
        const int kv0 = kt * 64;

        float c[8][4];
#pragma unroll
        for (int i = 0; i < 8; i++)
#pragma unroll
            for (int j = 0; j < 4; j++) c[i][j] = 0.f;

#pragma unroll
        for (int ks = 0; ks < 4; ks++) {
            uint32_t ah[4], al[4];
            LM4(ah, aq_h + ks * 32);
            LM4(al, aq_l + ks * 32);
#pragma unroll
            for (int pi = 0; pi < 4; pi++) {
                uint32_t kb[4];
                LM4(kb, stg + (uint32_t)((pi * 16 + krow) * 144 + kcol * 2) +
                            ks * 32);
                mma16816(c[2 * pi], ah, kb);
                mma16816(c[2 * pi], al, kb);
                mma16816(c[2 * pi + 1], ah, kb + 2);
                mma16816(c[2 * pi + 1], al, kb + 2);
            }
        }

        const float* keepf = (const float*)(smc + SKEEP + s * 256);
        float mx0 = -1e30f, mx1 = -1e30f;
#pragma unroll
        for (int ni = 0; ni < 8; ni++) {
            int cg = kv0 + ni * 8 + 2 * lc;
            float k0 = keepf[ni * 8 + 2 * lc];
            float k1 = keepf[ni * 8 + 2 * lc + 1];
            float t0 = c[ni][0] * SC_LOG2 + k0;
            float t1 = c[ni][1] * SC_LOG2 + k1;
            float t2 = c[ni][2] * SC_LOG2 + k0;
            float t3 = c[ni][3] * SC_LOG2 + k1;
            if (cg > r0gl) t0 = -1e30f;
            if (cg + 1 > r0gl) t1 = -1e30f;
            if (cg > r1gl) t2 = -1e30f;
            if (cg + 1 > r1gl) t3 = -1e30f;
            c[ni][0] = t0; c[ni][1] = t1; c[ni][2] = t2; c[ni][3] = t3;
            mx0 = fmaxf(mx0, fmaxf(t0, t1));
            mx1 = fmaxf(mx1, fmaxf(t2, t3));
        }
        mx0 = fmaxf(mx0, __shfl_xor_sync(0xffffffffu, mx0, 1));
        mx0 = fmaxf(mx0, __shfl_xor_sync(0xffffffffu, mx0, 2));
        mx1 = fmaxf(mx1, __shfl_xor_sync(0xffffffffu, mx1, 1));
        mx1 = fmaxf(mx1, __shfl_xor_sync(0xffffffffu, mx1, 2));
        float mn0 = fmaxf(m0r, mx0), mn1 = fmaxf(m1r, mx1);
        float al0 = ex2f(m0r - mn0), al1 = ex2f(m1r - mn1);
        float ls0 = 0.f, ls1 = 0.f;
#pragma unroll
        for (int ni = 0; ni < 8; ni++) {
            float p0 = ex2f(c[ni][0] - mn0);
            float p1 = ex2f(c[ni][1] - mn0);
            float p2 = ex2f(c[ni][2] - mn1);
            float p3 = ex2f(c[ni][3] - mn1);
            c[ni][0] = p0; c[ni][1] = p1; c[ni][2] = p2; c[ni][3] = p3;
            ls0 += p0 + p1;
            ls1 += p2 + p3;
        }
        ls0 += __shfl_xor_sync(0xffffffffu, ls0, 1);
        ls0 += __shfl_xor_sync(0xffffffffu, ls0, 2);
        ls1 += __shfl_xor_sync(0xffffffffu, ls1, 1);
        ls1 += __shfl_xor_sync(0xffffffffu, ls1, 2);
        l0r = l0r * al0 + ls0;
        l1r = l1r * al1 + ls1;
        m0r = mn0;
        m1r = mn1;
#pragma unroll
        for (int nd = 0; nd < 8; nd++) {
            o[nd][0] *= al0; o[nd][1] *= al0;
            o[nd][2] *= al1; o[nd][3] *= al1;
        }

#pragma unroll
        for (int ks = 0; ks < 4; ks++) {
            uint32_t pah[4], pal[4];
#pragma unroll
            for (int u = 0; u < 2; u++) {
                float x0 = c[2 * ks + u][0], x1 = c[2 * ks + u][1];
                float x2 = c[2 * ks + u][2], x3 = c[2 * ks + u][3];
                pah[2 * u] = hpack(x0, x1);
                pah[2 * u + 1] = hpack(x2, x3);
                pal[2 * u] = hpack(x0 - hred(x0), x1 - hred(x1));
                pal[2 * u + 1] = hpack(x2 - hred(x2), x3 - hred(x3));
            }
#pragma unroll
            for (int pd = 0; pd < 4; pd++) {
                uint32_t vb[4];
                LM4(vb, stg + 9216 +
                            (uint32_t)((pd * 16 + krow) * 144 + kcol * 2) +
                            ks * 32);
                mma16816(o[2 * pd], pah, vb);
                mma16816(o[2 * pd], pal, vb);
                mma16816(o[2 * pd + 1], pah, vb + 2);
                mma16816(o[2 * pd + 1], pal, vb + 2);
            }
        }
        __syncthreads();
    }

    const float i0 = 1.f / l0r, i1 = 1.f / l1r;
    const size_t row0 = (size_t)b * Tn + qbase + wm * 16 + lg;
    const size_t row1 = row0 + 8;
#pragma unroll
    for (int nd = 0; nd < 8; nd++) {
        int col = h * Dn + nd * 8 + 2 * lc;
        float y0 = o[nd][0] * i0, y1 = o[nd][1] * i0;
        float y2 = o[nd][2] * i1, y3 = o[nd][3] * i1;
        *(uint32_t*)&g_ah[row0 * En + col] = hpack(y0, y1);
        *(uint32_t*)&g_al[row0 * En + col] =
            hpack(y0 - hred(y0), y1 - hred(y1));
        *(uint32_t*)&g_ah[row1 * En + col] = hpack(y2, y3);
        *(uint32_t*)&g_al[row1 * En + col] =
            hpack(y2 - hred(y2), y3 - hred(y3));
    }
}

// ---------------------------------------------------------------------------
extern "C" void kernel_launch(void* const* d_in, const int* in_sizes, int n_in,
                              void* d_out, int out_size) {
    (void)in_sizes; (void)n_in; (void)out_size;
    const float* x = (const float*)d_in[0];
    const int* idsw = (const int*)d_in[1];
    const float* w_qkv = (const float*)d_in[2];
    const float* w_out = (const float*)d_in[3];
    const float* b_out = (const float*)d_in[4];
    float* out = (float*)d_out;

    detect_ids_kernel<<<1, 1>>>(idsw);

    split_kernel<<<(Bn * Tn * En / 4) / 256, 256>>>(x);
    wsplit_kernel<true><<<dim3(3 * En / 32, Kdim / 32), dim3(32, 8)>>>(w_qkv);
    wsplit_kernel<false><<<dim3(En / 32, Kdim / 32), dim3(32, 8)>>>(w_out);

    const int gsmem = 2 * 30720;  // 61440 B
    cudaFuncSetAttribute(hmma_gemm<3 * En, true>,
                         cudaFuncAttributeMaxDynamicSharedMemorySize, gsmem);
    cudaFuncSetAttribute(hmma_gemm<En, false>,
                         cudaFuncAttributeMaxDynamicSharedMemorySize, gsmem);

    // 1) QKV projection -> q hi/lo, k single, v^T single (all fp16)
    dim3 g1(3 * En / 128, Bn * Tn / 128);  // (24, 64)
    hmma_gemm<3 * En, true><<<g1, 256, gsmem>>>(nullptr, nullptr);

    // 2) flash attention (fp16 2-product) -> y hi/lo into g_ah/g_al
    cudaFuncSetAttribute(flash_kernel,
                         cudaFuncAttributeMaxDynamicSharedMemorySize, FLASH_SMEM);
    dim3 g2(Tn / 128, Bn * Hn);  // (16, 64)
    flash_kernel<<<g2, 256, FLASH_SMEM>>>(idsw);

    // 3) output projection + bias
    dim3 g3(En / 128, Bn * Tn / 128);  // (8, 64)
    hmma_gemm<En, false><<<g3, 256, gsmem>>>(b_out, out);
}

// round 10
// speedup vs baseline: 6.6320x; 1.6857x over previous
#include <cuda_runtime.h>
#include <cuda_fp16.h>
#include <cstdint>

#define Bn 4
#define Tn 2048
#define En 1024
#define Hn 16
#define Dn 64
#define Kdim 1024

// ---------------- static device scratch (allocation-free) -------------------
__device__ __half g_a[Bn * Tn * En];         // activation fp16 (x, then y)
__device__ __half g_wq[3 * En * Kdim];       // w_qkv^T fp16 [N=3072][K]
__device__ __half g_wo[En * Kdim];           // w_out^T fp16
__device__ __half g_q[Bn * Hn * Tn * Dn];    // q fp16 [bh][t][d]
__device__ __half g_k[Bn * Hn * Tn * Dn];    // k fp16 [bh][t][d]
__device__ __half g_vt[Bn * Hn * Dn * Tn];   // v fp16 TRANSPOSED [bh][d][t]
__device__ int g_shift;

// ---------------- helpers (baseline PTX only: sm_80+ features) --------------
__device__ __forceinline__ void cp16(uint32_t s, const void* g) {
    asm volatile("cp.async.cg.shared.global [%0], [%1], 16;" :: "r"(s), "l"(g));
}
#define CP_COMMIT() asm volatile("cp.async.commit_group;" ::: "memory")
#define CP_WAIT(n) asm volatile("cp.async.wait_group %0;" :: "n"(n) : "memory")

__device__ __forceinline__ uint32_t smem_u32(const void* p) {
    uint32_t a;
    asm("{ .reg .u64 t; cvta.to.shared.u64 t, %1; cvt.u32.u64 %0, t; }"
        : "=r"(a) : "l"(p));
    return a;
}
__device__ __forceinline__ void mma16816(float* c, const uint32_t* a,
                                         const uint32_t* b) {
    asm volatile(
        "mma.sync.aligned.m16n8k16.row.col.f32.f16.f16.f32 "
        "{%0,%1,%2,%3}, {%4,%5,%6,%7}, {%8,%9}, {%0,%1,%2,%3};"
        : "+f"(c[0]), "+f"(c[1]), "+f"(c[2]), "+f"(c[3])
        : "r"(a[0]), "r"(a[1]), "r"(a[2]), "r"(a[3]), "r"(b[0]), "r"(b[1]));
}
#define LM4(r, addr)                                                       \
    asm volatile("ldmatrix.sync.aligned.m8n8.x4.shared.b16 "               \
                 "{%0,%1,%2,%3}, [%4];"                                    \
                 : "=r"((r)[0]), "=r"((r)[1]), "=r"((r)[2]), "=r"((r)[3])  \
                 : "r"(addr))
__device__ __forceinline__ float ex2f(float x) {
    float r;
    asm("ex2.approx.f32 %0, %1;" : "=f"(r) : "f"(x));
    return r;
}
__device__ __forceinline__ uint32_t hpack(float lo, float hi) {
    __half2 t = __floats2half2_rn(lo, hi);
    return *(uint32_t*)&t;
}

// ---------------- int64-vs-int32 input_ids detection ------------------------
__global__ void detect_ids_kernel(const int* __restrict__ w) {
    bool all0 = true;
    for (int i = 1; i < 64; i += 2) all0 = all0 && (w[i] == 0);
    g_shift = all0 ? 1 : 0;
}

// ---------------- fp32 -> fp16 convert (x) ----------------------------------
__global__ void split_kernel(const float* __restrict__ src) {
    int i = blockIdx.x * blockDim.x + threadIdx.x;
    float4 v = ((const float4*)src)[i];
    uint32_t* ph = (uint32_t*)g_a;
    ph[2 * i] = hpack(v.x, v.y);
    ph[2 * i + 1] = hpack(v.z, v.w);
}

// ---------------- weight transpose: W[K,N] -> Wt[N,K] fp16 ------------------
template <bool QKVW>
__global__ void wsplit_kernel(const float* __restrict__ W) {
    constexpr int Nw = QKVW ? 3 * En : En;
    __half* oh = QKVW ? g_wq : g_wo;
    __shared__ float tile[32][33];
    int n0 = blockIdx.x * 32, k0 = blockIdx.y * 32;
    int tx = threadIdx.x, ty = threadIdx.y;  // (32, 8)
#pragma unroll
    for (int i = 0; i < 32; i += 8)
        tile[ty + i][tx] = W[(size_t)(k0 + ty + i) * Nw + n0 + tx];
    __syncthreads();
#pragma unroll
    for (int i = 0; i < 32; i += 8) {
        float a = tile[tx][ty + i];
        oh[(size_t)(n0 + ty + i) * Kdim + k0 + tx] = __float2half_rn(a);
    }
}

// ---------------- HMMA fp16 GEMM: C[8192, Ntot] = A * W^T -------------------
// BM=128, BN=128, BK=32. 2-stage cp.async, ldmatrix. 8 warps 4(m)x2(n),
// warp tile 32x64, single product.
template <int Ntot, bool QKV>
__global__ void __launch_bounds__(256, 2)
hmma_gemm(const float* __restrict__ bias, float* __restrict__ Cout) {
    constexpr int ROWB = 80;                    // bytes per smem row (40 half)
    constexpr int OFF_B = 10240;                // 128*80
    constexpr int STG = 20480;                  // bytes per stage
    constexpr int NK = Kdim / 32;               // 32
    extern __shared__ char smc[];
    const uint32_t smb = smem_u32(smc);

    const __half* Bg = QKV ? g_wq : g_wo;

    const int m0 = blockIdx.y * 128;
    const int n0 = blockIdx.x * 128;
    const int tid = threadIdx.x;
    const int wid = tid >> 5;
    const int lane = tid & 31;
    const int wm = wid >> 1;   // 0..3
    const int wn = wid & 1;    // 0..1
    const int lg = lane >> 2;
    const int lc = lane & 3;
    const int arow = (lane & 7) + ((lane >> 3) & 1) * 8;
    const int acol = ((lane >> 4) & 1) * 8;
    const int brow = (lane & 7) + ((lane >> 4) & 1) * 8;
    const int bcol = ((lane >> 3) & 1) * 8;

    float acc[2][8][4];
#pragma unroll
    for (int mi = 0; mi < 2; mi++)
#pragma unroll
        for (int ni = 0; ni < 8; ni++)
#pragma unroll
            for (int r = 0; r < 4; r++) acc[mi][ni][r] = 0.f;

    auto load_stage = [&](int kc, int s) {
        const int k0 = kc * 32;
        const uint32_t sb = smb + (uint32_t)s * STG;
#pragma unroll
        for (int c = tid; c < 512; c += 256) {
            int row = c >> 2, col8 = (c & 3) * 8;
            cp16(sb + (uint32_t)(row * ROWB + col8 * 2),
                 g_a + (size_t)(m0 + row) * Kdim + k0 + col8);
            cp16(sb + OFF_B + (uint32_t)(row * ROWB + col8 * 2),
                 Bg + (size_t)(n0 + row) * Kdim + k0 + col8);
        }
        CP_COMMIT();
    };

    load_stage(0, 0);

    int s = 0;
    for (int kc = 0; kc < NK; kc++) {
        CP_WAIT(0);
        __syncthreads();
        if (kc + 1 < NK) load_stage(kc + 1, s ^ 1);

        const uint32_t sb = smb + (uint32_t)s * STG;
        const uint32_t aB = sb + (uint32_t)((wm * 32 + arow) * ROWB + acol * 2);
        const uint32_t bB = sb + OFF_B + (uint32_t)(brow * ROWB + bcol * 2);
#pragma unroll
        for (int ks = 0; ks < 2; ks++) {
            uint32_t ah[2][4];
#pragma unroll
            for (int mi = 0; mi < 2; mi++)
                LM4(ah[mi], aB + mi * 16 * ROWB + ks * 32);
#pragma unroll
            for (int nj = 0; nj < 4; nj++) {
                uint32_t b[4];
                LM4(b, bB + (wn * 64 + nj * 16) * ROWB + ks * 32);
#pragma unroll
                for (int mi = 0; mi < 2; mi++) {
                    mma16816(acc[mi][2 * nj], ah[mi], b);
                    mma16816(acc[mi][2 * nj + 1], ah[mi], b + 2);
                }
            }
        }
        s ^= 1;
    }

    if (QKV) {
        const int which = n0 >> 10;
        const int b = m0 >> 11;
        if (which < 2) {
            __half* dst = which == 0 ? g_q : g_k;
#pragma unroll
            for (int mi = 0; mi < 2; mi++)
#pragma unroll
                for (int ni = 0; ni < 8; ni++)
#pragma unroll
                    for (int half = 0; half < 2; half++) {
                        int m = m0 + wm * 32 + mi * 16 + lg + half * 8;
                        int t = m & (Tn - 1);
                        int n = n0 + wn * 64 + ni * 8 + lc * 2;
                        int h = (n & 1023) >> 6;
                        int d = n & 63;
                        size_t off = (((size_t)(b * Hn + h)) * Tn + t) * Dn + d;
                        *(uint32_t*)&dst[off] =
                            hpack(acc[mi][ni][half * 2], acc[mi][ni][half * 2 + 1]);
                    }
        } else {
            // V: fp16, transposed through smem -> [bh][d][t]
            __syncthreads();
            __half* sV = (__half*)smc;  // [128 col][136]
#pragma unroll
            for (int mi = 0; mi < 2; mi++)
#pragma unroll
                for (int ni = 0; ni < 8; ni++)
#pragma unroll
                    for (int half = 0; half < 2; half++) {
                        int tl = wm * 32 + mi * 16 + lg + half * 8;
                        int col = wn * 64 + ni * 8 + lc * 2;
                        sV[col * 136 + tl] =
                            __float2half_rn(acc[mi][ni][half * 2]);
                        sV[(col + 1) * 136 + tl] =
                            __float2half_rn(acc[mi][ni][half * 2 + 1]);
                    }
            __syncthreads();
            const int h0 = (n0 & 1023) >> 6;
            const int t0 = m0 & (Tn - 1);
#pragma unroll
            for (int c = tid; c < 2048; c += 256) {
                int col = c >> 4, t8 = (c & 15) * 8;
                int h = h0 + (col >> 6);
                int d = col & 63;
                uint4 vh = *(uint4*)&sV[col * 136 + t8];
                size_t off = (((size_t)(b * Hn + h)) * Dn + d) * Tn + t0 + t8;
                *(uint4*)&g_vt[off] = vh;
            }
        }
    } else {
#pragma unroll
        for (int mi = 0; mi < 2; mi++)
#pragma unroll
            for (int ni = 0; ni < 8; ni++) {
                int r0 = m0 + wm * 32 + mi * 16 + lg;
                int n = n0 + wn * 64 + ni * 8 + lc * 2;
#pragma unroll
                for (int half = 0; half < 2; half++) {
                    int m = r0 + half * 8;
                    float2 v = make_float2(acc[mi][ni][half * 2],
                                           acc[mi][ni][half * 2 + 1]);
                    v.x += bias[n];
                    v.y += bias[n + 1];
                    *(float2*)&Cout[(size_t)m * Ntot + n] = v;
                }
            }
    }
}

// ---------------- flash attention: HMMA fp16 single, FA-2 style -------------
// Q tile: 128 rows x 144 BYTES = 18432 B. Stages follow it.
#define SSTG 18432       // stage base (after the full Q tile)
#define SSTGSZ 18432     // per stage: K@0 (9216), V@9216
#define SKEEP 55296      // float[2][64] (= 18432 + 2*18432)
#define FLASH_SMEM 55808
#define SC_LOG2 0.18033688f  // 0.125 * log2(e)

__global__ void __launch_bounds__(256, 2)
flash_kernel(const int* __restrict__ idsw) {
    extern __shared__ char smc[];
    const uint32_t smb = smem_u32(smc);

    const int qt = (int)gridDim.x - 1 - (int)blockIdx.x;
    const int bh = blockIdx.y;
    const int b = bh >> 4;
    const int h = bh & 15;
    const int qbase = qt * 128;
    const int tid = threadIdx.x;
    const int wm = tid >> 5;
    const int lane = tid & 31;
    const int lg = lane >> 2;
    const int lc = lane & 3;
    const int shift = g_shift;
    const int nt = 2 * qt + 2;

    const int qrow = (lane & 7) + ((lane >> 3) & 1) * 8;
    const int qcol = ((lane >> 4) & 1) * 8;
    const int krow = (lane & 7) + ((lane >> 4) & 1) * 8;
    const int kcol = ((lane >> 3) & 1) * 8;

    const uint32_t aq = smb + (uint32_t)((wm * 16 + qrow) * 144 + qcol * 2);

    auto load_kv = [&](int kt, int s) {
        const int kv0 = kt * 64;
        const uint32_t sb = smb + SSTG + (uint32_t)s * SSTGSZ;
        // 64 rows x 64 halfs = 8 chunks of 16B per row -> 512 transfers each
#pragma unroll
        for (int ch = tid; ch < 512; ch += 256) {
            int r = ch >> 3, c8 = (ch & 7) << 3;
            uint32_t so = sb + (uint32_t)(r * 144 + c8 * 2);
            cp16(so, g_k + ((size_t)bh * Tn + kv0 + r) * Dn + c8);
            cp16(so + 9216, g_vt + ((size_t)bh * Dn + r) * Tn + kv0 + c8);
        }
        if (tid < 64) {
            size_t w = ((size_t)(b * Tn + kv0 + tid)) << shift;
            float ka = (idsw[w] != 0) ? 0.f : -1e30f;
            *(float*)(smc + SKEEP + s * 256 + tid * 4) = ka;
        }
        CP_COMMIT();
    };

#pragma unroll
    for (int ch = tid; ch < 1024; ch += 256) {
        int r = ch >> 3, c8 = (ch & 7) << 3;
        cp16(smb + (uint32_t)(r * 144 + c8 * 2),
             g_q + ((size_t)bh * Tn + qbase + r) * Dn + c8);
    }
    load_kv(0, 0);

    float o[8][4];
#pragma unroll
    for (int i = 0; i < 8; i++)
#pragma unroll
        for (int j = 0; j < 4; j++) o[i][j] = 0.f;
    float m0r = -1e30f, m1r = -1e30f, l0r = 0.f, l1r = 0.f;

    const int r0gl = qbase + wm * 16 + lg;
    const int r1gl = r0gl + 8;

    for (int kt = 0; kt < nt; kt++) {
        const int s = kt & 1;
        if (kt + 1 < nt) {
            load_kv(kt + 1, s ^ 1);
            CP_WAIT(1);
        } else {
            CP_WAIT(0);
        }
        __syncthreads();

        const uint32_t stg = smb + SSTG + (uint32_t)s * SSTGSZ;
        const int kv0 = kt * 64;

        float c[8][4];
#pragma unroll
        for (int i = 0; i < 8; i++)
#pragma unroll
            for (int j = 0; j < 4; j++) c[i][j] = 0.f;

#pragma unroll
        for (int ks = 0; ks < 4; ks++) {
            uint32_t ah[4];
            LM4(ah, aq + ks * 32);
#pragma unroll
            for (int pi = 0; pi < 4; pi++) {
                uint32_t kb[4];
                LM4(kb, stg + (uint32_t)((pi * 16 + krow) * 144 + kcol * 2) +
                            ks * 32);
                mma16816(c[2 * pi], ah, kb);
                mma16816(c[2 * pi + 1], ah, kb + 2);
            }
        }

        const float* keepf = (const float*)(smc + SKEEP + s * 256);
        float mx0 = -1e30f, mx1 = -1e30f;
#pragma unroll
        for (int ni = 0; ni < 8; ni++) {
            int cg = kv0 + ni * 8 + 2 * lc;
            float k0 = keepf[ni * 8 + 2 * lc];
            float k1 = keepf[ni * 8 + 2 * lc + 1];
            float t0 = c[ni][0] * SC_LOG2 + k0;
            float t1 = c[ni][1] * SC_LOG2 + k1;
            float t2 = c[ni][2] * SC_LOG2 + k0;
            float t3 = c[ni][3] * SC_LOG2 + k1;
            if (cg > r0gl) t0 = -1e30f;
            if (cg + 1 > r0gl) t1 = -1e30f;
            if (cg > r1gl) t2 = -1e30f;
            if (cg + 1 > r1gl) t3 = -1e30f;
            c[ni][0] = t0; c[ni][1] = t1; c[ni][2] = t2; c[ni][3] = t3;
            mx0 = fmaxf(mx0, fmaxf(t0, t1));
            mx1 = fmaxf(mx1, fmaxf(t2, t3));
        }
        mx0 = fmaxf(mx0, __shfl_xor_sync(0xffffffffu, mx0, 1));
        mx0 = fmaxf(mx0, __shfl_xor_sync(0xffffffffu, mx0, 2));
        mx1 = fmaxf(mx1, __shfl_xor_sync(0xffffffffu, mx1, 1));
        mx1 = fmaxf(mx1, __shfl_xor_sync(0xffffffffu, mx1, 2));
        float mn0 = fmaxf(m0r, mx0), mn1 = fmaxf(m1r, mx1);
        float al0 = ex2f(m0r - mn0), al1 = ex2f(m1r - mn1);
        float ls0 = 0.f, ls1 = 0.f;
#pragma unroll
        for (int ni = 0; ni < 8; ni++) {
            float p0 = ex2f(c[ni][0] - mn0);
            float p1 = ex2f(c[ni][1] - mn0);
            float p2 = ex2f(c[ni][2] - mn1);
            float p3 = ex2f(c[ni][3] - mn1);
            c[ni][0] = p0; c[ni][1] = p1; c[ni][2] = p2; c[ni][3] = p3;
            ls0 += p0 + p1;
            ls1 += p2 + p3;
        }
        ls0 += __shfl_xor_sync(0xffffffffu, ls0, 1);
        ls0 += __shfl_xor_sync(0xffffffffu, ls0, 2);
        ls1 += __shfl_xor_sync(0xffffffffu, ls1, 1);
        ls1 += __shfl_xor_sync(0xffffffffu, ls1, 2);
        l0r = l0r * al0 + ls0;
        l1r = l1r * al1 + ls1;
        m0r = mn0;
        m1r = mn1;
#pragma unroll
        for (int nd = 0; nd < 8; nd++) {
            o[nd][0] *= al0; o[nd][1] *= al0;
            o[nd][2] *= al1; o[nd][3] *= al1;
        }

#pragma unroll
        for (int ks = 0; ks < 4; ks++) {
            uint32_t pah[4];
#pragma unroll
            for (int u = 0; u < 2; u++) {
                pah[2 * u] = hpack(c[2 * ks + u][0], c[2 * ks + u][1]);
                pah[2 * u + 1] = hpack(c[2 * ks + u][2], c[2 * ks + u][3]);
            }
#pragma unroll
            for (int pd = 0; pd < 4; pd++) {
                uint32_t vb[4];
                LM4(vb, stg + 9216 +
                            (uint32_t)((pd * 16 + krow) * 144 + kcol * 2) +
                            ks * 32);
                mma16816(o[2 * pd], pah, vb);
                mma16816(o[2 * pd + 1], pah, vb + 2);
            }
        }
        __syncthreads();
    }

    const float i0 = 1.f / l0r, i1 = 1.f / l1r;
    const size_t row0 = (size_t)b * Tn + qbase + wm * 16 + lg;
    const size_t row1 = row0 + 8;
#pragma unroll
    for (int nd = 0; nd < 8; nd++) {
        int col = h * Dn + nd * 8 + 2 * lc;
        *(uint32_t*)&g_a[row0 * En + col] = hpack(o[nd][0] * i0, o[nd][1] * i0);
        *(uint32_t*)&g_a[row1 * En + col] = hpack(o[nd][2] * i1, o[nd][3] * i1);
    }
}

// ---------------------------------------------------------------------------
extern "C" void kernel_launch(void* const* d_in, const int* in_sizes, int n_in,
                              void* d_out, int out_size) {
    (void)in_sizes; (void)n_in; (void)out_size;
    const float* x = (const float*)d_in[0];
    const int* idsw = (const int*)d_in[1];
    const float* w_qkv = (const float*)d_in[2];
    const float* w_out = (const float*)d_in[3];
    const float* b_out = (const float*)d_in[4];
    float* out = (float*)d_out;

    detect_ids_kernel<<<1, 1>>>(idsw);

    split_kernel<<<(Bn * Tn * En / 4) / 256, 256>>>(x);
    wsplit_kernel<true><<<dim3(3 * En / 32, Kdim / 32), dim3(32, 8)>>>(w_qkv);
    wsplit_kernel<false><<<dim3(En / 32, Kdim / 32), dim3(32, 8)>>>(w_out);

    const int gsmem = 2 * 20480;  // 40960 B
    cudaFuncSetAttribute(hmma_gemm<3 * En, true>,
                         cudaFuncAttributeMaxDynamicSharedMemorySize, gsmem);
    cudaFuncSetAttribute(hmma_gemm<En, false>,
                         cudaFuncAttributeMaxDynamicSharedMemorySize, gsmem);

    // 1) QKV projection -> q, k ([bh][t][d]) + v^T ([bh][d][t]), all fp16
    dim3 g1(3 * En / 128, Bn * Tn / 128);  // (24, 64)
    hmma_gemm<3 * En, true><<<g1, 256, gsmem>>>(nullptr, nullptr);

    // 2) flash attention (fp16 single) -> y fp16 into g_a
    cudaFuncSetAttribute(flash_kernel,
                         cudaFuncAttributeMaxDynamicSharedMemorySize, FLASH_SMEM);
    dim3 g2(Tn / 128, Bn * Hn);  // (16, 64)
    flash_kernel<<<g2, 256, FLASH_SMEM>>>(idsw);

    // 3) output projection + bias
    dim3 g3(En / 128, Bn * Tn / 128);  // (8, 64)
    hmma_gemm<En, false><<<g3, 256, gsmem>>>(b_out, out);
}

// round 11
// speedup vs baseline: 6.6835x; 1.0078x over previous
#include <cuda_runtime.h>
#include <cuda_fp16.h>
#include <cstdint>

#define Bn 4
#define Tn 2048
#define En 1024
#define Hn 16
#define Dn 64
#define Kdim 1024
#define SC_LOG2 0.18033688f  // 0.125 * log2(e)

// ---------------- static device scratch (allocation-free) -------------------
__device__ __half g_a[Bn * Tn * En];         // activation fp16 (x, then y)
__device__ __half g_wq[3 * En * Kdim];       // w_qkv^T fp16 [N=3072][K]
__device__ __half g_wo[En * Kdim];           // w_out^T fp16
__device__ __half g_q[Bn * Hn * Tn * Dn];    // q fp16 PRE-SCALED [bh][t][d]
__device__ __half g_k[Bn * Hn * Tn * Dn];    // k fp16 [bh][t][d]
__device__ __half g_vt[Bn * Hn * Dn * Tn];   // v fp16 TRANSPOSED [bh][d][t]
__device__ int g_shift;

// ---------------- helpers (baseline PTX only: sm_80+ features) --------------
__device__ __forceinline__ void cp16(uint32_t s, const void* g) {
    asm volatile("cp.async.cg.shared.global [%0], [%1], 16;" :: "r"(s), "l"(g));
}
#define CP_COMMIT() asm volatile("cp.async.commit_group;" ::: "memory")
#define CP_WAIT(n) asm volatile("cp.async.wait_group %0;" :: "n"(n) : "memory")

__device__ __forceinline__ uint32_t smem_u32(const void* p) {
    uint32_t a;
    asm("{ .reg .u64 t; cvta.to.shared.u64 t, %1; cvt.u32.u64 %0, t; }"
        : "=r"(a) : "l"(p));
    return a;
}
__device__ __forceinline__ void mma16816(float* c, const uint32_t* a,
                                         const uint32_t* b) {
    asm volatile(
        "mma.sync.aligned.m16n8k16.row.col.f32.f16.f16.f32 "
        "{%0,%1,%2,%3}, {%4,%5,%6,%7}, {%8,%9}, {%0,%1,%2,%3};"
        : "+f"(c[0]), "+f"(c[1]), "+f"(c[2]), "+f"(c[3])
        : "r"(a[0]), "r"(a[1]), "r"(a[2]), "r"(a[3]), "r"(b[0]), "r"(b[1]));
}
#define LM4(r, addr)                                                       \
    asm volatile("ldmatrix.sync.aligned.m8n8.x4.shared.b16 "               \
                 "{%0,%1,%2,%3}, [%4];"                                    \
                 : "=r"((r)[0]), "=r"((r)[1]), "=r"((r)[2]), "=r"((r)[3])  \
                 : "r"(addr))
__device__ __forceinline__ float ex2f(float x) {
    float r;
    asm("ex2.approx.f32 %0, %1;" : "=f"(r) : "f"(x));
    return r;
}
__device__ __forceinline__ uint32_t hpack(float lo, float hi) {
    __half2 t = __floats2half2_rn(lo, hi);
    return *(uint32_t*)&t;
}

// ---------------- int64-vs-int32 input_ids detection ------------------------
__global__ void detect_ids_kernel(const int* __restrict__ w) {
    bool all0 = true;
    for (int i = 1; i < 64; i += 2) all0 = all0 && (w[i] == 0);
    g_shift = all0 ? 1 : 0;
}

// ---------------- fp32 -> fp16 convert (x) ----------------------------------
__global__ void split_kernel(const float* __restrict__ src) {
    int i = blockIdx.x * blockDim.x + threadIdx.x;
    float4 v = ((const float4*)src)[i];
    uint32_t* ph = (uint32_t*)g_a;
    ph[2 * i] = hpack(v.x, v.y);
    ph[2 * i + 1] = hpack(v.z, v.w);
}

// ---------------- weight transpose: W[K,N] -> Wt[N,K] fp16 ------------------
template <bool QKVW>
__global__ void wsplit_kernel(const float* __restrict__ W) {
    constexpr int Nw = QKVW ? 3 * En : En;
    __half* oh = QKVW ? g_wq : g_wo;
    __shared__ float tile[32][33];
    int n0 = blockIdx.x * 32, k0 = blockIdx.y * 32;
    int tx = threadIdx.x, ty = threadIdx.y;  // (32, 8)
#pragma unroll
    for (int i = 0; i < 32; i += 8)
        tile[ty + i][tx] = W[(size_t)(k0 + ty + i) * Nw + n0 + tx];
    __syncthreads();
#pragma unroll
    for (int i = 0; i < 32; i += 8) {
        float a = tile[tx][ty + i];
        oh[(size_t)(n0 + ty + i) * Kdim + k0 + tx] = __float2half_rn(a);
    }
}

// ---------------- HMMA fp16 GEMM: C[8192, Ntot] = A * W^T -------------------
// BM=128, BN=128, BK=32. 2-stage cp.async, ldmatrix. 8 warps 4(m)x2(n),
// warp tile 32x64, single product. Q epilogue pre-scales by SC_LOG2.
template <int Ntot, bool QKV>
__global__ void __launch_bounds__(256, 2)
hmma_gemm(const float* __restrict__ bias, float* __restrict__ Cout) {
    constexpr int ROWB = 80;                    // bytes per smem row (40 half)
    constexpr int OFF_B = 10240;                // 128*80
    constexpr int STG = 20480;                  // bytes per stage
    constexpr int NK = Kdim / 32;               // 32
    extern __shared__ char smc[];
    const uint32_t smb = smem_u32(smc);

    const __half* Bg = QKV ? g_wq : g_wo;

    const int m0 = blockIdx.y * 128;
    const int n0 = blockIdx.x * 128;
    const int tid = threadIdx.x;
    const int wid = tid >> 5;
    const int lane = tid & 31;
    const int wm = wid >> 1;   // 0..3
    const int wn = wid & 1;    // 0..1
    const int lg = lane >> 2;
    const int lc = lane & 3;
    const int arow = (lane & 7) + ((lane >> 3) & 1) * 8;
    const int acol = ((lane >> 4) & 1) * 8;
    const int brow = (lane & 7) + ((lane >> 4) & 1) * 8;
    const int bcol = ((lane >> 3) & 1) * 8;

    float acc[2][8][4];
#pragma unroll
    for (int mi = 0; mi < 2; mi++)
#pragma unroll
        for (int ni = 0; ni < 8; ni++)
#pragma unroll
            for (int r = 0; r < 4; r++) acc[mi][ni][r] = 0.f;

    auto load_stage = [&](int kc, int s) {
        const int k0 = kc * 32;
        const uint32_t sb = smb + (uint32_t)s * STG;
#pragma unroll
        for (int c = tid; c < 512; c += 256) {
            int row = c >> 2, col8 = (c & 3) * 8;
            cp16(sb + (uint32_t)(row * ROWB + col8 * 2),
                 g_a + (size_t)(m0 + row) * Kdim + k0 + col8);
            cp16(sb + OFF_B + (uint32_t)(row * ROWB + col8 * 2),
                 Bg + (size_t)(n0 + row) * Kdim + k0 + col8);
        }
        CP_COMMIT();
    };

    load_stage(0, 0);

    int s = 0;
    for (int kc = 0; kc < NK; kc++) {
        CP_WAIT(0);
        __syncthreads();
        if (kc + 1 < NK) load_stage(kc + 1, s ^ 1);

        const uint32_t sb = smb + (uint32_t)s * STG;
        const uint32_t aB = sb + (uint32_t)((wm * 32 + arow) * ROWB + acol * 2);
        const uint32_t bB = sb + OFF_B + (uint32_t)(brow * ROWB + bcol * 2);
#pragma unroll
        for (int ks = 0; ks < 2; ks++) {
            uint32_t ah[2][4];
#pragma unroll
            for (int mi = 0; mi < 2; mi++)
                LM4(ah[mi], aB + mi * 16 * ROWB + ks * 32);
#pragma unroll
            for (int nj = 0; nj < 4; nj++) {
                uint32_t b[4];
                LM4(b, bB + (wn * 64 + nj * 16) * ROWB + ks * 32);
#pragma unroll
                for (int mi = 0; mi < 2; mi++) {
                    mma16816(acc[mi][2 * nj], ah[mi], b);
                    mma16816(acc[mi][2 * nj + 1], ah[mi], b + 2);
                }
            }
        }
        s ^= 1;
    }

    if (QKV) {
        const int which = n0 >> 10;
        const int b = m0 >> 11;
        if (which < 2) {
            __half* dst = which == 0 ? g_q : g_k;
            const float sc = which == 0 ? SC_LOG2 : 1.0f;  // pre-scale Q
#pragma unroll
            for (int mi = 0; mi < 2; mi++)
#pragma unroll
                for (int ni = 0; ni < 8; ni++)
#pragma unroll
                    for (int half = 0; half < 2; half++) {
                        int m = m0 + wm * 32 + mi * 16 + lg + half * 8;
                        int t = m & (Tn - 1);
                        int n = n0 + wn * 64 + ni * 8 + lc * 2;
                        int h = (n & 1023) >> 6;
                        int d = n & 63;
                        size_t off = (((size_t)(b * Hn + h)) * Tn + t) * Dn + d;
                        *(uint32_t*)&dst[off] =
                            hpack(acc[mi][ni][half * 2] * sc,
                                  acc[mi][ni][half * 2 + 1] * sc);
                    }
        } else {
            // V: fp16, transposed through smem -> [bh][d][t]
            __syncthreads();
            __half* sV = (__half*)smc;  // [128 col][136]
#pragma unroll
            for (int mi = 0; mi < 2; mi++)
#pragma unroll
                for (int ni = 0; ni < 8; ni++)
#pragma unroll
                    for (int half = 0; half < 2; half++) {
                        int tl = wm * 32 + mi * 16 + lg + half * 8;
                        int col = wn * 64 + ni * 8 + lc * 2;
                        sV[col * 136 + tl] =
                            __float2half_rn(acc[mi][ni][half * 2]);
                        sV[(col + 1) * 136 + tl] =
                            __float2half_rn(acc[mi][ni][half * 2 + 1]);
                    }
            __syncthreads();
            const int h0 = (n0 & 1023) >> 6;
            const int t0 = m0 & (Tn - 1);
#pragma unroll
            for (int c = tid; c < 2048; c += 256) {
                int col = c >> 4, t8 = (c & 15) * 8;
                int h = h0 + (col >> 6);
                int d = col & 63;
                uint4 vh = *(uint4*)&sV[col * 136 + t8];
                size_t off = (((size_t)(b * Hn + h)) * Dn + d) * Tn + t0 + t8;
                *(uint4*)&g_vt[off] = vh;
            }
        }
    } else {
#pragma unroll
        for (int mi = 0; mi < 2; mi++)
#pragma unroll
            for (int ni = 0; ni < 8; ni++) {
                int r0 = m0 + wm * 32 + mi * 16 + lg;
                int n = n0 + wn * 64 + ni * 8 + lc * 2;
#pragma unroll
                for (int half = 0; half < 2; half++) {
                    int m = r0 + half * 8;
                    float2 v = make_float2(acc[mi][ni][half * 2],
                                           acc[mi][ni][half * 2 + 1]);
                    v.x += bias[n];
                    v.y += bias[n + 1];
                    *(float2*)&Cout[(size_t)m * Ntot + n] = v;
                }
            }
    }
}

// ---------------- flash attention: HMMA fp16 single, FA-2 style -------------
// Q pre-scaled (scores exit MMA already in log2 domain). Causal compares only
// on diagonal-straddling tiles (uniform per-warp branch).
#define SSTG 18432       // stage base (after the full Q tile: 128 x 144 B)
#define SSTGSZ 18432     // per stage: K@0 (9216), V@9216
#define SKEEP 55296      // float[2][64]
#define FLASH_SMEM 55808

__global__ void __launch_bounds__(256, 2)
flash_kernel(const int* __restrict__ idsw) {
    extern __shared__ char smc[];
    const uint32_t smb = smem_u32(smc);

    const int qt = (int)gridDim.x - 1 - (int)blockIdx.x;
    const int bh = blockIdx.y;
    const int b = bh >> 4;
    const int h = bh & 15;
    const int qbase = qt * 128;
    const int tid = threadIdx.x;
    const int wm = tid >> 5;
    const int lane = tid & 31;
    const int lg = lane >> 2;
    const int lc = lane & 3;
    const int shift = g_shift;
    const int nt = 2 * qt + 2;

    const int qrow = (lane & 7) + ((lane >> 3) & 1) * 8;
    const int qcol = ((lane >> 4) & 1) * 8;
    const int krow = (lane & 7) + ((lane >> 4) & 1) * 8;
    const int kcol = ((lane >> 3) & 1) * 8;

    const uint32_t aq = smb + (uint32_t)((wm * 16 + qrow) * 144 + qcol * 2);

    auto load_kv = [&](int kt, int s) {
        const int kv0 = kt * 64;
        const uint32_t sb = smb + SSTG + (uint32_t)s * SSTGSZ;
#pragma unroll
        for (int ch = tid; ch < 512; ch += 256) {
            int r = ch >> 3, c8 = (ch & 7) << 3;
            uint32_t so = sb + (uint32_t)(r * 144 + c8 * 2);
            cp16(so, g_k + ((size_t)bh * Tn + kv0 + r) * Dn + c8);
            cp16(so + 9216, g_vt + ((size_t)bh * Dn + r) * Tn + kv0 + c8);
        }
        if (tid < 64) {
            size_t w = ((size_t)(b * Tn + kv0 + tid)) << shift;
            float ka = (idsw[w] != 0) ? 0.f : -1e30f;
            *(float*)(smc + SKEEP + s * 256 + tid * 4) = ka;
        }
        CP_COMMIT();
    };

#pragma unroll
    for (int ch = tid; ch < 1024; ch += 256) {
        int r = ch >> 3, c8 = (ch & 7) << 3;
        cp16(smb + (uint32_t)(r * 144 + c8 * 2),
             g_q + ((size_t)bh * Tn + qbase + r) * Dn + c8);
    }
    load_kv(0, 0);

    float o[8][4];
#pragma unroll
    for (int i = 0; i < 8; i++)
#pragma unroll
        for (int j = 0; j < 4; j++) o[i][j] = 0.f;
    float m0r = -1e30f, m1r = -1e30f, l0r = 0.f, l1r = 0.f;

    const int r0gl = qbase + wm * 16 + lg;
    const int r1gl = r0gl + 8;

    for (int kt = 0; kt < nt; kt++) {
        const int s = kt & 1;
        if (kt + 1 < nt) {
            load_kv(kt + 1, s ^ 1);
            CP_WAIT(1);
        } else {
            CP_WAIT(0);
        }
        __syncthreads();

        const uint32_t stg = smb + SSTG + (uint32_t)s * SSTGSZ;
        const int kv0 = kt * 64;

        float c[8][4];
#pragma unroll
        for (int i = 0; i < 8; i++)
#pragma unroll
            for (int j = 0; j < 4; j++) c[i][j] = 0.f;

#pragma unroll
        for (int ks = 0; ks < 4; ks++) {
            uint32_t ah[4];
            LM4(ah, aq + ks * 32);
#pragma unroll
            for (int pi = 0; pi < 4; pi++) {
                uint32_t kb[4];
                LM4(kb, stg + (uint32_t)((pi * 16 + krow) * 144 + kcol * 2) +
                            ks * 32);
                mma16816(c[2 * pi], ah, kb);
                mma16816(c[2 * pi + 1], ah, kb + 2);
            }
        }

        const float* keepf = (const float*)(smc + SKEEP + s * 256);
        float mx0 = -1e30f, mx1 = -1e30f;
        if (kv0 + 63 <= qbase + wm * 16) {
            // fully below the diagonal for every row this warp owns
#pragma unroll
            for (int ni = 0; ni < 8; ni++) {
                float2 kp = *(const float2*)&keepf[ni * 8 + 2 * lc];
                float t0 = c[ni][0] + kp.x;
                float t1 = c[ni][1] + kp.y;
                float t2 = c[ni][2] + kp.x;
                float t3 = c[ni][3] + kp.y;
                c[ni][0] = t0; c[ni][1] = t1; c[ni][2] = t2; c[ni][3] = t3;
                mx0 = fmaxf(mx0, fmaxf(t0, t1));
                mx1 = fmaxf(mx1, fmaxf(t2, t3));
            }
        } else {
#pragma unroll
            for (int ni = 0; ni < 8; ni++) {
                int cg = kv0 + ni * 8 + 2 * lc;
                float2 kp = *(const float2*)&keepf[ni * 8 + 2 * lc];
                float t0 = c[ni][0] + kp.x;
                float t1 = c[ni][1] + kp.y;
                float t2 = c[ni][2] + kp.x;
                float t3 = c[ni][3] + kp.y;
                if (cg > r0gl) t0 = -1e30f;
                if (cg + 1 > r0gl) t1 = -1e30f;
                if (cg > r1gl) t2 = -1e30f;
                if (cg + 1 > r1gl) t3 = -1e30f;
                c[ni][0] = t0; c[ni][1] = t1; c[ni][2] = t2; c[ni][3] = t3;
                mx0 = fmaxf(mx0, fmaxf(t0, t1));
                mx1 = fmaxf(mx1, fmaxf(t2, t3));
            }
        }
        mx0 = fmaxf(mx0, __shfl_xor_sync(0xffffffffu, mx0, 1));
        mx0 = fmaxf(mx0, __shfl_xor_sync(0xffffffffu, mx0, 2));
        mx1 = fmaxf(mx1, __shfl_xor_sync(0xffffffffu, mx1, 1));
        mx1 = fmaxf(mx1, __shfl_xor_sync(0xffffffffu, mx1, 2));
        float mn0 = fmaxf(m0r, mx0), mn1 = fmaxf(m1r, mx1);
        float al0 = ex2f(m0r - mn0), al1 = ex2f(m1r - mn1);
        float ls0 = 0.f, ls1 = 0.f;
#pragma unroll
        for (int ni = 0; ni < 8; ni++) {
            float p0 = ex2f(c[ni][0] - mn0);
            float p1 = ex2f(c[ni][1] - mn0);
            float p2 = ex2f(c[ni][2] - mn1);
            float p3 = ex2f(c[ni][3] - mn1);
            c[ni][0] = p0; c[ni][1] = p1; c[ni][2] = p2; c[ni][3] = p3;
            ls0 += p0 + p1;
            ls1 += p2 + p3;
        }
        ls0 += __shfl_xor_sync(0xffffffffu, ls0, 1);
        ls0 += __shfl_xor_sync(0xffffffffu, ls0, 2);
        ls1 += __shfl_xor_sync(0xffffffffu, ls1, 1);
        ls1 += __shfl_xor_sync(0xffffffffu, ls1, 2);
        l0r = l0r * al0 + ls0;
        l1r = l1r * al1 + ls1;
        m0r = mn0;
        m1r = mn1;
#pragma unroll
        for (int nd = 0; nd < 8; nd++) {
            o[nd][0] *= al0; o[nd][1] *= al0;
            o[nd][2] *= al1; o[nd][3] *= al1;
        }

#pragma unroll
        for (int ks = 0; ks < 4; ks++) {
            uint32_t pah[4];
#pragma unroll
            for (int u = 0; u < 2; u++) {
                pah[2 * u] = hpack(c[2 * ks + u][0], c[2 * ks + u][1]);
                pah[2 * u + 1] = hpack(c[2 * ks + u][2], c[2 * ks + u][3]);
            }
#pragma unroll
            for (int pd = 0; pd < 4; pd++) {
                uint32_t vb[4];
                LM4(vb, stg + 9216 +
                            (uint32_t)((pd * 16 + krow) * 144 + kcol * 2) +
                            ks * 32);
                mma16816(o[2 * pd], pah, vb);
                mma16816(o[2 * pd + 1], pah, vb + 2);
            }
        }
        __syncthreads();
    }

    const float i0 = 1.f / l0r, i1 = 1.f / l1r;
    const size_t row0 = (size_t)b * Tn + qbase + wm * 16 + lg;
    const size_t row1 = row0 + 8;
#pragma unroll
    for (int nd = 0; nd < 8; nd++) {
        int col = h * Dn + nd * 8 + 2 * lc;
        *(uint32_t*)&g_a[row0 * En + col] = hpack(o[nd][0] * i0, o[nd][1] * i0);
        *(uint32_t*)&g_a[row1 * En + col] = hpack(o[nd][2] * i1, o[nd][3] * i1);
    }
}

// ---------------------------------------------------------------------------
extern "C" void kernel_launch(void* const* d_in, const int* in_sizes, int n_in,
                              void* d_out, int out_size) {
    (void)in_sizes; (void)n_in; (void)out_size;
    const float* x = (const float*)d_in[0];
    const int* idsw = (const int*)d_in[1];
    const float* w_qkv = (const float*)d_in[2];
    const float* w_out = (const float*)d_in[3];
    const float* b_out = (const float*)d_in[4];
    float* out = (float*)d_out;

    detect_ids_kernel<<<1, 1>>>(idsw);

    split_kernel<<<(Bn * Tn * En / 4) / 256, 256>>>(x);
    wsplit_kernel<true><<<dim3(3 * En / 32, Kdim / 32), dim3(32, 8)>>>(w_qkv);
    wsplit_kernel<false><<<dim3(En / 32, Kdim / 32), dim3(32, 8)>>>(w_out);

    const int gsmem = 2 * 20480;  // 40960 B
    cudaFuncSetAttribute(hmma_gemm<3 * En, true>,
                         cudaFuncAttributeMaxDynamicSharedMemorySize, gsmem);
    cudaFuncSetAttribute(hmma_gemm<En, false>,
                         cudaFuncAttributeMaxDynamicSharedMemorySize, gsmem);

    // 1) QKV projection -> q (pre-scaled), k ([bh][t][d]) + v^T ([bh][d][t])
    dim3 g1(3 * En / 128, Bn * Tn / 128);  // (24, 64)
    hmma_gemm<3 * En, true><<<g1, 256, gsmem>>>(nullptr, nullptr);

    // 2) flash attention (fp16 single) -> y fp16 into g_a
    cudaFuncSetAttribute(flash_kernel,
                         cudaFuncAttributeMaxDynamicSharedMemorySize, FLASH_SMEM);
    dim3 g2(Tn / 128, Bn * Hn);  // (16, 64)
    flash_kernel<<<g2, 256, FLASH_SMEM>>>(idsw);

    // 3) output projection + bias
    dim3 g3(En / 128, Bn * Tn / 128);  // (8, 64)
    hmma_gemm<En, false><<<g3, 256, gsmem>>>(b_out, out);
}

// round 12
// speedup vs baseline: 7.0669x; 1.0574x over previous
#include <cuda_runtime.h>
#include <cuda_fp16.h>
#include <cstdint>

#define Bn 4
#define Tn 2048
#define En 1024
#define Hn 16
#define Dn 64
#define Kdim 1024
#define SC_LOG2 0.18033688f  // 0.125 * log2(e)

// ---------------- static device scratch (allocation-free) -------------------
__device__ __half g_a[Bn * Tn * En];         // activation fp16 (x, then y)
__device__ __half g_wq[3 * En * Kdim];       // w_qkv^T fp16 [N=3072][K]
__device__ __half g_wo[En * Kdim];           // w_out^T fp16
__device__ __half g_q[Bn * Hn * Tn * Dn];    // q fp16 PRE-SCALED [bh][t][d]
__device__ __half g_k[Bn * Hn * Tn * Dn];    // k fp16 [bh][t][d]
__device__ __half g_vt[Bn * Hn * Dn * Tn];   // v fp16 TRANSPOSED [bh][d][t]
__device__ int g_shift;

// ---------------- helpers (baseline PTX only: sm_80+ features) --------------
__device__ __forceinline__ void cp16(uint32_t s, const void* g) {
    asm volatile("cp.async.cg.shared.global [%0], [%1], 16;" :: "r"(s), "l"(g));
}
#define CP_COMMIT() asm volatile("cp.async.commit_group;" ::: "memory")
#define CP_WAIT(n) asm volatile("cp.async.wait_group %0;" :: "n"(n) : "memory")

__device__ __forceinline__ uint32_t smem_u32(const void* p) {
    uint32_t a;
    asm("{ .reg .u64 t; cvta.to.shared.u64 t, %1; cvt.u32.u64 %0, t; }"
        : "=r"(a) : "l"(p));
    return a;
}
__device__ __forceinline__ void mma16816(float* c, const uint32_t* a,
                                         const uint32_t* b) {
    asm volatile(
        "mma.sync.aligned.m16n8k16.row.col.f32.f16.f16.f32 "
        "{%0,%1,%2,%3}, {%4,%5,%6,%7}, {%8,%9}, {%0,%1,%2,%3};"
        : "+f"(c[0]), "+f"(c[1]), "+f"(c[2]), "+f"(c[3])
        : "r"(a[0]), "r"(a[1]), "r"(a[2]), "r"(a[3]), "r"(b[0]), "r"(b[1]));
}
#define LM4(r, addr)                                                       \
    asm volatile("ldmatrix.sync.aligned.m8n8.x4.shared.b16 "               \
                 "{%0,%1,%2,%3}, [%4];"                                    \
                 : "=r"((r)[0]), "=r"((r)[1]), "=r"((r)[2]), "=r"((r)[3])  \
                 : "r"(addr))
__device__ __forceinline__ float ex2f(float x) {
    float r;
    asm("ex2.approx.f32 %0, %1;" : "=f"(r) : "f"(x));
    return r;
}
__device__ __forceinline__ uint32_t hpack(float lo, float hi) {
    __half2 t = __floats2half2_rn(lo, hi);
    return *(uint32_t*)&t;
}

// ---------------- merged prep: x->fp16, weight transposes, ids detect -------
// blocks [0, 8192): split x; block 0 thread 0 also runs ids detection.
// blocks [8192, 11264): w_qkv transpose (96 x 32 tiles).
// blocks [11264, 12288): w_out transpose (32 x 32 tiles).
__global__ void __launch_bounds__(256)
prep_kernel(const float* __restrict__ x, const float* __restrict__ wqkv,
            const float* __restrict__ wout, const int* __restrict__ idsw) {
    __shared__ float tile[32][33];
    const int blk = blockIdx.x;
    const int tid = threadIdx.x;
    if (blk < 8192) {
        int i = blk * 256 + tid;
        float4 v = ((const float4*)x)[i];
        uint32_t* ph = (uint32_t*)g_a;
        ph[2 * i] = hpack(v.x, v.y);
        ph[2 * i + 1] = hpack(v.z, v.w);
        if (blk == 0 && tid == 0) {
            bool all0 = true;
            for (int j = 1; j < 64; j += 2) all0 = all0 && (idsw[j] == 0);
            g_shift = all0 ? 1 : 0;
        }
    } else {
        const float* W;
        __half* oh;
        int Nw, i;
        if (blk < 8192 + 3072) {
            i = blk - 8192; W = wqkv; oh = g_wq; Nw = 3 * En;
        } else {
            i = blk - 11264; W = wout; oh = g_wo; Nw = En;
        }
        const int nblk = Nw / 32;
        const int n0 = (i % nblk) * 32, k0 = (i / nblk) * 32;
        const int tx = tid & 31, ty = tid >> 5;
#pragma unroll
        for (int j = 0; j < 32; j += 8)
            tile[ty + j][tx] = W[(size_t)(k0 + ty + j) * Nw + n0 + tx];
        __syncthreads();
#pragma unroll
        for (int j = 0; j < 32; j += 8) {
            float a = tile[tx][ty + j];
            oh[(size_t)(n0 + ty + j) * Kdim + k0 + tx] = __float2half_rn(a);
        }
    }
}

// ---------------- HMMA fp16 GEMM: C[8192, Ntot] = A * W^T -------------------
// BM=128, BN=128, BK=64. 2-stage cp.async, ldmatrix. 8 warps 4(m)x2(n),
// warp tile 32x64. Row stride 144B (72 halfs) - proven conflict-free.
template <int Ntot, bool QKV>
__global__ void __launch_bounds__(256, 2)
hmma_gemm(const float* __restrict__ bias, float* __restrict__ Cout) {
    constexpr int ROWB = 144;                   // bytes per smem row (72 half)
    constexpr int OFF_B = 18432;                // 128*144
    constexpr int STG = 36864;                  // bytes per stage
    constexpr int NK = Kdim / 64;               // 16
    extern __shared__ char smc[];
    const uint32_t smb = smem_u32(smc);

    const __half* Bg = QKV ? g_wq : g_wo;

    const int m0 = blockIdx.y * 128;
    const int n0 = blockIdx.x * 128;
    const int tid = threadIdx.x;
    const int wid = tid >> 5;
    const int lane = tid & 31;
    const int wm = wid >> 1;   // 0..3
    const int wn = wid & 1;    // 0..1
    const int lg = lane >> 2;
    const int lc = lane & 3;
    const int arow = (lane & 7) + ((lane >> 3) & 1) * 8;
    const int acol = ((lane >> 4) & 1) * 8;
    const int brow = (lane & 7) + ((lane >> 4) & 1) * 8;
    const int bcol = ((lane >> 3) & 1) * 8;

    float acc[2][8][4];
#pragma unroll
    for (int mi = 0; mi < 2; mi++)
#pragma unroll
        for (int ni = 0; ni < 8; ni++)
#pragma unroll
            for (int r = 0; r < 4; r++) acc[mi][ni][r] = 0.f;

    auto load_stage = [&](int kc, int s) {
        const int k0 = kc * 64;
        const uint32_t sb = smb + (uint32_t)s * STG;
#pragma unroll
        for (int c = tid; c < 1024; c += 256) {
            int row = c >> 3, col8 = (c & 7) * 8;
            cp16(sb + (uint32_t)(row * ROWB + col8 * 2),
                 g_a + (size_t)(m0 + row) * Kdim + k0 + col8);
            cp16(sb + OFF_B + (uint32_t)(row * ROWB + col8 * 2),
                 Bg + (size_t)(n0 + row) * Kdim + k0 + col8);
        }
        CP_COMMIT();
    };

    load_stage(0, 0);

    int s = 0;
    for (int kc = 0; kc < NK; kc++) {
        CP_WAIT(0);
        __syncthreads();
        if (kc + 1 < NK) load_stage(kc + 1, s ^ 1);

        const uint32_t sb = smb + (uint32_t)s * STG;
        const uint32_t aB = sb + (uint32_t)((wm * 32 + arow) * ROWB + acol * 2);
        const uint32_t bB = sb + OFF_B + (uint32_t)(brow * ROWB + bcol * 2);
#pragma unroll
        for (int ks = 0; ks < 4; ks++) {
            uint32_t ah[2][4];
#pragma unroll
            for (int mi = 0; mi < 2; mi++)
                LM4(ah[mi], aB + mi * 16 * ROWB + ks * 32);
#pragma unroll
            for (int nj = 0; nj < 4; nj++) {
                uint32_t b[4];
                LM4(b, bB + (wn * 64 + nj * 16) * ROWB + ks * 32);
#pragma unroll
                for (int mi = 0; mi < 2; mi++) {
                    mma16816(acc[mi][2 * nj], ah[mi], b);
                    mma16816(acc[mi][2 * nj + 1], ah[mi], b + 2);
                }
            }
        }
        s ^= 1;
    }

    if (QKV) {
        const int which = n0 >> 10;
        const int b = m0 >> 11;
        if (which < 2) {
            __half* dst = which == 0 ? g_q : g_k;
            const float sc = which == 0 ? SC_LOG2 : 1.0f;  // pre-scale Q
#pragma unroll
            for (int mi = 0; mi < 2; mi++)
#pragma unroll
                for (int ni = 0; ni < 8; ni++)
#pragma unroll
                    for (int half = 0; half < 2; half++) {
                        int m = m0 + wm * 32 + mi * 16 + lg + half * 8;
                        int t = m & (Tn - 1);
                        int n = n0 + wn * 64 + ni * 8 + lc * 2;
                        int h = (n & 1023) >> 6;
                        int d = n & 63;
                        size_t off = (((size_t)(b * Hn + h)) * Tn + t) * Dn + d;
                        *(uint32_t*)&dst[off] =
                            hpack(acc[mi][ni][half * 2] * sc,
                                  acc[mi][ni][half * 2 + 1] * sc);
                    }
        } else {
            // V: fp16, transposed through smem -> [bh][d][t]
            __syncthreads();
            __half* sV = (__half*)smc;  // [128 col][136]
#pragma unroll
            for (int mi = 0; mi < 2; mi++)
#pragma unroll
                for (int ni = 0; ni < 8; ni++)
#pragma unroll
                    for (int half = 0; half < 2; half++) {
                        int tl = wm * 32 + mi * 16 + lg + half * 8;
                        int col = wn * 64 + ni * 8 + lc * 2;
                        sV[col * 136 + tl] =
                            __float2half_rn(acc[mi][ni][half * 2]);
                        sV[(col + 1) * 136 + tl] =
                            __float2half_rn(acc[mi][ni][half * 2 + 1]);
                    }
            __syncthreads();
            const int h0 = (n0 & 1023) >> 6;
            const int t0 = m0 & (Tn - 1);
#pragma unroll
            for (int c = tid; c < 2048; c += 256) {
                int col = c >> 4, t8 = (c & 15) * 8;
                int h = h0 + (col >> 6);
                int d = col & 63;
                uint4 vh = *(uint4*)&sV[col * 136 + t8];
                size_t off = (((size_t)(b * Hn + h)) * Dn + d) * Tn + t0 + t8;
                *(uint4*)&g_vt[off] = vh;
            }
        }
    } else {
#pragma unroll
        for (int mi = 0; mi < 2; mi++)
#pragma unroll
            for (int ni = 0; ni < 8; ni++) {
                int r0 = m0 + wm * 32 + mi * 16 + lg;
                int n = n0 + wn * 64 + ni * 8 + lc * 2;
#pragma unroll
                for (int half = 0; half < 2; half++) {
                    int m = r0 + half * 8;
                    float2 v = make_float2(acc[mi][ni][half * 2],
                                           acc[mi][ni][half * 2 + 1]);
                    v.x += bias[n];
                    v.y += bias[n + 1];
                    *(float2*)&Cout[(size_t)m * Ntot + n] = v;
                }
            }
    }
}

// ---------------- flash attention: HMMA fp16 single, FA-2 style -------------
// UNCHANGED from the passing round-11 kernel.
#define SSTG 18432       // stage base (after the full Q tile: 128 x 144 B)
#define SSTGSZ 18432     // per stage: K@0 (9216), V@9216
#define SKEEP 55296      // float[2][64]
#define FLASH_SMEM 55808

__global__ void __launch_bounds__(256, 2)
flash_kernel(const int* __restrict__ idsw) {
    extern __shared__ char smc[];
    const uint32_t smb = smem_u32(smc);

    const int qt = (int)gridDim.x - 1 - (int)blockIdx.x;
    const int bh = blockIdx.y;
    const int b = bh >> 4;
    const int h = bh & 15;
    const int qbase = qt * 128;
    const int tid = threadIdx.x;
    const int wm = tid >> 5;
    const int lane = tid & 31;
    const int lg = lane >> 2;
    const int lc = lane & 3;
    const int shift = g_shift;
    const int nt = 2 * qt + 2;

    const int qrow = (lane & 7) + ((lane >> 3) & 1) * 8;
    const int qcol = ((lane >> 4) & 1) * 8;
    const int krow = (lane & 7) + ((lane >> 4) & 1) * 8;
    const int kcol = ((lane >> 3) & 1) * 8;

    const uint32_t aq = smb + (uint32_t)((wm * 16 + qrow) * 144 + qcol * 2);

    auto load_kv = [&](int kt, int s) {
        const int kv0 = kt * 64;
        const uint32_t sb = smb + SSTG + (uint32_t)s * SSTGSZ;
#pragma unroll
        for (int ch = tid; ch < 512; ch += 256) {
            int r = ch >> 3, c8 = (ch & 7) << 3;
            uint32_t so = sb + (uint32_t)(r * 144 + c8 * 2);
            cp16(so, g_k + ((size_t)bh * Tn + kv0 + r) * Dn + c8);
            cp16(so + 9216, g_vt + ((size_t)bh * Dn + r) * Tn + kv0 + c8);
        }
        if (tid < 64) {
            size_t w = ((size_t)(b * Tn + kv0 + tid)) << shift;
            float ka = (idsw[w] != 0) ? 0.f : -1e30f;
            *(float*)(smc + SKEEP + s * 256 + tid * 4) = ka;
        }
        CP_COMMIT();
    };

#pragma unroll
    for (int ch = tid; ch < 1024; ch += 256) {
        int r = ch >> 3, c8 = (ch & 7) << 3;
        cp16(smb + (uint32_t)(r * 144 + c8 * 2),
             g_q + ((size_t)bh * Tn + qbase + r) * Dn + c8);
    }
    load_kv(0, 0);

    float o[8][4];
#pragma unroll
    for (int i = 0; i < 8; i++)
#pragma unroll
        for (int j = 0; j < 4; j++) o[i][j] = 0.f;
    float m0r = -1e30f, m1r = -1e30f, l0r = 0.f, l1r = 0.f;

    const int r0gl = qbase + wm * 16 + lg;
    const int r1gl = r0gl + 8;

    for (int kt = 0; kt < nt; kt++) {
        const int s = kt & 1;
        if (kt + 1 < nt) {
            load_kv(kt + 1, s ^ 1);
            CP_WAIT(1);
        } else {
            CP_WAIT(0);
        }
        __syncthreads();

        const uint32_t stg = smb + SSTG + (uint32_t)s * SSTGSZ;
        const int kv0 = kt * 64;

        float c[8][4];
#pragma unroll
        for (int i = 0; i < 8; i++)
#pragma unroll
            for (int j = 0; j < 4; j++) c[i][j] = 0.f;

#pragma unroll
        for (int ks = 0; ks < 4; ks++) {
            uint32_t ah[4];
            LM4(ah, aq + ks * 32);
#pragma unroll
            for (int pi = 0; pi < 4; pi++) {
                uint32_t kb[4];
                LM4(kb, stg + (uint32_t)((pi * 16 + krow) * 144 + kcol * 2) +
                            ks * 32);
                mma16816(c[2 * pi], ah, kb);
                mma16816(c[2 * pi + 1], ah, kb + 2);
            }
        }

        const float* keepf = (const float*)(smc + SKEEP + s * 256);
        float mx0 = -1e30f, mx1 = -1e30f;
        if (kv0 + 63 <= qbase + wm * 16) {
#pragma unroll
            for (int ni = 0; ni < 8; ni++) {
                float2 kp = *(const float2*)&keepf[ni * 8 + 2 * lc];
                float t0 = c[ni][0] + kp.x;
                float t1 = c[ni][1] + kp.y;
                float t2 = c[ni][2] + kp.x;
                float t3 = c[ni][3] + kp.y;
                c[ni][0] = t0; c[ni][1] = t1; c[ni][2] = t2; c[ni][3] = t3;
                mx0 = fmaxf(mx0, fmaxf(t0, t1));
                mx1 = fmaxf(mx1, fmaxf(t2, t3));
            }
        } else {
#pragma unroll
            for (int ni = 0; ni < 8; ni++) {
                int cg = kv0 + ni * 8 + 2 * lc;
                float2 kp = *(const float2*)&keepf[ni * 8 + 2 * lc];
                float t0 = c[ni][0] + kp.x;
                float t1 = c[ni][1] + kp.y;
                float t2 = c[ni][2] + kp.x;
                float t3 = c[ni][3] + kp.y;
                if (cg > r0gl) t0 = -1e30f;
                if (cg + 1 > r0gl) t1 = -1e30f;
                if (cg > r1gl) t2 = -1e30f;
                if (cg + 1 > r1gl) t3 = -1e30f;
                c[ni][0] = t0; c[ni][1] = t1; c[ni][2] = t2; c[ni][3] = t3;
                mx0 = fmaxf(mx0, fmaxf(t0, t1));
                mx1 = fmaxf(mx1, fmaxf(t2, t3));
            }
        }
        mx0 = fmaxf(mx0, __shfl_xor_sync(0xffffffffu, mx0, 1));
        mx0 = fmaxf(mx0, __shfl_xor_sync(0xffffffffu, mx0, 2));
        mx1 = fmaxf(mx1, __shfl_xor_sync(0xffffffffu, mx1, 1));
        mx1 = fmaxf(mx1, __shfl_xor_sync(0xffffffffu, mx1, 2));
        float mn0 = fmaxf(m0r, mx0), mn1 = fmaxf(m1r, mx1);
        float al0 = ex2f(m0r - mn0), al1 = ex2f(m1r - mn1);
        float ls0 = 0.f, ls1 = 0.f;
#pragma unroll
        for (int ni = 0; ni < 8; ni++) {
            float p0 = ex2f(c[ni][0] - mn0);
            float p1 = ex2f(c[ni][1] - mn0);
            float p2 = ex2f(c[ni][2] - mn1);
            float p3 = ex2f(c[ni][3] - mn1);
            c[ni][0] = p0; c[ni][1] = p1; c[ni][2] = p2; c[ni][3] = p3;
            ls0 += p0 + p1;
            ls1 += p2 + p3;
        }
        ls0 += __shfl_xor_sync(0xffffffffu, ls0, 1);
        ls0 += __shfl_xor_sync(0xffffffffu, ls0, 2);
        ls1 += __shfl_xor_sync(0xffffffffu, ls1, 1);
        ls1 += __shfl_xor_sync(0xffffffffu, ls1, 2);
        l0r = l0r * al0 + ls0;
        l1r = l1r * al1 + ls1;
        m0r = mn0;
        m1r = mn1;
#pragma unroll
        for (int nd = 0; nd < 8; nd++) {
            o[nd][0] *= al0; o[nd][1] *= al0;
            o[nd][2] *= al1; o[nd][3] *= al1;
        }

#pragma unroll
        for (int ks = 0; ks < 4; ks++) {
            uint32_t pah[4];
#pragma unroll
            for (int u = 0; u < 2; u++) {
                pah[2 * u] = hpack(c[2 * ks + u][0], c[2 * ks + u][1]);
                pah[2 * u + 1] = hpack(c[2 * ks + u][2], c[2 * ks + u][3]);
            }
#pragma unroll
            for (int pd = 0; pd < 4; pd++) {
                uint32_t vb[4];
                LM4(vb, stg + 9216 +
                            (uint32_t)((pd * 16 + krow) * 144 + kcol * 2) +
                            ks * 32);
                mma16816(o[2 * pd], pah, vb);
                mma16816(o[2 * pd + 1], pah, vb + 2);
            }
        }
        __syncthreads();
    }

    const float i0 = 1.f / l0r, i1 = 1.f / l1r;
    const size_t row0 = (size_t)b * Tn + qbase + wm * 16 + lg;
    const size_t row1 = row0 + 8;
#pragma unroll
    for (int nd = 0; nd < 8; nd++) {
        int col = h * Dn + nd * 8 + 2 * lc;
        *(uint32_t*)&g_a[row0 * En + col] = hpack(o[nd][0] * i0, o[nd][1] * i0);
        *(uint32_t*)&g_a[row1 * En + col] = hpack(o[nd][2] * i1, o[nd][3] * i1);
    }
}

// ---------------------------------------------------------------------------
extern "C" void kernel_launch(void* const* d_in, const int* in_sizes, int n_in,
                              void* d_out, int out_size) {
    (void)in_sizes; (void)n_in; (void)out_size;
    const float* x = (const float*)d_in[0];
    const int* idsw = (const int*)d_in[1];
    const float* w_qkv = (const float*)d_in[2];
    const float* w_out = (const float*)d_in[3];
    const float* b_out = (const float*)d_in[4];
    float* out = (float*)d_out;

    // merged prep: x->fp16 + ids detect + weight transposes (one launch)
    prep_kernel<<<12288, 256>>>(x, w_qkv, w_out, idsw);

    const int gsmem = 2 * 36864;  // 73728 B
    cudaFuncSetAttribute(hmma_gemm<3 * En, true>,
                         cudaFuncAttributeMaxDynamicSharedMemorySize, gsmem);
    cudaFuncSetAttribute(hmma_gemm<En, false>,
                         cudaFuncAttributeMaxDynamicSharedMemorySize, gsmem);

    // 1) QKV projection -> q (pre-scaled), k ([bh][t][d]) + v^T ([bh][d][t])
    dim3 g1(3 * En / 128, Bn * Tn / 128);  // (24, 64)
    hmma_gemm<3 * En, true><<<g1, 256, gsmem>>>(nullptr, nullptr);

    // 2) flash attention (fp16 single) -> y fp16 into g_a
    cudaFuncSetAttribute(flash_kernel,
                         cudaFuncAttributeMaxDynamicSharedMemorySize, FLASH_SMEM);
    dim3 g2(Tn / 128, Bn * Hn);  // (16, 64)
    flash_kernel<<<g2, 256, FLASH_SMEM>>>(idsw);

    // 3) output projection + bias
    dim3 g3(En / 128, Bn * Tn / 128);  // (8, 64)
    hmma_gemm<En, false><<<g3, 256, gsmem>>>(b_out, out);
}